// round 8
// baseline (speedup 1.0000x reference)
#include <cuda_runtime.h>
#include <cuda_bf16.h>
#include <cstdint>
#include <math.h>

// Problem constants
#define BB 4
#define TT 2048
#define CC 1024
#define HH 16
#define HD 64
#define MM (BB * TT)   // 8192
#define KK CC          // 1024
#define NN CC          // 1024

// ---------------------------------------------------------------------------
// Scratch (__device__ globals; no allocation allowed)
// ---------------------------------------------------------------------------
__device__ __nv_bfloat16 g_xh[(size_t)MM * KK];
__device__ __nv_bfloat16 g_xl[(size_t)MM * KK];
__device__ __nv_bfloat16 g_wh[(size_t)4 * KK * NN];   // transposed [N,K]; Q,K,V,P
__device__ __nv_bfloat16 g_wl[(size_t)4 * KK * NN];
__device__ __nv_bfloat16 g_yh[(size_t)MM * NN];
__device__ __nv_bfloat16 g_yl[(size_t)MM * NN];
// head-layout bf16 splits of q/k/v (q pre-scaled by 1/8)
__device__ __nv_bfloat16 g_qh[(size_t)BB * HH * TT * HD];
__device__ __nv_bfloat16 g_ql[(size_t)BB * HH * TT * HD];
__device__ __nv_bfloat16 g_kh[(size_t)BB * HH * TT * HD];
__device__ __nv_bfloat16 g_kl[(size_t)BB * HH * TT * HD];
__device__ __nv_bfloat16 g_vh[(size_t)BB * HH * TT * HD];
__device__ __nv_bfloat16 g_vl[(size_t)BB * HH * TT * HD];

// ---------------------------------------------------------------------------
// PTX helpers (base compute_100-safe: cp.async / ldmatrix / mma.sync only)
// ---------------------------------------------------------------------------
__device__ __forceinline__ uint32_t smem_u32(const void* p) {
  uint32_t a;
  asm("{ .reg .u64 t; cvta.to.shared.u64 t, %1; cvt.u32.u64 %0, t; }"
      : "=r"(a) : "l"(p));
  return a;
}
__device__ __forceinline__ void cpasync16(uint32_t dst, const void* src) {
  asm volatile("cp.async.cg.shared.global [%0], [%1], 16;" ::"r"(dst),
               "l"(src));
}
#define CP_COMMIT() asm volatile("cp.async.commit_group;" ::: "memory")

__device__ __forceinline__ void ldsm4(uint32_t* r, uint32_t addr) {
  asm volatile(
      "ldmatrix.sync.aligned.m8n8.x4.shared.b16 {%0,%1,%2,%3}, [%4];"
      : "=r"(r[0]), "=r"(r[1]), "=r"(r[2]), "=r"(r[3])
      : "r"(addr));
}
__device__ __forceinline__ void ldsm2(uint32_t* r, uint32_t addr) {
  asm volatile("ldmatrix.sync.aligned.m8n8.x2.shared.b16 {%0,%1}, [%2];"
               : "=r"(r[0]), "=r"(r[1])
               : "r"(addr));
}
__device__ __forceinline__ void ldsm4t(uint32_t* r, uint32_t addr) {
  asm volatile(
      "ldmatrix.sync.aligned.m8n8.x4.trans.shared.b16 {%0,%1,%2,%3}, [%4];"
      : "=r"(r[0]), "=r"(r[1]), "=r"(r[2]), "=r"(r[3])
      : "r"(addr));
}

// D += A @ B (m16n8k16, bf16 in, fp32 acc)
__device__ __forceinline__ void mma16816(float* c, const uint32_t* a,
                                         const uint32_t* b) {
  asm volatile(
      "mma.sync.aligned.m16n8k16.row.col.f32.bf16.bf16.f32 "
      "{%0,%1,%2,%3}, {%4,%5,%6,%7}, {%8,%9}, {%0,%1,%2,%3};"
      : "+f"(c[0]), "+f"(c[1]), "+f"(c[2]), "+f"(c[3])
      : "r"(a[0]), "r"(a[1]), "r"(a[2]), "r"(a[3]), "r"(b[0]), "r"(b[1]));
}

// hi/lo split of two floats, packed bf16x2
__device__ __forceinline__ void split2(float a, float b, uint32_t& hi,
                                       uint32_t& lo) {
  __nv_bfloat16 h0 = __float2bfloat16(a);
  __nv_bfloat16 h1 = __float2bfloat16(b);
  __nv_bfloat16 l0 = __float2bfloat16(a - __bfloat162float(h0));
  __nv_bfloat16 l1 = __float2bfloat16(b - __bfloat162float(h1));
  hi = (uint32_t)__bfloat16_as_ushort(h0) |
       ((uint32_t)__bfloat16_as_ushort(h1) << 16);
  lo = (uint32_t)__bfloat16_as_ushort(l0) |
       ((uint32_t)__bfloat16_as_ushort(l1) << 16);
}

// ---------------------------------------------------------------------------
// Fused conversion kernel: z=0 -> x hi/lo split (vectorized);
// z=1..4 -> W transpose+split for Wq,Wk,Wv,Wp.
// Grid (32,32,5), block (32,8).
// ---------------------------------------------------------------------------
__global__ void conv_all(const float* __restrict__ x,
                         const float* __restrict__ Wq,
                         const float* __restrict__ Wk,
                         const float* __restrict__ Wv,
                         const float* __restrict__ Wp,
                         __nv_bfloat16* __restrict__ xh,
                         __nv_bfloat16* __restrict__ xl,
                         __nv_bfloat16* __restrict__ wh,
                         __nv_bfloat16* __restrict__ wl) {
  __shared__ float tile[32][33];
  const int z = blockIdx.z;
  const int tx = threadIdx.x, ty = threadIdx.y;
  if (z == 0) {
    // 1024 blocks x 256 thr x 8 float4 = 8.39M floats
    const int bid = blockIdx.y * 32 + blockIdx.x;
    const int t = ty * 32 + tx;
    const float4* src = (const float4*)x + (size_t)bid * 2048;
    uint2* dh = (uint2*)xh + (size_t)bid * 2048;
    uint2* dl = (uint2*)xl + (size_t)bid * 2048;
#pragma unroll
    for (int it = 0; it < 8; it++) {
      const int i4 = it * 256 + t;
      float4 v = src[i4];
      uint32_t h0, l0, h1, l1;
      split2(v.x, v.y, h0, l0);
      split2(v.z, v.w, h1, l1);
      dh[i4] = make_uint2(h0, h1);
      dl[i4] = make_uint2(l0, l1);
    }
  } else {
    const float* W = (z == 1) ? Wq : (z == 2) ? Wk : (z == 3) ? Wv : Wp;
    const size_t WSZ = (size_t)KK * NN;
    __nv_bfloat16* th = wh + (size_t)(z - 1) * WSZ;
    __nv_bfloat16* tl = wl + (size_t)(z - 1) * WSZ;
    const int x0 = blockIdx.x * 32;  // n
    const int y0 = blockIdx.y * 32;  // k
#pragma unroll
    for (int r = 0; r < 32; r += 8)
      tile[ty + r][tx] = W[(size_t)(y0 + ty + r) * NN + x0 + tx];
    __syncthreads();
#pragma unroll
    for (int r = 0; r < 32; r += 8) {
      float v = tile[tx][ty + r];
      __nv_bfloat16 h = __float2bfloat16(v);
      const size_t o = (size_t)(x0 + ty + r) * KK + y0 + tx;
      th[o] = h;
      tl[o] = __float2bfloat16(v - __bfloat162float(h));
    }
  }
}

// ---------------------------------------------------------------------------
// mma.sync split-bf16 GEMM. 128x128 block tile, BKC=16, NST=4 single-sync
// multistage cp.async pipeline -> 96KB smem -> 2 CTAs/SM.
// Row pitch 48B: ldmatrix conflict-free (12*r mod 32 distinct, r=0..7).
// FUSED=1: QKV fused (grid.x spans 3*NN/128); routes epilogue by n0>>10.
// FUSED=0: proj; fp32 row-major out + bias b0p.
// ---------------------------------------------------------------------------
#define BKC 16
#define ROWB 48
#define TILEB (128 * ROWB)           // 6144
#define STAGEB (4 * TILEB)           // 24576
#define NST 4
#define NCH (KK / BKC)               // 64
#define GEMM_SMEM (NST * STAGEB)     // 98304

__device__ __forceinline__ void load_tile16(uint32_t sbase,
                                            const __nv_bfloat16* g, int tid) {
  // 128 rows x 32B data (2 x 16B); 256 threads -> 1 cp each
  const int row = tid >> 1, cc = tid & 1;
  cpasync16(sbase + row * ROWB + cc * 16, g + (size_t)row * KK + cc * 8);
}

__device__ __forceinline__ void load_chunk(uint32_t st, const __nv_bfloat16* Ahb,
                                           const __nv_bfloat16* Alb,
                                           const __nv_bfloat16* Bhb,
                                           const __nv_bfloat16* Blb, int k0,
                                           int tid) {
  load_tile16(st + 0 * TILEB, Ahb + k0, tid);
  load_tile16(st + 1 * TILEB, Alb + k0, tid);
  load_tile16(st + 2 * TILEB, Bhb + k0, tid);
  load_tile16(st + 3 * TILEB, Blb + k0, tid);
  CP_COMMIT();
}

template <int FUSED>
__global__ __launch_bounds__(256, 2) void gemm_tc(
    const __nv_bfloat16* __restrict__ Ah, const __nv_bfloat16* __restrict__ Al,
    const __nv_bfloat16* __restrict__ Bh, const __nv_bfloat16* __restrict__ Bl,
    const float* __restrict__ b0p, const float* __restrict__ b1p,
    const float* __restrict__ b2p, float* __restrict__ out,
    float* __restrict__ kout, float* __restrict__ vout,
    __nv_bfloat16* __restrict__ qh, __nv_bfloat16* __restrict__ ql,
    __nv_bfloat16* __restrict__ kh, __nv_bfloat16* __restrict__ kl,
    __nv_bfloat16* __restrict__ vh, __nv_bfloat16* __restrict__ vl) {
  extern __shared__ __align__(128) uint8_t smem_raw[];
  const uint32_t sb = smem_u32(smem_raw);
  const int tid = threadIdx.x;
  const int wid = tid >> 5, lane = tid & 31;
  const int gid = lane >> 2, tig = lane & 3;
  const int n0 = blockIdx.x * 128;
  const int m0 = blockIdx.y * 128;
  const int wm0 = (wid & 1) * 64;
  const int wn0 = (wid >> 1) * 32;

  const __nv_bfloat16* Ahb = Ah + (size_t)m0 * KK;
  const __nv_bfloat16* Alb = Al + (size_t)m0 * KK;
  const __nv_bfloat16* Bhb = Bh + (size_t)n0 * KK;
  const __nv_bfloat16* Blb = Bl + (size_t)n0 * KK;

  float acc[4][4][4];
#pragma unroll
  for (int i = 0; i < 4; i++)
#pragma unroll
    for (int j = 0; j < 4; j++)
#pragma unroll
      for (int r = 0; r < 4; r++) acc[i][j][r] = 0.f;

  const int amat = lane >> 3;
  const int arow_in = ((amat & 1) << 3) + (lane & 7);
  const int acol = (amat >> 1) << 4;
  const int brow_in = lane & 7;
  const int bcol = ((lane >> 3) & 1) << 4;

  // Prologue: chunks 0..2 into stages 0..2 (3 groups in flight)
#pragma unroll
  for (int c = 0; c < 3; c++)
    load_chunk(sb + c * STAGEB, Ahb, Alb, Bhb, Blb, c * BKC, tid);

  for (int c = 0; c < NCH; c++) {
    if (c + 2 < NCH)
      asm volatile("cp.async.wait_group 2;" ::: "memory");
    else if (c + 1 < NCH)
      asm volatile("cp.async.wait_group 1;" ::: "memory");
    else
      asm volatile("cp.async.wait_group 0;" ::: "memory");
    __syncthreads();

    // Issue loads for chunk c+3 into the stage freed by chunk c-1
    // (safe: the sync above proves all threads finished computing c-1).
    if (c + 3 < NCH)
      load_chunk(sb + ((c + 3) & 3) * STAGEB, Ahb, Alb, Bhb, Blb,
                 (c + 3) * BKC, tid);

    const uint32_t st = sb + (c & 3) * STAGEB;
    const uint32_t tAh = st + 0 * TILEB;
    const uint32_t tAl = st + 1 * TILEB;
    const uint32_t tBh = st + 2 * TILEB;
    const uint32_t tBl = st + 3 * TILEB;

    uint32_t bh[4][2], bl[4][2];
#pragma unroll
    for (int j = 0; j < 4; j++) {
      const uint32_t bo = (wn0 + j * 8 + brow_in) * ROWB + bcol;
      ldsm2(bh[j], tBh + bo);
      ldsm2(bl[j], tBl + bo);
    }
#pragma unroll
    for (int i = 0; i < 4; i++) {
      uint32_t ah[4], al[4];
      const uint32_t ao = (wm0 + i * 16 + arow_in) * ROWB + acol;
      ldsm4(ah, tAh + ao);
      ldsm4(al, tAl + ao);
#pragma unroll
      for (int j = 0; j < 4; j++) {
        mma16816(acc[i][j], ah, bh[j]);
        mma16816(acc[i][j], ah, bl[j]);
        mma16816(acc[i][j], al, bh[j]);
      }
    }
  }

  // Epilogue
  int mat = 0;
  const float* bias = b0p;
  if (FUSED) {
    mat = n0 >> 10;  // uniform per block
    bias = (mat == 0) ? b0p : (mat == 1) ? b1p : b2p;
  }
#pragma unroll
  for (int i = 0; i < 4; i++) {
#pragma unroll
    for (int j = 0; j < 4; j++) {
      const int col = n0 + wn0 + j * 8 + tig * 2;
      const int cloc = col & (NN - 1);
      const float bb0 = __ldg(bias + cloc);
      const float bb1 = __ldg(bias + cloc + 1);
#pragma unroll
      for (int hh = 0; hh < 2; hh++) {
        const int m = m0 + wm0 + i * 16 + gid + hh * 8;
        float v0 = acc[i][j][hh * 2 + 0] + bb0;
        float v1 = acc[i][j][hh * 2 + 1] + bb1;
        if (!FUSED) {
          *(float2*)(out + (size_t)m * NN + col) = make_float2(v0, v1);
        } else {
          const int b = m >> 11, t = m & (TT - 1);
          const int h = cloc >> 6, hd = cloc & (HD - 1);
          const size_t ho = (((size_t)b * HH + h) * TT + t) * HD + hd;
          uint32_t hw, lw;
          if (mat == 0) {  // Q: pre-scale by 1/8 (exact)
            split2(v0 * 0.125f, v1 * 0.125f, hw, lw);
            *(uint32_t*)(qh + ho) = hw;
            *(uint32_t*)(ql + ho) = lw;
          } else if (mat == 1) {  // K
            *(float2*)(kout + ho) = make_float2(v0, v1);
            split2(v0, v1, hw, lw);
            *(uint32_t*)(kh + ho) = hw;
            *(uint32_t*)(kl + ho) = lw;
          } else {  // V
            *(float2*)(vout + ho) = make_float2(v0, v1);
            split2(v0, v1, hw, lw);
            *(uint32_t*)(vh + ho) = hw;
            *(uint32_t*)(vl + ho) = lw;
          }
        }
      }
    }
  }
}

// ---------------------------------------------------------------------------
// Tensor-core causal flash attention, split-bf16 (3-term) for both matmuls.
// (unchanged — verified at rel_err 1.16e-5)
// ---------------------------------------------------------------------------
#define AROW 144
#define QSZ (128 * AROW)
#define KSZ (64 * AROW)
#define STG4 (4 * KSZ)
#define ATT_SMEM (2 * QSZ + 2 * STG4)

__device__ __forceinline__ void loadkv(uint32_t st, const __nv_bfloat16* khp,
                                       const __nv_bfloat16* klp,
                                       const __nv_bfloat16* vhp,
                                       const __nv_bfloat16* vlp, int kv0,
                                       int tid) {
#pragma unroll
  for (int it = 0; it < 8; it++) {
    const int arr = it >> 1;
    const int rem = ((it & 1) << 8) + tid;
    const int row = rem >> 3, c = rem & 7;
    const __nv_bfloat16* base = (arr == 0) ? khp : (arr == 1) ? klp
                                : (arr == 2) ? vhp : vlp;
    cpasync16(st + arr * KSZ + row * AROW + c * 16,
              base + (size_t)(kv0 + row) * HD + c * 8);
  }
}

__global__ __launch_bounds__(256, 2) void attn_mma(
    const __nv_bfloat16* __restrict__ qh, const __nv_bfloat16* __restrict__ ql,
    const __nv_bfloat16* __restrict__ kh, const __nv_bfloat16* __restrict__ kl,
    const __nv_bfloat16* __restrict__ vh, const __nv_bfloat16* __restrict__ vl,
    __nv_bfloat16* __restrict__ yh, __nv_bfloat16* __restrict__ yl) {
  extern __shared__ __align__(128) uint8_t smem_raw[];
  const uint32_t sb = smem_u32(smem_raw);
  const int tid = threadIdx.x;
  const int w = tid >> 5, lane = tid & 31;
  const int gid = lane >> 2, tig = lane & 3;
  const int qblk = blockIdx.x, h = blockIdx.y, b = blockIdx.z;
  const int q0 = qblk * 128;
  const size_t hoff = (((size_t)b * HH + h) * TT) * HD;
  const __nv_bfloat16* qhp = qh + hoff;
  const __nv_bfloat16* qlp = ql + hoff;
  const __nv_bfloat16* khp = kh + hoff;
  const __nv_bfloat16* klp = kl + hoff;
  const __nv_bfloat16* vhp = vh + hoff;
  const __nv_bfloat16* vlp = vl + hoff;

#pragma unroll
  for (int it = 0; it < 8; it++) {
    const int arr = it >> 2;
    const int rem = ((it & 3) << 8) + tid;
    const int row = rem >> 3, c = rem & 7;
    cpasync16(sb + arr * QSZ + row * AROW + c * 16,
              (arr ? qlp : qhp) + (size_t)(q0 + row) * HD + c * 8);
  }
  loadkv(sb + 2 * QSZ, khp, klp, vhp, vlp, 0, tid);
  CP_COMMIT();
  loadkv(sb + 2 * QSZ + STG4, khp, klp, vhp, vlp, 64, tid);
  CP_COMMIT();

  float s[8][4], o[8][4];
  float mrow[2] = {-INFINITY, -INFINITY};
  float lrow[2] = {0.f, 0.f};
#pragma unroll
  for (int j = 0; j < 8; j++)
#pragma unroll
    for (int r = 0; r < 4; r++) o[j][r] = 0.f;

  const int amat = lane >> 3;
  const int arow_in = ((amat & 1) << 3) + (lane & 7);
  const int acol = (amat >> 1) << 4;
  const int brow_in = lane & 7;
  const int bcol = ((lane >> 3) & 1) << 4;
  const int ntiles = 2 * qblk + 2;

  for (int t = 0; t < ntiles; t++) {
    if (t + 1 < ntiles)
      asm volatile("cp.async.wait_group 1;" ::: "memory");
    else
      asm volatile("cp.async.wait_group 0;" ::: "memory");
    __syncthreads();

    const uint32_t st = sb + 2 * QSZ + (t & 1) * STG4;
    const uint32_t tKh = st, tKl = st + KSZ;
    const uint32_t tVh = st + 2 * KSZ, tVl = st + 3 * KSZ;

#pragma unroll
    for (int j = 0; j < 8; j++)
#pragma unroll
      for (int r = 0; r < 4; r++) s[j][r] = 0.f;

#pragma unroll
    for (int kk = 0; kk < 4; kk++) {
      uint32_t aq[4], aql[4];
      const uint32_t qo = (w * 16 + arow_in) * AROW + kk * 32 + acol;
      ldsm4(aq, sb + qo);
      ldsm4(aql, sb + QSZ + qo);
#pragma unroll
      for (int j = 0; j < 8; j++) {
        uint32_t bh2[2], bl2[2];
        const uint32_t ko = (j * 8 + brow_in) * AROW + kk * 32 + bcol;
        ldsm2(bh2, tKh + ko);
        ldsm2(bl2, tKl + ko);
        mma16816(s[j], aq, bh2);
        mma16816(s[j], aq, bl2);
        mma16816(s[j], aql, bh2);
      }
    }

    const int kv0 = t * 64;
    if (kv0 + 63 > q0) {
#pragma unroll
      for (int j = 0; j < 8; j++) {
        const int jg = kv0 + j * 8 + tig * 2;
#pragma unroll
        for (int r = 0; r < 2; r++) {
          const int rg = q0 + w * 16 + gid + r * 8;
          if (jg > rg) s[j][r * 2] = -INFINITY;
          if (jg + 1 > rg) s[j][r * 2 + 1] = -INFINITY;
        }
      }
    }

#pragma unroll
    for (int r = 0; r < 2; r++) {
      float mx = mrow[r];
#pragma unroll
      for (int j = 0; j < 8; j++)
        mx = fmaxf(mx, fmaxf(s[j][r * 2], s[j][r * 2 + 1]));
      mx = fmaxf(mx, __shfl_xor_sync(0xffffffffu, mx, 1));
      mx = fmaxf(mx, __shfl_xor_sync(0xffffffffu, mx, 2));
      const float alpha = __expf(mrow[r] - mx);
      mrow[r] = mx;
      float ls = 0.f;
#pragma unroll
      for (int j = 0; j < 8; j++) {
        const float p0 = __expf(s[j][r * 2] - mx);
        const float p1 = __expf(s[j][r * 2 + 1] - mx);
        s[j][r * 2] = p0;
        s[j][r * 2 + 1] = p1;
        ls += p0 + p1;
      }
      ls += __shfl_xor_sync(0xffffffffu, ls, 1);
      ls += __shfl_xor_sync(0xffffffffu, ls, 2);
      lrow[r] = lrow[r] * alpha + ls;
#pragma unroll
      for (int j = 0; j < 8; j++) {
        o[j][r * 2] *= alpha;
        o[j][r * 2 + 1] *= alpha;
      }
    }

#pragma unroll
    for (int kk = 0; kk < 4; kk++) {
      uint32_t ph4[4], pl4[4];
#pragma unroll
      for (int half = 0; half < 2; half++) {
        const int j = 2 * kk + half;
        split2(s[j][0], s[j][1], ph4[half * 2 + 0], pl4[half * 2 + 0]);
        split2(s[j][2], s[j][3], ph4[half * 2 + 1], pl4[half * 2 + 1]);
      }
      const uint32_t vrow = kk * 16 + (lane & 15);
      const uint32_t vco = (lane >> 4) << 4;
#pragma unroll
      for (int np = 0; np < 4; np++) {
        uint32_t vh4[4], vl4[4];
        const uint32_t vo = vrow * AROW + np * 32 + vco;
        ldsm4t(vh4, tVh + vo);
        ldsm4t(vl4, tVl + vo);
        mma16816(o[2 * np], ph4, vh4);
        mma16816(o[2 * np], ph4, vl4);
        mma16816(o[2 * np], pl4, vh4);
        mma16816(o[2 * np + 1], ph4, vh4 + 2);
        mma16816(o[2 * np + 1], ph4, vl4 + 2);
        mma16816(o[2 * np + 1], pl4, vh4 + 2);
      }
    }
    __syncthreads();

    if (t + 2 < ntiles) {
      loadkv(st, khp, klp, vhp, vlp, (t + 2) * 64, tid);
      CP_COMMIT();
    }
  }

  const float i0 = 1.f / lrow[0];
  const float i1 = 1.f / lrow[1];
  const int r0 = q0 + w * 16 + gid;
  const size_t base0 = ((size_t)b * TT + r0) * CC + h * HD;
  const size_t base1 = base0 + (size_t)8 * CC;
#pragma unroll
  for (int n = 0; n < 8; n++) {
    const int col = n * 8 + tig * 2;
    uint32_t hw, lw;
    split2(o[n][0] * i0, o[n][1] * i0, hw, lw);
    *(uint32_t*)(yh + base0 + col) = hw;
    *(uint32_t*)(yl + base0 + col) = lw;
    split2(o[n][2] * i1, o[n][3] * i1, hw, lw);
    *(uint32_t*)(yh + base1 + col) = hw;
    *(uint32_t*)(yl + base1 + col) = lw;
  }
}

// ---------------------------------------------------------------------------
// kernel_launch
// ---------------------------------------------------------------------------
extern "C" void kernel_launch(void* const* d_in, const int* in_sizes, int n_in,
                              void* d_out, int out_size) {
  const float* x = (const float*)d_in[0];
  const float* Wq = (const float*)d_in[2];
  const float* bq = (const float*)d_in[3];
  const float* Wk = (const float*)d_in[4];
  const float* bk = (const float*)d_in[5];
  const float* Wv = (const float*)d_in[6];
  const float* bv = (const float*)d_in[7];
  const float* Wp = (const float*)d_in[8];
  const float* bp = (const float*)d_in[9];

  float* out = (float*)d_out;
  float* kout = out + (size_t)BB * TT * CC;        // present[0] = k
  float* vout = kout + (size_t)BB * HH * TT * HD;  // present[1] = v

  __nv_bfloat16 *xh, *xl, *wh, *wl, *yh, *yl;
  __nv_bfloat16 *qhb, *qlb, *khb, *klb, *vhb, *vlb;
  cudaGetSymbolAddress((void**)&xh, g_xh);
  cudaGetSymbolAddress((void**)&xl, g_xl);
  cudaGetSymbolAddress((void**)&wh, g_wh);
  cudaGetSymbolAddress((void**)&wl, g_wl);
  cudaGetSymbolAddress((void**)&yh, g_yh);
  cudaGetSymbolAddress((void**)&yl, g_yl);
  cudaGetSymbolAddress((void**)&qhb, g_qh);
  cudaGetSymbolAddress((void**)&qlb, g_ql);
  cudaGetSymbolAddress((void**)&khb, g_kh);
  cudaGetSymbolAddress((void**)&klb, g_kl);
  cudaGetSymbolAddress((void**)&vhb, g_vh);
  cudaGetSymbolAddress((void**)&vlb, g_vl);

  // #1: fused conversions (x split + 4 W transposes)
  conv_all<<<dim3(32, 32, 5), dim3(32, 8)>>>(x, Wq, Wk, Wv, Wp, xh, xl, wh, wl);

  // #2: fused QKV projection (tensor core, 2 CTAs/SM)
  cudaFuncSetAttribute(gemm_tc<1>, cudaFuncAttributeMaxDynamicSharedMemorySize,
                       GEMM_SMEM);
  cudaFuncSetAttribute(gemm_tc<0>, cudaFuncAttributeMaxDynamicSharedMemorySize,
                       GEMM_SMEM);
  dim3 qkvgrid(3 * NN / 128, MM / 128);  // (24, 64)
  gemm_tc<1><<<qkvgrid, 256, GEMM_SMEM>>>(xh, xl, wh, wl, bq, bk, bv, nullptr,
                                          kout, vout, qhb, qlb, khb, klb, vhb,
                                          vlb);

  // #3: tensor-core attention
  cudaFuncSetAttribute(attn_mma, cudaFuncAttributeMaxDynamicSharedMemorySize,
                       ATT_SMEM);
  dim3 agrid(TT / 128, HH, BB);
  attn_mma<<<agrid, 256, ATT_SMEM>>>(qhb, qlb, khb, klb, vhb, vlb, yh, yl);

  // #4: output projection (this one lands under ncu -s 5)
  const size_t WSZ = (size_t)KK * NN;
  dim3 pgrid(NN / 128, MM / 128);
  gemm_tc<0><<<pgrid, 256, GEMM_SMEM>>>(yh, yl, wh + 3 * WSZ, wl + 3 * WSZ, bp,
                                        nullptr, nullptr, out, nullptr, nullptr,
                                        nullptr, nullptr, nullptr, nullptr,
                                        nullptr, nullptr);
}

// round 10
// speedup vs baseline: 1.0304x; 1.0304x over previous
#include <cuda_runtime.h>
#include <cuda_bf16.h>
#include <cstdint>
#include <math.h>

// Problem constants
#define BB 4
#define TT 2048
#define CC 1024
#define HH 16
#define HD 64
#define MM (BB * TT)   // 8192
#define KK CC          // 1024
#define NN CC          // 1024

// ---------------------------------------------------------------------------
// Scratch (__device__ globals; no allocation allowed)
// ---------------------------------------------------------------------------
__device__ __nv_bfloat16 g_xh[(size_t)MM * KK];
__device__ __nv_bfloat16 g_xl[(size_t)MM * KK];
__device__ __nv_bfloat16 g_wh[(size_t)4 * KK * NN];   // transposed [N,K]; Q,K,V,P
__device__ __nv_bfloat16 g_wl[(size_t)4 * KK * NN];
__device__ __nv_bfloat16 g_yh[(size_t)MM * NN];
__device__ __nv_bfloat16 g_yl[(size_t)MM * NN];
// head-layout bf16 splits of q/k/v (q pre-scaled by 1/8)
__device__ __nv_bfloat16 g_qh[(size_t)BB * HH * TT * HD];
__device__ __nv_bfloat16 g_ql[(size_t)BB * HH * TT * HD];
__device__ __nv_bfloat16 g_kh[(size_t)BB * HH * TT * HD];
__device__ __nv_bfloat16 g_kl[(size_t)BB * HH * TT * HD];
__device__ __nv_bfloat16 g_vh[(size_t)BB * HH * TT * HD];
__device__ __nv_bfloat16 g_vl[(size_t)BB * HH * TT * HD];

// ---------------------------------------------------------------------------
// PTX helpers (base compute_100-safe: cp.async / ldmatrix / mma.sync only)
// ---------------------------------------------------------------------------
__device__ __forceinline__ uint32_t smem_u32(const void* p) {
  uint32_t a;
  asm("{ .reg .u64 t; cvta.to.shared.u64 t, %1; cvt.u32.u64 %0, t; }"
      : "=r"(a) : "l"(p));
  return a;
}
__device__ __forceinline__ void cpasync16(uint32_t dst, const void* src) {
  asm volatile("cp.async.cg.shared.global [%0], [%1], 16;" ::"r"(dst),
               "l"(src));
}
#define CP_COMMIT() asm volatile("cp.async.commit_group;" ::: "memory")

__device__ __forceinline__ void ldsm4(uint32_t* r, uint32_t addr) {
  asm volatile(
      "ldmatrix.sync.aligned.m8n8.x4.shared.b16 {%0,%1,%2,%3}, [%4];"
      : "=r"(r[0]), "=r"(r[1]), "=r"(r[2]), "=r"(r[3])
      : "r"(addr));
}
__device__ __forceinline__ void ldsm2(uint32_t* r, uint32_t addr) {
  asm volatile("ldmatrix.sync.aligned.m8n8.x2.shared.b16 {%0,%1}, [%2];"
               : "=r"(r[0]), "=r"(r[1])
               : "r"(addr));
}
__device__ __forceinline__ void ldsm4t(uint32_t* r, uint32_t addr) {
  asm volatile(
      "ldmatrix.sync.aligned.m8n8.x4.trans.shared.b16 {%0,%1,%2,%3}, [%4];"
      : "=r"(r[0]), "=r"(r[1]), "=r"(r[2]), "=r"(r[3])
      : "r"(addr));
}

// D += A @ B (m16n8k16, bf16 in, fp32 acc)
__device__ __forceinline__ void mma16816(float* c, const uint32_t* a,
                                         const uint32_t* b) {
  asm volatile(
      "mma.sync.aligned.m16n8k16.row.col.f32.bf16.bf16.f32 "
      "{%0,%1,%2,%3}, {%4,%5,%6,%7}, {%8,%9}, {%0,%1,%2,%3};"
      : "+f"(c[0]), "+f"(c[1]), "+f"(c[2]), "+f"(c[3])
      : "r"(a[0]), "r"(a[1]), "r"(a[2]), "r"(a[3]), "r"(b[0]), "r"(b[1]));
}

// hi/lo split of two floats, packed bf16x2
__device__ __forceinline__ void split2(float a, float b, uint32_t& hi,
                                       uint32_t& lo) {
  __nv_bfloat16 h0 = __float2bfloat16(a);
  __nv_bfloat16 h1 = __float2bfloat16(b);
  __nv_bfloat16 l0 = __float2bfloat16(a - __bfloat162float(h0));
  __nv_bfloat16 l1 = __float2bfloat16(b - __bfloat162float(h1));
  hi = (uint32_t)__bfloat16_as_ushort(h0) |
       ((uint32_t)__bfloat16_as_ushort(h1) << 16);
  lo = (uint32_t)__bfloat16_as_ushort(l0) |
       ((uint32_t)__bfloat16_as_ushort(l1) << 16);
}

// ---------------------------------------------------------------------------
// Fused conversion kernel: z=0 -> x hi/lo split (vectorized);
// z=1..4 -> W transpose+split for Wq,Wk,Wv,Wp.
// ---------------------------------------------------------------------------
__global__ void conv_all(const float* __restrict__ x,
                         const float* __restrict__ Wq,
                         const float* __restrict__ Wk,
                         const float* __restrict__ Wv,
                         const float* __restrict__ Wp,
                         __nv_bfloat16* __restrict__ xh,
                         __nv_bfloat16* __restrict__ xl,
                         __nv_bfloat16* __restrict__ wh,
                         __nv_bfloat16* __restrict__ wl) {
  __shared__ float tile[32][33];
  const int z = blockIdx.z;
  const int tx = threadIdx.x, ty = threadIdx.y;
  if (z == 0) {
    const int bid = blockIdx.y * 32 + blockIdx.x;
    const int t = ty * 32 + tx;
    const float4* src = (const float4*)x + (size_t)bid * 2048;
    uint2* dh = (uint2*)xh + (size_t)bid * 2048;
    uint2* dl = (uint2*)xl + (size_t)bid * 2048;
#pragma unroll
    for (int it = 0; it < 8; it++) {
      const int i4 = it * 256 + t;
      float4 v = src[i4];
      uint32_t h0, l0, h1, l1;
      split2(v.x, v.y, h0, l0);
      split2(v.z, v.w, h1, l1);
      dh[i4] = make_uint2(h0, h1);
      dl[i4] = make_uint2(l0, l1);
    }
  } else {
    const float* W = (z == 1) ? Wq : (z == 2) ? Wk : (z == 3) ? Wv : Wp;
    const size_t WSZ = (size_t)KK * NN;
    __nv_bfloat16* th = wh + (size_t)(z - 1) * WSZ;
    __nv_bfloat16* tl = wl + (size_t)(z - 1) * WSZ;
    const int x0 = blockIdx.x * 32;  // n
    const int y0 = blockIdx.y * 32;  // k
#pragma unroll
    for (int r = 0; r < 32; r += 8)
      tile[ty + r][tx] = W[(size_t)(y0 + ty + r) * NN + x0 + tx];
    __syncthreads();
#pragma unroll
    for (int r = 0; r < 32; r += 8) {
      float v = tile[tx][ty + r];
      __nv_bfloat16 h = __float2bfloat16(v);
      const size_t o = (size_t)(x0 + ty + r) * KK + y0 + tx;
      th[o] = h;
      tl[o] = __float2bfloat16(v - __bfloat162float(h));
    }
  }
}

// ---------------------------------------------------------------------------
// mma.sync split-bf16 GEMM. 128x128 block tile, BKC=32, NST=2 double-buffered
// cp.async -> 80KB smem -> 2 CTAs/SM. A-fragments double-buffered in regs
// (prefetch i+1 before i's MMAs) to hide ldmatrix latency.
// FUSED=1: QKV fused (grid.x spans 3*NN/128); routes epilogue by n0>>10.
// FUSED=0: proj; fp32 row-major out + bias b0p.
// ---------------------------------------------------------------------------
#define BKC 32
#define ROWB 80
#define TILEB (128 * ROWB)           // 10240
#define STAGEB (4 * TILEB)           // 40960
#define NST 2
#define NCH (KK / BKC)               // 32
#define GEMM_SMEM (NST * STAGEB)     // 81920

__device__ __forceinline__ void load_tile32(uint32_t sbase,
                                            const __nv_bfloat16* g, int tid) {
#pragma unroll
  for (int it = 0; it < 2; it++) {
    const int lin = it * 256 + tid;
    const int row = lin >> 2, cc = lin & 3;
    cpasync16(sbase + row * ROWB + cc * 16, g + (size_t)row * KK + cc * 8);
  }
}

__device__ __forceinline__ void load_chunk(uint32_t st,
                                           const __nv_bfloat16* Ahb,
                                           const __nv_bfloat16* Alb,
                                           const __nv_bfloat16* Bhb,
                                           const __nv_bfloat16* Blb, int k0,
                                           int tid) {
  load_tile32(st + 0 * TILEB, Ahb + k0, tid);
  load_tile32(st + 1 * TILEB, Alb + k0, tid);
  load_tile32(st + 2 * TILEB, Bhb + k0, tid);
  load_tile32(st + 3 * TILEB, Blb + k0, tid);
  CP_COMMIT();
}

template <int FUSED>
__global__ __launch_bounds__(256, 2) void gemm_tc(
    const __nv_bfloat16* __restrict__ Ah, const __nv_bfloat16* __restrict__ Al,
    const __nv_bfloat16* __restrict__ Bh, const __nv_bfloat16* __restrict__ Bl,
    const float* __restrict__ b0p, const float* __restrict__ b1p,
    const float* __restrict__ b2p, float* __restrict__ out,
    float* __restrict__ kout, float* __restrict__ vout,
    __nv_bfloat16* __restrict__ qh, __nv_bfloat16* __restrict__ ql,
    __nv_bfloat16* __restrict__ kh, __nv_bfloat16* __restrict__ kl,
    __nv_bfloat16* __restrict__ vh, __nv_bfloat16* __restrict__ vl) {
  extern __shared__ __align__(128) uint8_t smem_raw[];
  const uint32_t sb = smem_u32(smem_raw);
  const int tid = threadIdx.x;
  const int wid = tid >> 5, lane = tid & 31;
  const int gid = lane >> 2, tig = lane & 3;
  const int n0 = blockIdx.x * 128;
  const int m0 = blockIdx.y * 128;
  const int wm0 = (wid & 1) * 64;
  const int wn0 = (wid >> 1) * 32;

  const __nv_bfloat16* Ahb = Ah + (size_t)m0 * KK;
  const __nv_bfloat16* Alb = Al + (size_t)m0 * KK;
  const __nv_bfloat16* Bhb = Bh + (size_t)n0 * KK;
  const __nv_bfloat16* Blb = Bl + (size_t)n0 * KK;

  float acc[4][4][4];
#pragma unroll
  for (int i = 0; i < 4; i++)
#pragma unroll
    for (int j = 0; j < 4; j++)
#pragma unroll
      for (int r = 0; r < 4; r++) acc[i][j][r] = 0.f;

  const int amat = lane >> 3;
  const int arow_in = ((amat & 1) << 3) + (lane & 7);
  const int acol = (amat >> 1) << 4;
  const int brow_in = lane & 7;
  const int bcol = ((lane >> 3) & 1) << 4;

  // Prologue: chunks 0,1 into stages 0,1
#pragma unroll
  for (int c = 0; c < 2; c++)
    load_chunk(sb + c * STAGEB, Ahb, Alb, Bhb, Blb, c * BKC, tid);

  for (int c = 0; c < NCH; c++) {
    if (c + 1 < NCH)
      asm volatile("cp.async.wait_group 1;" ::: "memory");
    else
      asm volatile("cp.async.wait_group 0;" ::: "memory");
    __syncthreads();

    const uint32_t st = sb + (c & 1) * STAGEB;
    const uint32_t tAh = st + 0 * TILEB;
    const uint32_t tAl = st + 1 * TILEB;
    const uint32_t tBh = st + 2 * TILEB;
    const uint32_t tBl = st + 3 * TILEB;

    // A fragments double-buffered across u = ks*4 + i (8 steps).
    uint32_t ah[2][4], al[2][4];
    {
      const uint32_t ao = (wm0 + arow_in) * ROWB + acol;  // u=0: i=0, ks=0
      ldsm4(ah[0], tAh + ao);
      ldsm4(al[0], tAl + ao);
    }
#pragma unroll
    for (int ks = 0; ks < 2; ks++) {
      const int kb = ks * 32;
      uint32_t bh[4][2], bl[4][2];
#pragma unroll
      for (int j = 0; j < 4; j++) {
        const uint32_t bo = (wn0 + j * 8 + brow_in) * ROWB + kb + bcol;
        ldsm2(bh[j], tBh + bo);
        ldsm2(bl[j], tBl + bo);
      }
#pragma unroll
      for (int i = 0; i < 4; i++) {
        const int u = ks * 4 + i;
        if (u + 1 < 8) {
          const int nks = (u + 1) >> 2, ni = (u + 1) & 3;
          const uint32_t ao =
              (wm0 + ni * 16 + arow_in) * ROWB + nks * 32 + acol;
          ldsm4(ah[(u + 1) & 1], tAh + ao);
          ldsm4(al[(u + 1) & 1], tAl + ao);
        }
#pragma unroll
        for (int j = 0; j < 4; j++) {
          mma16816(acc[i][j], ah[u & 1], bh[j]);
          mma16816(acc[i][j], ah[u & 1], bl[j]);
          mma16816(acc[i][j], al[u & 1], bh[j]);
        }
      }
    }
    __syncthreads();

    if (c + 2 < NCH)
      load_chunk(sb + (c & 1) * STAGEB, Ahb, Alb, Bhb, Blb, (c + 2) * BKC,
                 tid);
  }

  // Epilogue
  int mat = 0;
  const float* bias = b0p;
  if (FUSED) {
    mat = n0 >> 10;  // uniform per block
    bias = (mat == 0) ? b0p : (mat == 1) ? b1p : b2p;
  }
#pragma unroll
  for (int i = 0; i < 4; i++) {
#pragma unroll
    for (int j = 0; j < 4; j++) {
      const int col = n0 + wn0 + j * 8 + tig * 2;
      const int cloc = col & (NN - 1);
      const float bb0 = __ldg(bias + cloc);
      const float bb1 = __ldg(bias + cloc + 1);
#pragma unroll
      for (int hh = 0; hh < 2; hh++) {
        const int m = m0 + wm0 + i * 16 + gid + hh * 8;
        float v0 = acc[i][j][hh * 2 + 0] + bb0;
        float v1 = acc[i][j][hh * 2 + 1] + bb1;
        if (!FUSED) {
          *(float2*)(out + (size_t)m * NN + col) = make_float2(v0, v1);
        } else {
          const int b = m >> 11, t = m & (TT - 1);
          const int h = cloc >> 6, hd = cloc & (HD - 1);
          const size_t ho = (((size_t)b * HH + h) * TT + t) * HD + hd;
          uint32_t hw, lw;
          if (mat == 0) {  // Q: pre-scale by 1/8 (exact)
            split2(v0 * 0.125f, v1 * 0.125f, hw, lw);
            *(uint32_t*)(qh + ho) = hw;
            *(uint32_t*)(ql + ho) = lw;
          } else if (mat == 1) {  // K
            *(float2*)(kout + ho) = make_float2(v0, v1);
            split2(v0, v1, hw, lw);
            *(uint32_t*)(kh + ho) = hw;
            *(uint32_t*)(kl + ho) = lw;
          } else {  // V
            *(float2*)(vout + ho) = make_float2(v0, v1);
            split2(v0, v1, hw, lw);
            *(uint32_t*)(vh + ho) = hw;
            *(uint32_t*)(vl + ho) = lw;
          }
        }
      }
    }
  }
}

// ---------------------------------------------------------------------------
// Tensor-core causal flash attention, split-bf16 (3-term) for both matmuls.
// (unchanged — verified at rel_err 1.16e-5)
// ---------------------------------------------------------------------------
#define AROW 144
#define QSZ (128 * AROW)
#define KSZ (64 * AROW)
#define STG4 (4 * KSZ)
#define ATT_SMEM (2 * QSZ + 2 * STG4)

__device__ __forceinline__ void loadkv(uint32_t st, const __nv_bfloat16* khp,
                                       const __nv_bfloat16* klp,
                                       const __nv_bfloat16* vhp,
                                       const __nv_bfloat16* vlp, int kv0,
                                       int tid) {
#pragma unroll
  for (int it = 0; it < 8; it++) {
    const int arr = it >> 1;
    const int rem = ((it & 1) << 8) + tid;
    const int row = rem >> 3, c = rem & 7;
    const __nv_bfloat16* base = (arr == 0) ? khp : (arr == 1) ? klp
                                : (arr == 2) ? vhp : vlp;
    cpasync16(st + arr * KSZ + row * AROW + c * 16,
              base + (size_t)(kv0 + row) * HD + c * 8);
  }
}

__global__ __launch_bounds__(256, 2) void attn_mma(
    const __nv_bfloat16* __restrict__ qh, const __nv_bfloat16* __restrict__ ql,
    const __nv_bfloat16* __restrict__ kh, const __nv_bfloat16* __restrict__ kl,
    const __nv_bfloat16* __restrict__ vh, const __nv_bfloat16* __restrict__ vl,
    __nv_bfloat16* __restrict__ yh, __nv_bfloat16* __restrict__ yl) {
  extern __shared__ __align__(128) uint8_t smem_raw[];
  const uint32_t sb = smem_u32(smem_raw);
  const int tid = threadIdx.x;
  const int w = tid >> 5, lane = tid & 31;
  const int gid = lane >> 2, tig = lane & 3;
  const int qblk = blockIdx.x, h = blockIdx.y, b = blockIdx.z;
  const int q0 = qblk * 128;
  const size_t hoff = (((size_t)b * HH + h) * TT) * HD;
  const __nv_bfloat16* qhp = qh + hoff;
  const __nv_bfloat16* qlp = ql + hoff;
  const __nv_bfloat16* khp = kh + hoff;
  const __nv_bfloat16* klp = kl + hoff;
  const __nv_bfloat16* vhp = vh + hoff;
  const __nv_bfloat16* vlp = vl + hoff;

#pragma unroll
  for (int it = 0; it < 8; it++) {
    const int arr = it >> 2;
    const int rem = ((it & 3) << 8) + tid;
    const int row = rem >> 3, c = rem & 7;
    cpasync16(sb + arr * QSZ + row * AROW + c * 16,
              (arr ? qlp : qhp) + (size_t)(q0 + row) * HD + c * 8);
  }
  loadkv(sb + 2 * QSZ, khp, klp, vhp, vlp, 0, tid);
  CP_COMMIT();
  loadkv(sb + 2 * QSZ + STG4, khp, klp, vhp, vlp, 64, tid);
  CP_COMMIT();

  float s[8][4], o[8][4];
  float mrow[2] = {-INFINITY, -INFINITY};
  float lrow[2] = {0.f, 0.f};
#pragma unroll
  for (int j = 0; j < 8; j++)
#pragma unroll
    for (int r = 0; r < 4; r++) o[j][r] = 0.f;

  const int amat = lane >> 3;
  const int arow_in = ((amat & 1) << 3) + (lane & 7);
  const int acol = (amat >> 1) << 4;
  const int brow_in = lane & 7;
  const int bcol = ((lane >> 3) & 1) << 4;
  const int ntiles = 2 * qblk + 2;

  for (int t = 0; t < ntiles; t++) {
    if (t + 1 < ntiles)
      asm volatile("cp.async.wait_group 1;" ::: "memory");
    else
      asm volatile("cp.async.wait_group 0;" ::: "memory");
    __syncthreads();

    const uint32_t st = sb + 2 * QSZ + (t & 1) * STG4;
    const uint32_t tKh = st, tKl = st + KSZ;
    const uint32_t tVh = st + 2 * KSZ, tVl = st + 3 * KSZ;

#pragma unroll
    for (int j = 0; j < 8; j++)
#pragma unroll
      for (int r = 0; r < 4; r++) s[j][r] = 0.f;

#pragma unroll
    for (int kk = 0; kk < 4; kk++) {
      uint32_t aq[4], aql[4];
      const uint32_t qo = (w * 16 + arow_in) * AROW + kk * 32 + acol;
      ldsm4(aq, sb + qo);
      ldsm4(aql, sb + QSZ + qo);
#pragma unroll
      for (int j = 0; j < 8; j++) {
        uint32_t bh2[2], bl2[2];
        const uint32_t ko = (j * 8 + brow_in) * AROW + kk * 32 + bcol;
        ldsm2(bh2, tKh + ko);
        ldsm2(bl2, tKl + ko);
        mma16816(s[j], aq, bh2);
        mma16816(s[j], aq, bl2);
        mma16816(s[j], aql, bh2);
      }
    }

    const int kv0 = t * 64;
    if (kv0 + 63 > q0) {
#pragma unroll
      for (int j = 0; j < 8; j++) {
        const int jg = kv0 + j * 8 + tig * 2;
#pragma unroll
        for (int r = 0; r < 2; r++) {
          const int rg = q0 + w * 16 + gid + r * 8;
          if (jg > rg) s[j][r * 2] = -INFINITY;
          if (jg + 1 > rg) s[j][r * 2 + 1] = -INFINITY;
        }
      }
    }

#pragma unroll
    for (int r = 0; r < 2; r++) {
      float mx = mrow[r];
#pragma unroll
      for (int j = 0; j < 8; j++)
        mx = fmaxf(mx, fmaxf(s[j][r * 2], s[j][r * 2 + 1]));
      mx = fmaxf(mx, __shfl_xor_sync(0xffffffffu, mx, 1));
      mx = fmaxf(mx, __shfl_xor_sync(0xffffffffu, mx, 2));
      const float alpha = __expf(mrow[r] - mx);
      mrow[r] = mx;
      float ls = 0.f;
#pragma unroll
      for (int j = 0; j < 8; j++) {
        const float p0 = __expf(s[j][r * 2] - mx);
        const float p1 = __expf(s[j][r * 2 + 1] - mx);
        s[j][r * 2] = p0;
        s[j][r * 2 + 1] = p1;
        ls += p0 + p1;
      }
      ls += __shfl_xor_sync(0xffffffffu, ls, 1);
      ls += __shfl_xor_sync(0xffffffffu, ls, 2);
      lrow[r] = lrow[r] * alpha + ls;
#pragma unroll
      for (int j = 0; j < 8; j++) {
        o[j][r * 2] *= alpha;
        o[j][r * 2 + 1] *= alpha;
      }
    }

#pragma unroll
    for (int kk = 0; kk < 4; kk++) {
      uint32_t ph4[4], pl4[4];
#pragma unroll
      for (int half = 0; half < 2; half++) {
        const int j = 2 * kk + half;
        split2(s[j][0], s[j][1], ph4[half * 2 + 0], pl4[half * 2 + 0]);
        split2(s[j][2], s[j][3], ph4[half * 2 + 1], pl4[half * 2 + 1]);
      }
      const uint32_t vrow = kk * 16 + (lane & 15);
      const uint32_t vco = (lane >> 4) << 4;
#pragma unroll
      for (int np = 0; np < 4; np++) {
        uint32_t vh4[4], vl4[4];
        const uint32_t vo = vrow * AROW + np * 32 + vco;
        ldsm4t(vh4, tVh + vo);
        ldsm4t(vl4, tVl + vo);
        mma16816(o[2 * np], ph4, vh4);
        mma16816(o[2 * np], ph4, vl4);
        mma16816(o[2 * np], pl4, vh4);
        mma16816(o[2 * np + 1], ph4, vh4 + 2);
        mma16816(o[2 * np + 1], ph4, vl4 + 2);
        mma16816(o[2 * np + 1], pl4, vh4 + 2);
      }
    }
    __syncthreads();

    if (t + 2 < ntiles) {
      loadkv(st, khp, klp, vhp, vlp, (t + 2) * 64, tid);
      CP_COMMIT();
    }
  }

  const float i0 = 1.f / lrow[0];
  const float i1 = 1.f / lrow[1];
  const int r0 = q0 + w * 16 + gid;
  const size_t base0 = ((size_t)b * TT + r0) * CC + h * HD;
  const size_t base1 = base0 + (size_t)8 * CC;
#pragma unroll
  for (int n = 0; n < 8; n++) {
    const int col = n * 8 + tig * 2;
    uint32_t hw, lw;
    split2(o[n][0] * i0, o[n][1] * i0, hw, lw);
    *(uint32_t*)(yh + base0 + col) = hw;
    *(uint32_t*)(yl + base0 + col) = lw;
    split2(o[n][2] * i1, o[n][3] * i1, hw, lw);
    *(uint32_t*)(yh + base1 + col) = hw;
    *(uint32_t*)(yl + base1 + col) = lw;
  }
}

// ---------------------------------------------------------------------------
// kernel_launch
// ---------------------------------------------------------------------------
extern "C" void kernel_launch(void* const* d_in, const int* in_sizes, int n_in,
                              void* d_out, int out_size) {
  const float* x = (const float*)d_in[0];
  const float* Wq = (const float*)d_in[2];
  const float* bq = (const float*)d_in[3];
  const float* Wk = (const float*)d_in[4];
  const float* bk = (const float*)d_in[5];
  const float* Wv = (const float*)d_in[6];
  const float* bv = (const float*)d_in[7];
  const float* Wp = (const float*)d_in[8];
  const float* bp = (const float*)d_in[9];

  float* out = (float*)d_out;
  float* kout = out + (size_t)BB * TT * CC;        // present[0] = k
  float* vout = kout + (size_t)BB * HH * TT * HD;  // present[1] = v

  __nv_bfloat16 *xh, *xl, *wh, *wl, *yh, *yl;
  __nv_bfloat16 *qhb, *qlb, *khb, *klb, *vhb, *vlb;
  cudaGetSymbolAddress((void**)&xh, g_xh);
  cudaGetSymbolAddress((void**)&xl, g_xl);
  cudaGetSymbolAddress((void**)&wh, g_wh);
  cudaGetSymbolAddress((void**)&wl, g_wl);
  cudaGetSymbolAddress((void**)&yh, g_yh);
  cudaGetSymbolAddress((void**)&yl, g_yl);
  cudaGetSymbolAddress((void**)&qhb, g_qh);
  cudaGetSymbolAddress((void**)&qlb, g_ql);
  cudaGetSymbolAddress((void**)&khb, g_kh);
  cudaGetSymbolAddress((void**)&klb, g_kl);
  cudaGetSymbolAddress((void**)&vhb, g_vh);
  cudaGetSymbolAddress((void**)&vlb, g_vl);

  // #1: fused conversions (x split + 4 W transposes)
  conv_all<<<dim3(32, 32, 5), dim3(32, 8)>>>(x, Wq, Wk, Wv, Wp, xh, xl, wh, wl);

  // #2: fused QKV projection (tensor core, 2 CTAs/SM)
  cudaFuncSetAttribute(gemm_tc<1>, cudaFuncAttributeMaxDynamicSharedMemorySize,
                       GEMM_SMEM);
  cudaFuncSetAttribute(gemm_tc<0>, cudaFuncAttributeMaxDynamicSharedMemorySize,
                       GEMM_SMEM);
  dim3 qkvgrid(3 * NN / 128, MM / 128);  // (24, 64)
  gemm_tc<1><<<qkvgrid, 256, GEMM_SMEM>>>(xh, xl, wh, wl, bq, bk, bv, nullptr,
                                          kout, vout, qhb, qlb, khb, klb, vhb,
                                          vlb);

  // #3: tensor-core attention
  cudaFuncSetAttribute(attn_mma, cudaFuncAttributeMaxDynamicSharedMemorySize,
                       ATT_SMEM);
  dim3 agrid(TT / 128, HH, BB);
  attn_mma<<<agrid, 256, ATT_SMEM>>>(qhb, qlb, khb, klb, vhb, vlb, yh, yl);

  // #4: output projection (lands under ncu -s 5)
  const size_t WSZ = (size_t)KK * NN;
  dim3 pgrid(NN / 128, MM / 128);
  gemm_tc<0><<<pgrid, 256, GEMM_SMEM>>>(yh, yl, wh + 3 * WSZ, wl + 3 * WSZ, bp,
                                        nullptr, nullptr, out, nullptr, nullptr,
                                        nullptr, nullptr, nullptr, nullptr,
                                        nullptr, nullptr);
}

// round 11
// speedup vs baseline: 1.0324x; 1.0019x over previous
#include <cuda_runtime.h>
#include <cuda_bf16.h>
#include <cstdint>
#include <math.h>

// Problem constants
#define BB 4
#define TT 2048
#define CC 1024
#define HH 16
#define HD 64
#define MM (BB * TT)   // 8192
#define KK CC          // 1024
#define NN CC          // 1024

// ---------------------------------------------------------------------------
// Scratch (__device__ globals; no allocation allowed)
// ---------------------------------------------------------------------------
__device__ __nv_bfloat16 g_xh[(size_t)MM * KK];
__device__ __nv_bfloat16 g_xl[(size_t)MM * KK];
__device__ __nv_bfloat16 g_wh[(size_t)4 * KK * NN];   // transposed [N,K]; Q,K,V,P
__device__ __nv_bfloat16 g_wl[(size_t)4 * KK * NN];
__device__ __nv_bfloat16 g_yh[(size_t)MM * NN];
__device__ __nv_bfloat16 g_yl[(size_t)MM * NN];
// head-layout bf16 splits of q/k/v (q pre-scaled by 1/8)
__device__ __nv_bfloat16 g_qh[(size_t)BB * HH * TT * HD];
__device__ __nv_bfloat16 g_ql[(size_t)BB * HH * TT * HD];
__device__ __nv_bfloat16 g_kh[(size_t)BB * HH * TT * HD];
__device__ __nv_bfloat16 g_kl[(size_t)BB * HH * TT * HD];
__device__ __nv_bfloat16 g_vh[(size_t)BB * HH * TT * HD];
__device__ __nv_bfloat16 g_vl[(size_t)BB * HH * TT * HD];

// ---------------------------------------------------------------------------
// PTX helpers (base compute_100-safe: cp.async / ldmatrix / mma.sync only)
// ---------------------------------------------------------------------------
__device__ __forceinline__ uint32_t smem_u32(const void* p) {
  uint32_t a;
  asm("{ .reg .u64 t; cvta.to.shared.u64 t, %1; cvt.u32.u64 %0, t; }"
      : "=r"(a) : "l"(p));
  return a;
}
__device__ __forceinline__ void cpasync16(uint32_t dst, const void* src) {
  asm volatile("cp.async.cg.shared.global [%0], [%1], 16;" ::"r"(dst),
               "l"(src));
}
#define CP_COMMIT() asm volatile("cp.async.commit_group;" ::: "memory")

__device__ __forceinline__ void ldsm4(uint32_t* r, uint32_t addr) {
  asm volatile(
      "ldmatrix.sync.aligned.m8n8.x4.shared.b16 {%0,%1,%2,%3}, [%4];"
      : "=r"(r[0]), "=r"(r[1]), "=r"(r[2]), "=r"(r[3])
      : "r"(addr));
}
__device__ __forceinline__ void ldsm2(uint32_t* r, uint32_t addr) {
  asm volatile("ldmatrix.sync.aligned.m8n8.x2.shared.b16 {%0,%1}, [%2];"
               : "=r"(r[0]), "=r"(r[1])
               : "r"(addr));
}
__device__ __forceinline__ void ldsm4t(uint32_t* r, uint32_t addr) {
  asm volatile(
      "ldmatrix.sync.aligned.m8n8.x4.trans.shared.b16 {%0,%1,%2,%3}, [%4];"
      : "=r"(r[0]), "=r"(r[1]), "=r"(r[2]), "=r"(r[3])
      : "r"(addr));
}

// D += A @ B (m16n8k16, bf16 in, fp32 acc)
__device__ __forceinline__ void mma16816(float* c, const uint32_t* a,
                                         const uint32_t* b) {
  asm volatile(
      "mma.sync.aligned.m16n8k16.row.col.f32.bf16.bf16.f32 "
      "{%0,%1,%2,%3}, {%4,%5,%6,%7}, {%8,%9}, {%0,%1,%2,%3};"
      : "+f"(c[0]), "+f"(c[1]), "+f"(c[2]), "+f"(c[3])
      : "r"(a[0]), "r"(a[1]), "r"(a[2]), "r"(a[3]), "r"(b[0]), "r"(b[1]));
}

// hi/lo split of two floats, packed bf16x2
__device__ __forceinline__ void split2(float a, float b, uint32_t& hi,
                                       uint32_t& lo) {
  __nv_bfloat16 h0 = __float2bfloat16(a);
  __nv_bfloat16 h1 = __float2bfloat16(b);
  __nv_bfloat16 l0 = __float2bfloat16(a - __bfloat162float(h0));
  __nv_bfloat16 l1 = __float2bfloat16(b - __bfloat162float(h1));
  hi = (uint32_t)__bfloat16_as_ushort(h0) |
       ((uint32_t)__bfloat16_as_ushort(h1) << 16);
  lo = (uint32_t)__bfloat16_as_ushort(l0) |
       ((uint32_t)__bfloat16_as_ushort(l1) << 16);
}

// ---------------------------------------------------------------------------
// Fused conversion kernel: z=0 -> x hi/lo split (vectorized);
// z=1..4 -> W transpose+split for Wq,Wk,Wv,Wp.
// ---------------------------------------------------------------------------
__global__ void conv_all(const float* __restrict__ x,
                         const float* __restrict__ Wq,
                         const float* __restrict__ Wk,
                         const float* __restrict__ Wv,
                         const float* __restrict__ Wp,
                         __nv_bfloat16* __restrict__ xh,
                         __nv_bfloat16* __restrict__ xl,
                         __nv_bfloat16* __restrict__ wh,
                         __nv_bfloat16* __restrict__ wl) {
  __shared__ float tile[32][33];
  const int z = blockIdx.z;
  const int tx = threadIdx.x, ty = threadIdx.y;
  if (z == 0) {
    const int bid = blockIdx.y * 32 + blockIdx.x;
    const int t = ty * 32 + tx;
    const float4* src = (const float4*)x + (size_t)bid * 2048;
    uint2* dh = (uint2*)xh + (size_t)bid * 2048;
    uint2* dl = (uint2*)xl + (size_t)bid * 2048;
#pragma unroll
    for (int it = 0; it < 8; it++) {
      const int i4 = it * 256 + t;
      float4 v = src[i4];
      uint32_t h0, l0, h1, l1;
      split2(v.x, v.y, h0, l0);
      split2(v.z, v.w, h1, l1);
      dh[i4] = make_uint2(h0, h1);
      dl[i4] = make_uint2(l0, l1);
    }
  } else {
    const float* W = (z == 1) ? Wq : (z == 2) ? Wk : (z == 3) ? Wv : Wp;
    const size_t WSZ = (size_t)KK * NN;
    __nv_bfloat16* th = wh + (size_t)(z - 1) * WSZ;
    __nv_bfloat16* tl = wl + (size_t)(z - 1) * WSZ;
    const int x0 = blockIdx.x * 32;  // n
    const int y0 = blockIdx.y * 32;  // k
#pragma unroll
    for (int r = 0; r < 32; r += 8)
      tile[ty + r][tx] = W[(size_t)(y0 + ty + r) * NN + x0 + tx];
    __syncthreads();
#pragma unroll
    for (int r = 0; r < 32; r += 8) {
      float v = tile[tx][ty + r];
      __nv_bfloat16 h = __float2bfloat16(v);
      const size_t o = (size_t)(x0 + ty + r) * KK + y0 + tx;
      th[o] = h;
      tl[o] = __float2bfloat16(v - __bfloat162float(h));
    }
  }
}

// ---------------------------------------------------------------------------
// mma.sync split-bf16 GEMM. 128x128 block tile, BKC=32, NST=2 double-buffered
// cp.async -> 80KB smem -> 2 CTAs/SM. All fragments resident per k16 step;
// MMAs issued TERM-MAJOR so same-accumulator MMAs are 16 apart (hides HMMA
// accumulator RAW latency; the adjacent-term ordering capped tensor at ~52%).
// FUSED=1: QKV fused (grid.x spans 3*NN/128); routes epilogue by n0>>10.
// FUSED=0: proj; fp32 row-major out + bias b0p.
// ---------------------------------------------------------------------------
#define BKC 32
#define ROWB 80
#define TILEB (128 * ROWB)           // 10240
#define STAGEB (4 * TILEB)           // 40960
#define NST 2
#define NCH (KK / BKC)               // 32
#define GEMM_SMEM (NST * STAGEB)     // 81920

__device__ __forceinline__ void load_tile32(uint32_t sbase,
                                            const __nv_bfloat16* g, int tid) {
#pragma unroll
  for (int it = 0; it < 2; it++) {
    const int lin = it * 256 + tid;
    const int row = lin >> 2, cc = lin & 3;
    cpasync16(sbase + row * ROWB + cc * 16, g + (size_t)row * KK + cc * 8);
  }
}

__device__ __forceinline__ void load_chunk(uint32_t st,
                                           const __nv_bfloat16* Ahb,
                                           const __nv_bfloat16* Alb,
                                           const __nv_bfloat16* Bhb,
                                           const __nv_bfloat16* Blb, int k0,
                                           int tid) {
  load_tile32(st + 0 * TILEB, Ahb + k0, tid);
  load_tile32(st + 1 * TILEB, Alb + k0, tid);
  load_tile32(st + 2 * TILEB, Bhb + k0, tid);
  load_tile32(st + 3 * TILEB, Blb + k0, tid);
  CP_COMMIT();
}

template <int FUSED>
__global__ __launch_bounds__(256, 2) void gemm_tc(
    const __nv_bfloat16* __restrict__ Ah, const __nv_bfloat16* __restrict__ Al,
    const __nv_bfloat16* __restrict__ Bh, const __nv_bfloat16* __restrict__ Bl,
    const float* __restrict__ b0p, const float* __restrict__ b1p,
    const float* __restrict__ b2p, float* __restrict__ out,
    float* __restrict__ kout, float* __restrict__ vout,
    __nv_bfloat16* __restrict__ qh, __nv_bfloat16* __restrict__ ql,
    __nv_bfloat16* __restrict__ kh, __nv_bfloat16* __restrict__ kl,
    __nv_bfloat16* __restrict__ vh, __nv_bfloat16* __restrict__ vl) {
  extern __shared__ __align__(128) uint8_t smem_raw[];
  const uint32_t sb = smem_u32(smem_raw);
  const int tid = threadIdx.x;
  const int wid = tid >> 5, lane = tid & 31;
  const int gid = lane >> 2, tig = lane & 3;
  const int n0 = blockIdx.x * 128;
  const int m0 = blockIdx.y * 128;
  const int wm0 = (wid & 1) * 64;
  const int wn0 = (wid >> 1) * 32;

  const __nv_bfloat16* Ahb = Ah + (size_t)m0 * KK;
  const __nv_bfloat16* Alb = Al + (size_t)m0 * KK;
  const __nv_bfloat16* Bhb = Bh + (size_t)n0 * KK;
  const __nv_bfloat16* Blb = Bl + (size_t)n0 * KK;

  float acc[4][4][4];
#pragma unroll
  for (int i = 0; i < 4; i++)
#pragma unroll
    for (int j = 0; j < 4; j++)
#pragma unroll
      for (int r = 0; r < 4; r++) acc[i][j][r] = 0.f;

  const int amat = lane >> 3;
  const int arow_in = ((amat & 1) << 3) + (lane & 7);
  const int acol = (amat >> 1) << 4;
  const int brow_in = lane & 7;
  const int bcol = ((lane >> 3) & 1) << 4;

  // Prologue: chunks 0,1 into stages 0,1
#pragma unroll
  for (int c = 0; c < 2; c++)
    load_chunk(sb + c * STAGEB, Ahb, Alb, Bhb, Blb, c * BKC, tid);

  for (int c = 0; c < NCH; c++) {
    if (c + 1 < NCH)
      asm volatile("cp.async.wait_group 1;" ::: "memory");
    else
      asm volatile("cp.async.wait_group 0;" ::: "memory");
    __syncthreads();

    const uint32_t st = sb + (c & 1) * STAGEB;
    const uint32_t tAh = st + 0 * TILEB;
    const uint32_t tAl = st + 1 * TILEB;
    const uint32_t tBh = st + 2 * TILEB;
    const uint32_t tBl = st + 3 * TILEB;

#pragma unroll
    for (int ks = 0; ks < 2; ks++) {
      const int kb = ks * 32;
      uint32_t ah[4][4], al[4][4], bh[4][2], bl[4][2];
#pragma unroll
      for (int i = 0; i < 4; i++) {
        const uint32_t ao = (wm0 + i * 16 + arow_in) * ROWB + kb + acol;
        ldsm4(ah[i], tAh + ao);
        ldsm4(al[i], tAl + ao);
      }
#pragma unroll
      for (int j = 0; j < 4; j++) {
        const uint32_t bo = (wn0 + j * 8 + brow_in) * ROWB + kb + bcol;
        ldsm2(bh[j], tBh + bo);
        ldsm2(bl[j], tBl + bo);
      }
      // Term-major: same-acc MMAs are 16 apart (acc RAW hidden).
#pragma unroll
      for (int i = 0; i < 4; i++)
#pragma unroll
        for (int j = 0; j < 4; j++) mma16816(acc[i][j], ah[i], bh[j]);
#pragma unroll
      for (int i = 0; i < 4; i++)
#pragma unroll
        for (int j = 0; j < 4; j++) mma16816(acc[i][j], ah[i], bl[j]);
#pragma unroll
      for (int i = 0; i < 4; i++)
#pragma unroll
        for (int j = 0; j < 4; j++) mma16816(acc[i][j], al[i], bh[j]);
    }
    __syncthreads();

    if (c + 2 < NCH)
      load_chunk(sb + (c & 1) * STAGEB, Ahb, Alb, Bhb, Blb, (c + 2) * BKC,
                 tid);
  }

  // Epilogue
  int mat = 0;
  const float* bias = b0p;
  if (FUSED) {
    mat = n0 >> 10;  // uniform per block
    bias = (mat == 0) ? b0p : (mat == 1) ? b1p : b2p;
  }
#pragma unroll
  for (int i = 0; i < 4; i++) {
#pragma unroll
    for (int j = 0; j < 4; j++) {
      const int col = n0 + wn0 + j * 8 + tig * 2;
      const int cloc = col & (NN - 1);
      const float bb0 = __ldg(bias + cloc);
      const float bb1 = __ldg(bias + cloc + 1);
#pragma unroll
      for (int hh = 0; hh < 2; hh++) {
        const int m = m0 + wm0 + i * 16 + gid + hh * 8;
        float v0 = acc[i][j][hh * 2 + 0] + bb0;
        float v1 = acc[i][j][hh * 2 + 1] + bb1;
        if (!FUSED) {
          *(float2*)(out + (size_t)m * NN + col) = make_float2(v0, v1);
        } else {
          const int b = m >> 11, t = m & (TT - 1);
          const int h = cloc >> 6, hd = cloc & (HD - 1);
          const size_t ho = (((size_t)b * HH + h) * TT + t) * HD + hd;
          uint32_t hw, lw;
          if (mat == 0) {  // Q: pre-scale by 1/8 (exact)
            split2(v0 * 0.125f, v1 * 0.125f, hw, lw);
            *(uint32_t*)(qh + ho) = hw;
            *(uint32_t*)(ql + ho) = lw;
          } else if (mat == 1) {  // K
            *(float2*)(kout + ho) = make_float2(v0, v1);
            split2(v0, v1, hw, lw);
            *(uint32_t*)(kh + ho) = hw;
            *(uint32_t*)(kl + ho) = lw;
          } else {  // V
            *(float2*)(vout + ho) = make_float2(v0, v1);
            split2(v0, v1, hw, lw);
            *(uint32_t*)(vh + ho) = hw;
            *(uint32_t*)(vl + ho) = lw;
          }
        }
      }
    }
  }
}

// ---------------------------------------------------------------------------
// Tensor-core causal flash attention, split-bf16 (3-term) for both matmuls.
// S-phase: K-tiles in groups of 4, MMAs term-major (same-acc distance 4).
// PV-phase: 2 np-pairs (4 accs) per group, term-major (distance 4).
// ---------------------------------------------------------------------------
#define AROW 144
#define QSZ (128 * AROW)
#define KSZ (64 * AROW)
#define STG4 (4 * KSZ)
#define ATT_SMEM (2 * QSZ + 2 * STG4)

__device__ __forceinline__ void loadkv(uint32_t st, const __nv_bfloat16* khp,
                                       const __nv_bfloat16* klp,
                                       const __nv_bfloat16* vhp,
                                       const __nv_bfloat16* vlp, int kv0,
                                       int tid) {
#pragma unroll
  for (int it = 0; it < 8; it++) {
    const int arr = it >> 1;
    const int rem = ((it & 1) << 8) + tid;
    const int row = rem >> 3, c = rem & 7;
    const __nv_bfloat16* base = (arr == 0) ? khp : (arr == 1) ? klp
                                : (arr == 2) ? vhp : vlp;
    cpasync16(st + arr * KSZ + row * AROW + c * 16,
              base + (size_t)(kv0 + row) * HD + c * 8);
  }
}

__global__ __launch_bounds__(256, 2) void attn_mma(
    const __nv_bfloat16* __restrict__ qh, const __nv_bfloat16* __restrict__ ql,
    const __nv_bfloat16* __restrict__ kh, const __nv_bfloat16* __restrict__ kl,
    const __nv_bfloat16* __restrict__ vh, const __nv_bfloat16* __restrict__ vl,
    __nv_bfloat16* __restrict__ yh, __nv_bfloat16* __restrict__ yl) {
  extern __shared__ __align__(128) uint8_t smem_raw[];
  const uint32_t sb = smem_u32(smem_raw);
  const int tid = threadIdx.x;
  const int w = tid >> 5, lane = tid & 31;
  const int gid = lane >> 2, tig = lane & 3;
  const int qblk = blockIdx.x, h = blockIdx.y, b = blockIdx.z;
  const int q0 = qblk * 128;
  const size_t hoff = (((size_t)b * HH + h) * TT) * HD;
  const __nv_bfloat16* qhp = qh + hoff;
  const __nv_bfloat16* qlp = ql + hoff;
  const __nv_bfloat16* khp = kh + hoff;
  const __nv_bfloat16* klp = kl + hoff;
  const __nv_bfloat16* vhp = vh + hoff;
  const __nv_bfloat16* vlp = vl + hoff;

#pragma unroll
  for (int it = 0; it < 8; it++) {
    const int arr = it >> 2;
    const int rem = ((it & 3) << 8) + tid;
    const int row = rem >> 3, c = rem & 7;
    cpasync16(sb + arr * QSZ + row * AROW + c * 16,
              (arr ? qlp : qhp) + (size_t)(q0 + row) * HD + c * 8);
  }
  loadkv(sb + 2 * QSZ, khp, klp, vhp, vlp, 0, tid);
  CP_COMMIT();
  loadkv(sb + 2 * QSZ + STG4, khp, klp, vhp, vlp, 64, tid);
  CP_COMMIT();

  float s[8][4], o[8][4];
  float mrow[2] = {-INFINITY, -INFINITY};
  float lrow[2] = {0.f, 0.f};
#pragma unroll
  for (int j = 0; j < 8; j++)
#pragma unroll
    for (int r = 0; r < 4; r++) o[j][r] = 0.f;

  const int amat = lane >> 3;
  const int arow_in = ((amat & 1) << 3) + (lane & 7);
  const int acol = (amat >> 1) << 4;
  const int brow_in = lane & 7;
  const int bcol = ((lane >> 3) & 1) << 4;
  const int ntiles = 2 * qblk + 2;

  for (int t = 0; t < ntiles; t++) {
    if (t + 1 < ntiles)
      asm volatile("cp.async.wait_group 1;" ::: "memory");
    else
      asm volatile("cp.async.wait_group 0;" ::: "memory");
    __syncthreads();

    const uint32_t st = sb + 2 * QSZ + (t & 1) * STG4;
    const uint32_t tKh = st, tKl = st + KSZ;
    const uint32_t tVh = st + 2 * KSZ, tVl = st + 3 * KSZ;

#pragma unroll
    for (int j = 0; j < 8; j++)
#pragma unroll
      for (int r = 0; r < 4; r++) s[j][r] = 0.f;

    // ---- S = Q K^T: j-groups of 4, term-major MMA order ----
#pragma unroll
    for (int kk = 0; kk < 4; kk++) {
      uint32_t aq[4], aql[4];
      const uint32_t qo = (w * 16 + arow_in) * AROW + kk * 32 + acol;
      ldsm4(aq, sb + qo);
      ldsm4(aql, sb + QSZ + qo);
#pragma unroll
      for (int g = 0; g < 2; g++) {
        uint32_t kbf[4][2], klf[4][2];
#pragma unroll
        for (int jj = 0; jj < 4; jj++) {
          const uint32_t ko =
              ((g * 4 + jj) * 8 + brow_in) * AROW + kk * 32 + bcol;
          ldsm2(kbf[jj], tKh + ko);
          ldsm2(klf[jj], tKl + ko);
        }
#pragma unroll
        for (int jj = 0; jj < 4; jj++) mma16816(s[g * 4 + jj], aq, kbf[jj]);
#pragma unroll
        for (int jj = 0; jj < 4; jj++) mma16816(s[g * 4 + jj], aq, klf[jj]);
#pragma unroll
        for (int jj = 0; jj < 4; jj++) mma16816(s[g * 4 + jj], aql, kbf[jj]);
      }
    }

    const int kv0 = t * 64;
    if (kv0 + 63 > q0) {
#pragma unroll
      for (int j = 0; j < 8; j++) {
        const int jg = kv0 + j * 8 + tig * 2;
#pragma unroll
        for (int r = 0; r < 2; r++) {
          const int rg = q0 + w * 16 + gid + r * 8;
          if (jg > rg) s[j][r * 2] = -INFINITY;
          if (jg + 1 > rg) s[j][r * 2 + 1] = -INFINITY;
        }
      }
    }

#pragma unroll
    for (int r = 0; r < 2; r++) {
      float mx = mrow[r];
#pragma unroll
      for (int j = 0; j < 8; j++)
        mx = fmaxf(mx, fmaxf(s[j][r * 2], s[j][r * 2 + 1]));
      mx = fmaxf(mx, __shfl_xor_sync(0xffffffffu, mx, 1));
      mx = fmaxf(mx, __shfl_xor_sync(0xffffffffu, mx, 2));
      const float alpha = __expf(mrow[r] - mx);
      mrow[r] = mx;
      float ls = 0.f;
#pragma unroll
      for (int j = 0; j < 8; j++) {
        const float p0 = __expf(s[j][r * 2] - mx);
        const float p1 = __expf(s[j][r * 2 + 1] - mx);
        s[j][r * 2] = p0;
        s[j][r * 2 + 1] = p1;
        ls += p0 + p1;
      }
      ls += __shfl_xor_sync(0xffffffffu, ls, 1);
      ls += __shfl_xor_sync(0xffffffffu, ls, 2);
      lrow[r] = lrow[r] * alpha + ls;
#pragma unroll
      for (int j = 0; j < 8; j++) {
        o[j][r * 2] *= alpha;
        o[j][r * 2 + 1] *= alpha;
      }
    }

    // ---- O += P V: np-pairs (4 accs) per group, term-major ----
#pragma unroll
    for (int kk = 0; kk < 4; kk++) {
      uint32_t ph4[4], pl4[4];
#pragma unroll
      for (int half = 0; half < 2; half++) {
        const int j = 2 * kk + half;
        split2(s[j][0], s[j][1], ph4[half * 2 + 0], pl4[half * 2 + 0]);
        split2(s[j][2], s[j][3], ph4[half * 2 + 1], pl4[half * 2 + 1]);
      }
      const uint32_t vrow = kk * 16 + (lane & 15);
      const uint32_t vco = (lane >> 4) << 4;
#pragma unroll
      for (int npg = 0; npg < 2; npg++) {
        uint32_t vh4[2][4], vl4[2][4];
#pragma unroll
        for (int p = 0; p < 2; p++) {
          const uint32_t vo = vrow * AROW + (npg * 2 + p) * 32 + vco;
          ldsm4t(vh4[p], tVh + vo);
          ldsm4t(vl4[p], tVl + vo);
        }
#pragma unroll
        for (int p = 0; p < 2; p++) {
          const int np = npg * 2 + p;
          mma16816(o[2 * np], ph4, vh4[p]);
          mma16816(o[2 * np + 1], ph4, vh4[p] + 2);
        }
#pragma unroll
        for (int p = 0; p < 2; p++) {
          const int np = npg * 2 + p;
          mma16816(o[2 * np], ph4, vl4[p]);
          mma16816(o[2 * np + 1], ph4, vl4[p] + 2);
        }
#pragma unroll
        for (int p = 0; p < 2; p++) {
          const int np = npg * 2 + p;
          mma16816(o[2 * np], pl4, vh4[p]);
          mma16816(o[2 * np + 1], pl4, vh4[p] + 2);
        }
      }
    }
    __syncthreads();

    if (t + 2 < ntiles) {
      loadkv(st, khp, klp, vhp, vlp, (t + 2) * 64, tid);
      CP_COMMIT();
    }
  }

  const float i0 = 1.f / lrow[0];
  const float i1 = 1.f / lrow[1];
  const int r0 = q0 + w * 16 + gid;
  const size_t base0 = ((size_t)b * TT + r0) * CC + h * HD;
  const size_t base1 = base0 + (size_t)8 * CC;
#pragma unroll
  for (int n = 0; n < 8; n++) {
    const int col = n * 8 + tig * 2;
    uint32_t hw, lw;
    split2(o[n][0] * i0, o[n][1] * i0, hw, lw);
    *(uint32_t*)(yh + base0 + col) = hw;
    *(uint32_t*)(yl + base0 + col) = lw;
    split2(o[n][2] * i1, o[n][3] * i1, hw, lw);
    *(uint32_t*)(yh + base1 + col) = hw;
    *(uint32_t*)(yl + base1 + col) = lw;
  }
}

// ---------------------------------------------------------------------------
// kernel_launch
// ---------------------------------------------------------------------------
extern "C" void kernel_launch(void* const* d_in, const int* in_sizes, int n_in,
                              void* d_out, int out_size) {
  const float* x = (const float*)d_in[0];
  const float* Wq = (const float*)d_in[2];
  const float* bq = (const float*)d_in[3];
  const float* Wk = (const float*)d_in[4];
  const float* bk = (const float*)d_in[5];
  const float* Wv = (const float*)d_in[6];
  const float* bv = (const float*)d_in[7];
  const float* Wp = (const float*)d_in[8];
  const float* bp = (const float*)d_in[9];

  float* out = (float*)d_out;
  float* kout = out + (size_t)BB * TT * CC;        // present[0] = k
  float* vout = kout + (size_t)BB * HH * TT * HD;  // present[1] = v

  __nv_bfloat16 *xh, *xl, *wh, *wl, *yh, *yl;
  __nv_bfloat16 *qhb, *qlb, *khb, *klb, *vhb, *vlb;
  cudaGetSymbolAddress((void**)&xh, g_xh);
  cudaGetSymbolAddress((void**)&xl, g_xl);
  cudaGetSymbolAddress((void**)&wh, g_wh);
  cudaGetSymbolAddress((void**)&wl, g_wl);
  cudaGetSymbolAddress((void**)&yh, g_yh);
  cudaGetSymbolAddress((void**)&yl, g_yl);
  cudaGetSymbolAddress((void**)&qhb, g_qh);
  cudaGetSymbolAddress((void**)&qlb, g_ql);
  cudaGetSymbolAddress((void**)&khb, g_kh);
  cudaGetSymbolAddress((void**)&klb, g_kl);
  cudaGetSymbolAddress((void**)&vhb, g_vh);
  cudaGetSymbolAddress((void**)&vlb, g_vl);

  // #1: fused conversions (x split + 4 W transposes)
  conv_all<<<dim3(32, 32, 5), dim3(32, 8)>>>(x, Wq, Wk, Wv, Wp, xh, xl, wh, wl);

  // #2: fused QKV projection (tensor core, 2 CTAs/SM)
  cudaFuncSetAttribute(gemm_tc<1>, cudaFuncAttributeMaxDynamicSharedMemorySize,
                       GEMM_SMEM);
  cudaFuncSetAttribute(gemm_tc<0>, cudaFuncAttributeMaxDynamicSharedMemorySize,
                       GEMM_SMEM);
  dim3 qkvgrid(3 * NN / 128, MM / 128);  // (24, 64)
  gemm_tc<1><<<qkvgrid, 256, GEMM_SMEM>>>(xh, xl, wh, wl, bq, bk, bv, nullptr,
                                          kout, vout, qhb, qlb, khb, klb, vhb,
                                          vlb);

  // #3: tensor-core attention
  cudaFuncSetAttribute(attn_mma, cudaFuncAttributeMaxDynamicSharedMemorySize,
                       ATT_SMEM);
  dim3 agrid(TT / 128, HH, BB);
  attn_mma<<<agrid, 256, ATT_SMEM>>>(qhb, qlb, khb, klb, vhb, vlb, yh, yl);

  // #4: output projection (lands under ncu -s 5)
  const size_t WSZ = (size_t)KK * NN;
  dim3 pgrid(NN / 128, MM / 128);
  gemm_tc<0><<<pgrid, 256, GEMM_SMEM>>>(yh, yl, wh + 3 * WSZ, wl + 3 * WSZ, bp,
                                        nullptr, nullptr, out, nullptr, nullptr,
                                        nullptr, nullptr, nullptr, nullptr,
                                        nullptr, nullptr);
}

// round 12
// speedup vs baseline: 1.1963x; 1.1588x over previous
#include <cuda_runtime.h>
#include <cuda_bf16.h>
#include <cuda_fp16.h>
#include <cstdint>
#include <math.h>

// Problem constants
#define BB 4
#define TT 2048
#define CC 1024
#define HH 16
#define HD 64
#define MM (BB * TT)   // 8192
#define KK CC          // 1024
#define NN CC          // 1024

// ---------------------------------------------------------------------------
// Scratch (__device__ globals; no allocation allowed)
// ---------------------------------------------------------------------------
__device__ __half g_xh[(size_t)MM * KK];          // x hi (fp16)
__device__ __half g_xl[(size_t)MM * KK];          // x lo (fp16 residual)
__device__ __half g_wt[(size_t)4 * KK * NN];      // W^T fp16 [N,K]; Q,K,V,P
__device__ __half g_yh[(size_t)MM * NN];          // y hi (fp16)
__device__ __half g_yl[(size_t)MM * NN];          // y lo (fp16 residual)
// head-layout bf16 splits of q/k/v for attention (q pre-scaled by 1/8)
__device__ __nv_bfloat16 g_qh[(size_t)BB * HH * TT * HD];
__device__ __nv_bfloat16 g_ql[(size_t)BB * HH * TT * HD];
__device__ __nv_bfloat16 g_kh[(size_t)BB * HH * TT * HD];
__device__ __nv_bfloat16 g_kl[(size_t)BB * HH * TT * HD];
__device__ __nv_bfloat16 g_vh[(size_t)BB * HH * TT * HD];
__device__ __nv_bfloat16 g_vl[(size_t)BB * HH * TT * HD];

// ---------------------------------------------------------------------------
// PTX helpers (base compute_100-safe: cp.async / ldmatrix / mma.sync only)
// ---------------------------------------------------------------------------
__device__ __forceinline__ uint32_t smem_u32(const void* p) {
  uint32_t a;
  asm("{ .reg .u64 t; cvta.to.shared.u64 t, %1; cvt.u32.u64 %0, t; }"
      : "=r"(a) : "l"(p));
  return a;
}
__device__ __forceinline__ void cpasync16(uint32_t dst, const void* src) {
  asm volatile("cp.async.cg.shared.global [%0], [%1], 16;" ::"r"(dst),
               "l"(src));
}
#define CP_COMMIT() asm volatile("cp.async.commit_group;" ::: "memory")

__device__ __forceinline__ void ldsm4(uint32_t* r, uint32_t addr) {
  asm volatile(
      "ldmatrix.sync.aligned.m8n8.x4.shared.b16 {%0,%1,%2,%3}, [%4];"
      : "=r"(r[0]), "=r"(r[1]), "=r"(r[2]), "=r"(r[3])
      : "r"(addr));
}
__device__ __forceinline__ void ldsm2(uint32_t* r, uint32_t addr) {
  asm volatile("ldmatrix.sync.aligned.m8n8.x2.shared.b16 {%0,%1}, [%2];"
               : "=r"(r[0]), "=r"(r[1])
               : "r"(addr));
}
__device__ __forceinline__ void ldsm4t(uint32_t* r, uint32_t addr) {
  asm volatile(
      "ldmatrix.sync.aligned.m8n8.x4.trans.shared.b16 {%0,%1,%2,%3}, [%4];"
      : "=r"(r[0]), "=r"(r[1]), "=r"(r[2]), "=r"(r[3])
      : "r"(addr));
}

// D += A @ B (m16n8k16, bf16 in, fp32 acc)
__device__ __forceinline__ void mma16816(float* c, const uint32_t* a,
                                         const uint32_t* b) {
  asm volatile(
      "mma.sync.aligned.m16n8k16.row.col.f32.bf16.bf16.f32 "
      "{%0,%1,%2,%3}, {%4,%5,%6,%7}, {%8,%9}, {%0,%1,%2,%3};"
      : "+f"(c[0]), "+f"(c[1]), "+f"(c[2]), "+f"(c[3])
      : "r"(a[0]), "r"(a[1]), "r"(a[2]), "r"(a[3]), "r"(b[0]), "r"(b[1]));
}
// D += A @ B (m16n8k16, fp16 in, fp32 acc)
__device__ __forceinline__ void mma16816h(float* c, const uint32_t* a,
                                          const uint32_t* b) {
  asm volatile(
      "mma.sync.aligned.m16n8k16.row.col.f32.f16.f16.f32 "
      "{%0,%1,%2,%3}, {%4,%5,%6,%7}, {%8,%9}, {%0,%1,%2,%3};"
      : "+f"(c[0]), "+f"(c[1]), "+f"(c[2]), "+f"(c[3])
      : "r"(a[0]), "r"(a[1]), "r"(a[2]), "r"(a[3]), "r"(b[0]), "r"(b[1]));
}

// hi/lo split of two floats, packed bf16x2
__device__ __forceinline__ void split2(float a, float b, uint32_t& hi,
                                       uint32_t& lo) {
  __nv_bfloat16 h0 = __float2bfloat16(a);
  __nv_bfloat16 h1 = __float2bfloat16(b);
  __nv_bfloat16 l0 = __float2bfloat16(a - __bfloat162float(h0));
  __nv_bfloat16 l1 = __float2bfloat16(b - __bfloat162float(h1));
  hi = (uint32_t)__bfloat16_as_ushort(h0) |
       ((uint32_t)__bfloat16_as_ushort(h1) << 16);
  lo = (uint32_t)__bfloat16_as_ushort(l0) |
       ((uint32_t)__bfloat16_as_ushort(l1) << 16);
}
// hi/lo split of two floats, packed fp16x2
__device__ __forceinline__ void split2h(float a, float b, uint32_t& hi,
                                        uint32_t& lo) {
  __half h0 = __float2half_rn(a);
  __half h1 = __float2half_rn(b);
  __half l0 = __float2half_rn(a - __half2float(h0));
  __half l1 = __float2half_rn(b - __half2float(h1));
  hi = (uint32_t)__half_as_ushort(h0) | ((uint32_t)__half_as_ushort(h1) << 16);
  lo = (uint32_t)__half_as_ushort(l0) | ((uint32_t)__half_as_ushort(l1) << 16);
}

// ---------------------------------------------------------------------------
// Fused conversion kernel: z=0 -> x fp16 hi/lo split (vectorized);
// z=1..4 -> W transpose to fp16 [N,K] for Wq,Wk,Wv,Wp (single term).
// ---------------------------------------------------------------------------
__global__ void conv_all(const float* __restrict__ x,
                         const float* __restrict__ Wq,
                         const float* __restrict__ Wk,
                         const float* __restrict__ Wv,
                         const float* __restrict__ Wp,
                         __half* __restrict__ xh, __half* __restrict__ xl,
                         __half* __restrict__ wt) {
  __shared__ float tile[32][33];
  const int z = blockIdx.z;
  const int tx = threadIdx.x, ty = threadIdx.y;
  if (z == 0) {
    const int bid = blockIdx.y * 32 + blockIdx.x;
    const int t = ty * 32 + tx;
    const float4* src = (const float4*)x + (size_t)bid * 2048;
    uint2* dh = (uint2*)xh + (size_t)bid * 2048;
    uint2* dl = (uint2*)xl + (size_t)bid * 2048;
#pragma unroll
    for (int it = 0; it < 8; it++) {
      const int i4 = it * 256 + t;
      float4 v = src[i4];
      uint32_t h0, l0, h1, l1;
      split2h(v.x, v.y, h0, l0);
      split2h(v.z, v.w, h1, l1);
      dh[i4] = make_uint2(h0, h1);
      dl[i4] = make_uint2(l0, l1);
    }
  } else {
    const float* W = (z == 1) ? Wq : (z == 2) ? Wk : (z == 3) ? Wv : Wp;
    const size_t WSZ = (size_t)KK * NN;
    __half* th = wt + (size_t)(z - 1) * WSZ;
    const int x0 = blockIdx.x * 32;  // n
    const int y0 = blockIdx.y * 32;  // k
#pragma unroll
    for (int r = 0; r < 32; r += 8)
      tile[ty + r][tx] = W[(size_t)(y0 + ty + r) * NN + x0 + tx];
    __syncthreads();
#pragma unroll
    for (int r = 0; r < 32; r += 8) {
      float v = tile[tx][ty + r];
      th[(size_t)(x0 + ty + r) * KK + y0 + tx] = __float2half_rn(v);
    }
  }
}

// ---------------------------------------------------------------------------
// mma.sync 2-term fp16 GEMM: out = (Ah+Al)[M,K] @ W[N,K]^T + bias.
// A split exact to O(u^2); only W's fp16 rounding contributes (~3e-4).
// 128x128 block tile, BKC=32, NST=2 double-buffered, 3 tiles/stage -> 60KB.
// FUSED=1: QKV fused (grid.x spans 3*NN/128); routes epilogue by n0>>10.
// FUSED=0: proj; fp32 row-major out + bias b0p.
// ---------------------------------------------------------------------------
#define BKC 32
#define ROWB 80
#define TILEB (128 * ROWB)           // 10240
#define STAGEB (3 * TILEB)           // 30720 (Ah, Al, W)
#define NST 2
#define NCH (KK / BKC)               // 32
#define GEMM_SMEM (NST * STAGEB)     // 61440

__device__ __forceinline__ void load_tile32(uint32_t sbase, const __half* g,
                                            int tid) {
#pragma unroll
  for (int it = 0; it < 2; it++) {
    const int lin = it * 256 + tid;
    const int row = lin >> 2, cc = lin & 3;
    cpasync16(sbase + row * ROWB + cc * 16, g + (size_t)row * KK + cc * 8);
  }
}

__device__ __forceinline__ void load_chunk(uint32_t st, const __half* Ahb,
                                           const __half* Alb,
                                           const __half* Wb, int k0, int tid) {
  load_tile32(st + 0 * TILEB, Ahb + k0, tid);
  load_tile32(st + 1 * TILEB, Alb + k0, tid);
  load_tile32(st + 2 * TILEB, Wb + k0, tid);
  CP_COMMIT();
}

template <int FUSED>
__global__ __launch_bounds__(256, 2) void gemm_tc(
    const __half* __restrict__ Ah, const __half* __restrict__ Al,
    const __half* __restrict__ Bw, const float* __restrict__ b0p,
    const float* __restrict__ b1p, const float* __restrict__ b2p,
    float* __restrict__ out, float* __restrict__ kout,
    float* __restrict__ vout, __nv_bfloat16* __restrict__ qh,
    __nv_bfloat16* __restrict__ ql, __nv_bfloat16* __restrict__ kh,
    __nv_bfloat16* __restrict__ kl, __nv_bfloat16* __restrict__ vh,
    __nv_bfloat16* __restrict__ vl) {
  extern __shared__ __align__(128) uint8_t smem_raw[];
  const uint32_t sb = smem_u32(smem_raw);
  const int tid = threadIdx.x;
  const int wid = tid >> 5, lane = tid & 31;
  const int gid = lane >> 2, tig = lane & 3;
  const int n0 = blockIdx.x * 128;
  const int m0 = blockIdx.y * 128;
  const int wm0 = (wid & 1) * 64;
  const int wn0 = (wid >> 1) * 32;

  const __half* Ahb = Ah + (size_t)m0 * KK;
  const __half* Alb = Al + (size_t)m0 * KK;
  const __half* Wb = Bw + (size_t)n0 * KK;

  float acc[4][4][4];
#pragma unroll
  for (int i = 0; i < 4; i++)
#pragma unroll
    for (int j = 0; j < 4; j++)
#pragma unroll
      for (int r = 0; r < 4; r++) acc[i][j][r] = 0.f;

  const int amat = lane >> 3;
  const int arow_in = ((amat & 1) << 3) + (lane & 7);
  const int acol = (amat >> 1) << 4;
  const int brow_in = lane & 7;
  const int bcol = ((lane >> 3) & 1) << 4;

  // Prologue: chunks 0,1 into stages 0,1
#pragma unroll
  for (int c = 0; c < 2; c++)
    load_chunk(sb + c * STAGEB, Ahb, Alb, Wb, c * BKC, tid);

  for (int c = 0; c < NCH; c++) {
    if (c + 1 < NCH)
      asm volatile("cp.async.wait_group 1;" ::: "memory");
    else
      asm volatile("cp.async.wait_group 0;" ::: "memory");
    __syncthreads();

    const uint32_t st = sb + (c & 1) * STAGEB;
    const uint32_t tAh = st + 0 * TILEB;
    const uint32_t tAl = st + 1 * TILEB;
    const uint32_t tBw = st + 2 * TILEB;

#pragma unroll
    for (int ks = 0; ks < 2; ks++) {
      const int kb = ks * 32;
      uint32_t ah[4][4], al[4][4], bw[4][2];
#pragma unroll
      for (int i = 0; i < 4; i++) {
        const uint32_t ao = (wm0 + i * 16 + arow_in) * ROWB + kb + acol;
        ldsm4(ah[i], tAh + ao);
        ldsm4(al[i], tAl + ao);
      }
#pragma unroll
      for (int j = 0; j < 4; j++) {
        const uint32_t bo = (wn0 + j * 8 + brow_in) * ROWB + kb + bcol;
        ldsm2(bw[j], tBw + bo);
      }
      // Term-major (same-acc distance 16)
#pragma unroll
      for (int i = 0; i < 4; i++)
#pragma unroll
        for (int j = 0; j < 4; j++) mma16816h(acc[i][j], ah[i], bw[j]);
#pragma unroll
      for (int i = 0; i < 4; i++)
#pragma unroll
        for (int j = 0; j < 4; j++) mma16816h(acc[i][j], al[i], bw[j]);
    }
    __syncthreads();

    if (c + 2 < NCH)
      load_chunk(sb + (c & 1) * STAGEB, Ahb, Alb, Wb, (c + 2) * BKC, tid);
  }

  // Epilogue
  int mat = 0;
  const float* bias = b0p;
  if (FUSED) {
    mat = n0 >> 10;  // uniform per block
    bias = (mat == 0) ? b0p : (mat == 1) ? b1p : b2p;
  }
#pragma unroll
  for (int i = 0; i < 4; i++) {
#pragma unroll
    for (int j = 0; j < 4; j++) {
      const int col = n0 + wn0 + j * 8 + tig * 2;
      const int cloc = col & (NN - 1);
      const float bb0 = __ldg(bias + cloc);
      const float bb1 = __ldg(bias + cloc + 1);
#pragma unroll
      for (int hh = 0; hh < 2; hh++) {
        const int m = m0 + wm0 + i * 16 + gid + hh * 8;
        float v0 = acc[i][j][hh * 2 + 0] + bb0;
        float v1 = acc[i][j][hh * 2 + 1] + bb1;
        if (!FUSED) {
          *(float2*)(out + (size_t)m * NN + col) = make_float2(v0, v1);
        } else {
          const int b = m >> 11, t = m & (TT - 1);
          const int h = cloc >> 6, hd = cloc & (HD - 1);
          const size_t ho = (((size_t)b * HH + h) * TT + t) * HD + hd;
          uint32_t hw, lw;
          if (mat == 0) {  // Q: pre-scale by 1/8 (exact), bf16 split for attn
            split2(v0 * 0.125f, v1 * 0.125f, hw, lw);
            *(uint32_t*)(qh + ho) = hw;
            *(uint32_t*)(ql + ho) = lw;
          } else if (mat == 1) {  // K
            *(float2*)(kout + ho) = make_float2(v0, v1);
            split2(v0, v1, hw, lw);
            *(uint32_t*)(kh + ho) = hw;
            *(uint32_t*)(kl + ho) = lw;
          } else {  // V
            *(float2*)(vout + ho) = make_float2(v0, v1);
            split2(v0, v1, hw, lw);
            *(uint32_t*)(vh + ho) = hw;
            *(uint32_t*)(vl + ho) = lw;
          }
        }
      }
    }
  }
}

// ---------------------------------------------------------------------------
// Tensor-core causal flash attention, split-bf16 (3-term) for both matmuls.
// (R10 version — measured equal to best; epilogue now emits fp16 hi/lo y.)
// ---------------------------------------------------------------------------
#define AROW 144
#define QSZ (128 * AROW)
#define KSZ (64 * AROW)
#define STG4 (4 * KSZ)
#define ATT_SMEM (2 * QSZ + 2 * STG4)

__device__ __forceinline__ void loadkv(uint32_t st, const __nv_bfloat16* khp,
                                       const __nv_bfloat16* klp,
                                       const __nv_bfloat16* vhp,
                                       const __nv_bfloat16* vlp, int kv0,
                                       int tid) {
#pragma unroll
  for (int it = 0; it < 8; it++) {
    const int arr = it >> 1;
    const int rem = ((it & 1) << 8) + tid;
    const int row = rem >> 3, c = rem & 7;
    const __nv_bfloat16* base = (arr == 0) ? khp : (arr == 1) ? klp
                                : (arr == 2) ? vhp : vlp;
    cpasync16(st + arr * KSZ + row * AROW + c * 16,
              base + (size_t)(kv0 + row) * HD + c * 8);
  }
}

__global__ __launch_bounds__(256, 2) void attn_mma(
    const __nv_bfloat16* __restrict__ qh, const __nv_bfloat16* __restrict__ ql,
    const __nv_bfloat16* __restrict__ kh, const __nv_bfloat16* __restrict__ kl,
    const __nv_bfloat16* __restrict__ vh, const __nv_bfloat16* __restrict__ vl,
    __half* __restrict__ yh, __half* __restrict__ yl) {
  extern __shared__ __align__(128) uint8_t smem_raw[];
  const uint32_t sb = smem_u32(smem_raw);
  const int tid = threadIdx.x;
  const int w = tid >> 5, lane = tid & 31;
  const int gid = lane >> 2, tig = lane & 3;
  const int qblk = blockIdx.x, h = blockIdx.y, b = blockIdx.z;
  const int q0 = qblk * 128;
  const size_t hoff = (((size_t)b * HH + h) * TT) * HD;
  const __nv_bfloat16* qhp = qh + hoff;
  const __nv_bfloat16* qlp = ql + hoff;
  const __nv_bfloat16* khp = kh + hoff;
  const __nv_bfloat16* klp = kl + hoff;
  const __nv_bfloat16* vhp = vh + hoff;
  const __nv_bfloat16* vlp = vl + hoff;

#pragma unroll
  for (int it = 0; it < 8; it++) {
    const int arr = it >> 2;
    const int rem = ((it & 3) << 8) + tid;
    const int row = rem >> 3, c = rem & 7;
    cpasync16(sb + arr * QSZ + row * AROW + c * 16,
              (arr ? qlp : qhp) + (size_t)(q0 + row) * HD + c * 8);
  }
  loadkv(sb + 2 * QSZ, khp, klp, vhp, vlp, 0, tid);
  CP_COMMIT();
  loadkv(sb + 2 * QSZ + STG4, khp, klp, vhp, vlp, 64, tid);
  CP_COMMIT();

  float s[8][4], o[8][4];
  float mrow[2] = {-INFINITY, -INFINITY};
  float lrow[2] = {0.f, 0.f};
#pragma unroll
  for (int j = 0; j < 8; j++)
#pragma unroll
    for (int r = 0; r < 4; r++) o[j][r] = 0.f;

  const int amat = lane >> 3;
  const int arow_in = ((amat & 1) << 3) + (lane & 7);
  const int acol = (amat >> 1) << 4;
  const int brow_in = lane & 7;
  const int bcol = ((lane >> 3) & 1) << 4;
  const int ntiles = 2 * qblk + 2;

  for (int t = 0; t < ntiles; t++) {
    if (t + 1 < ntiles)
      asm volatile("cp.async.wait_group 1;" ::: "memory");
    else
      asm volatile("cp.async.wait_group 0;" ::: "memory");
    __syncthreads();

    const uint32_t st = sb + 2 * QSZ + (t & 1) * STG4;
    const uint32_t tKh = st, tKl = st + KSZ;
    const uint32_t tVh = st + 2 * KSZ, tVl = st + 3 * KSZ;

#pragma unroll
    for (int j = 0; j < 8; j++)
#pragma unroll
      for (int r = 0; r < 4; r++) s[j][r] = 0.f;

#pragma unroll
    for (int kk = 0; kk < 4; kk++) {
      uint32_t aq[4], aql[4];
      const uint32_t qo = (w * 16 + arow_in) * AROW + kk * 32 + acol;
      ldsm4(aq, sb + qo);
      ldsm4(aql, sb + QSZ + qo);
#pragma unroll
      for (int g = 0; g < 2; g++) {
        uint32_t kbf[4][2], klf[4][2];
#pragma unroll
        for (int jj = 0; jj < 4; jj++) {
          const uint32_t ko =
              ((g * 4 + jj) * 8 + brow_in) * AROW + kk * 32 + bcol;
          ldsm2(kbf[jj], tKh + ko);
          ldsm2(klf[jj], tKl + ko);
        }
#pragma unroll
        for (int jj = 0; jj < 4; jj++) mma16816(s[g * 4 + jj], aq, kbf[jj]);
#pragma unroll
        for (int jj = 0; jj < 4; jj++) mma16816(s[g * 4 + jj], aq, klf[jj]);
#pragma unroll
        for (int jj = 0; jj < 4; jj++) mma16816(s[g * 4 + jj], aql, kbf[jj]);
      }
    }

    const int kv0 = t * 64;
    if (kv0 + 63 > q0) {
#pragma unroll
      for (int j = 0; j < 8; j++) {
        const int jg = kv0 + j * 8 + tig * 2;
#pragma unroll
        for (int r = 0; r < 2; r++) {
          const int rg = q0 + w * 16 + gid + r * 8;
          if (jg > rg) s[j][r * 2] = -INFINITY;
          if (jg + 1 > rg) s[j][r * 2 + 1] = -INFINITY;
        }
      }
    }

#pragma unroll
    for (int r = 0; r < 2; r++) {
      float mx = mrow[r];
#pragma unroll
      for (int j = 0; j < 8; j++)
        mx = fmaxf(mx, fmaxf(s[j][r * 2], s[j][r * 2 + 1]));
      mx = fmaxf(mx, __shfl_xor_sync(0xffffffffu, mx, 1));
      mx = fmaxf(mx, __shfl_xor_sync(0xffffffffu, mx, 2));
      const float alpha = __expf(mrow[r] - mx);
      mrow[r] = mx;
      float ls = 0.f;
#pragma unroll
      for (int j = 0; j < 8; j++) {
        const float p0 = __expf(s[j][r * 2] - mx);
        const float p1 = __expf(s[j][r * 2 + 1] - mx);
        s[j][r * 2] = p0;
        s[j][r * 2 + 1] = p1;
        ls += p0 + p1;
      }
      ls += __shfl_xor_sync(0xffffffffu, ls, 1);
      ls += __shfl_xor_sync(0xffffffffu, ls, 2);
      lrow[r] = lrow[r] * alpha + ls;
#pragma unroll
      for (int j = 0; j < 8; j++) {
        o[j][r * 2] *= alpha;
        o[j][r * 2 + 1] *= alpha;
      }
    }

#pragma unroll
    for (int kk = 0; kk < 4; kk++) {
      uint32_t ph4[4], pl4[4];
#pragma unroll
      for (int half = 0; half < 2; half++) {
        const int j = 2 * kk + half;
        split2(s[j][0], s[j][1], ph4[half * 2 + 0], pl4[half * 2 + 0]);
        split2(s[j][2], s[j][3], ph4[half * 2 + 1], pl4[half * 2 + 1]);
      }
      const uint32_t vrow = kk * 16 + (lane & 15);
      const uint32_t vco = (lane >> 4) << 4;
#pragma unroll
      for (int npg = 0; npg < 2; npg++) {
        uint32_t vh4[2][4], vl4[2][4];
#pragma unroll
        for (int p = 0; p < 2; p++) {
          const uint32_t vo = vrow * AROW + (npg * 2 + p) * 32 + vco;
          ldsm4t(vh4[p], tVh + vo);
          ldsm4t(vl4[p], tVl + vo);
        }
#pragma unroll
        for (int p = 0; p < 2; p++) {
          const int np = npg * 2 + p;
          mma16816(o[2 * np], ph4, vh4[p]);
          mma16816(o[2 * np + 1], ph4, vh4[p] + 2);
        }
#pragma unroll
        for (int p = 0; p < 2; p++) {
          const int np = npg * 2 + p;
          mma16816(o[2 * np], ph4, vl4[p]);
          mma16816(o[2 * np + 1], ph4, vl4[p] + 2);
        }
#pragma unroll
        for (int p = 0; p < 2; p++) {
          const int np = npg * 2 + p;
          mma16816(o[2 * np], pl4, vh4[p]);
          mma16816(o[2 * np + 1], pl4, vh4[p] + 2);
        }
      }
    }
    __syncthreads();

    if (t + 2 < ntiles) {
      loadkv(st, khp, klp, vhp, vlp, (t + 2) * 64, tid);
      CP_COMMIT();
    }
  }

  // Epilogue: normalize, emit fp16 hi/lo y for the proj GEMM.
  const float i0 = 1.f / lrow[0];
  const float i1 = 1.f / lrow[1];
  const int r0 = q0 + w * 16 + gid;
  const size_t base0 = ((size_t)b * TT + r0) * CC + h * HD;
  const size_t base1 = base0 + (size_t)8 * CC;
#pragma unroll
  for (int n = 0; n < 8; n++) {
    const int col = n * 8 + tig * 2;
    uint32_t hw, lw;
    split2h(o[n][0] * i0, o[n][1] * i0, hw, lw);
    *(uint32_t*)(yh + base0 + col) = hw;
    *(uint32_t*)(yl + base0 + col) = lw;
    split2h(o[n][2] * i1, o[n][3] * i1, hw, lw);
    *(uint32_t*)(yh + base1 + col) = hw;
    *(uint32_t*)(yl + base1 + col) = lw;
  }
}

// ---------------------------------------------------------------------------
// kernel_launch
// ---------------------------------------------------------------------------
extern "C" void kernel_launch(void* const* d_in, const int* in_sizes, int n_in,
                              void* d_out, int out_size) {
  const float* x = (const float*)d_in[0];
  const float* Wq = (const float*)d_in[2];
  const float* bq = (const float*)d_in[3];
  const float* Wk = (const float*)d_in[4];
  const float* bk = (const float*)d_in[5];
  const float* Wv = (const float*)d_in[6];
  const float* bv = (const float*)d_in[7];
  const float* Wp = (const float*)d_in[8];
  const float* bp = (const float*)d_in[9];

  float* out = (float*)d_out;
  float* kout = out + (size_t)BB * TT * CC;        // present[0] = k
  float* vout = kout + (size_t)BB * HH * TT * HD;  // present[1] = v

  __half *xh, *xl, *wt, *yh, *yl;
  __nv_bfloat16 *qhb, *qlb, *khb, *klb, *vhb, *vlb;
  cudaGetSymbolAddress((void**)&xh, g_xh);
  cudaGetSymbolAddress((void**)&xl, g_xl);
  cudaGetSymbolAddress((void**)&wt, g_wt);
  cudaGetSymbolAddress((void**)&yh, g_yh);
  cudaGetSymbolAddress((void**)&yl, g_yl);
  cudaGetSymbolAddress((void**)&qhb, g_qh);
  cudaGetSymbolAddress((void**)&qlb, g_ql);
  cudaGetSymbolAddress((void**)&khb, g_kh);
  cudaGetSymbolAddress((void**)&klb, g_kl);
  cudaGetSymbolAddress((void**)&vhb, g_vh);
  cudaGetSymbolAddress((void**)&vlb, g_vl);

  // #1: fused conversions (x fp16 split + 4 W transposes to fp16)
  conv_all<<<dim3(32, 32, 5), dim3(32, 8)>>>(x, Wq, Wk, Wv, Wp, xh, xl, wt);

  // #2: fused QKV projection (2-term fp16, tensor core, 2 CTAs/SM)
  cudaFuncSetAttribute(gemm_tc<1>, cudaFuncAttributeMaxDynamicSharedMemorySize,
                       GEMM_SMEM);
  cudaFuncSetAttribute(gemm_tc<0>, cudaFuncAttributeMaxDynamicSharedMemorySize,
                       GEMM_SMEM);
  dim3 qkvgrid(3 * NN / 128, MM / 128);  // (24, 64)
  gemm_tc<1><<<qkvgrid, 256, GEMM_SMEM>>>(xh, xl, wt, bq, bk, bv, nullptr,
                                          kout, vout, qhb, qlb, khb, klb, vhb,
                                          vlb);

  // #3: tensor-core attention (bf16 3-term, unchanged)
  cudaFuncSetAttribute(attn_mma, cudaFuncAttributeMaxDynamicSharedMemorySize,
                       ATT_SMEM);
  dim3 agrid(TT / 128, HH, BB);
  attn_mma<<<agrid, 256, ATT_SMEM>>>(qhb, qlb, khb, klb, vhb, vlb, yh, yl);

  // #4: output projection (lands under ncu -s 5)
  const size_t WSZ = (size_t)KK * NN;
  dim3 pgrid(NN / 128, MM / 128);
  gemm_tc<0><<<pgrid, 256, GEMM_SMEM>>>(yh, yl, wt + 3 * WSZ, bp, nullptr,
                                        nullptr, out, nullptr, nullptr, nullptr,
                                        nullptr, nullptr, nullptr, nullptr,
                                        nullptr);
}

// round 14
// speedup vs baseline: 1.4690x; 1.2279x over previous
#include <cuda_runtime.h>
#include <cuda_bf16.h>
#include <cuda_fp16.h>
#include <cstdint>
#include <math.h>

// Problem constants
#define BB 4
#define TT 2048
#define CC 1024
#define HH 16
#define HD 64
#define MM (BB * TT)   // 8192
#define KK CC          // 1024
#define NN CC          // 1024

// ---------------------------------------------------------------------------
// Scratch (__device__ globals; no allocation allowed)
// ---------------------------------------------------------------------------
__device__ __half g_xh[(size_t)MM * KK];          // x hi (fp16)
__device__ __half g_xl[(size_t)MM * KK];          // x lo (fp16 residual)
__device__ __half g_wt[(size_t)4 * KK * NN];      // W^T fp16 [N,K]; Q,K,V,P
__device__ __half g_yh[(size_t)MM * NN];          // y hi (fp16)
__device__ __half g_yl[(size_t)MM * NN];          // y lo (fp16 residual)
// head-layout fp16 attention operands (q pre-scaled by 1/8, split; k/v single)
__device__ __half g_qh[(size_t)BB * HH * TT * HD];
__device__ __half g_ql[(size_t)BB * HH * TT * HD];
__device__ __half g_kf[(size_t)BB * HH * TT * HD];
__device__ __half g_vf[(size_t)BB * HH * TT * HD];

// ---------------------------------------------------------------------------
// PTX helpers (base compute_100-safe: cp.async / ldmatrix / mma.sync only)
// ---------------------------------------------------------------------------
__device__ __forceinline__ uint32_t smem_u32(const void* p) {
  uint32_t a;
  asm("{ .reg .u64 t; cvta.to.shared.u64 t, %1; cvt.u32.u64 %0, t; }"
      : "=r"(a) : "l"(p));
  return a;
}
__device__ __forceinline__ void cpasync16(uint32_t dst, const void* src) {
  asm volatile("cp.async.cg.shared.global [%0], [%1], 16;" ::"r"(dst),
               "l"(src));
}
#define CP_COMMIT() asm volatile("cp.async.commit_group;" ::: "memory")

__device__ __forceinline__ void ldsm4(uint32_t* r, uint32_t addr) {
  asm volatile(
      "ldmatrix.sync.aligned.m8n8.x4.shared.b16 {%0,%1,%2,%3}, [%4];"
      : "=r"(r[0]), "=r"(r[1]), "=r"(r[2]), "=r"(r[3])
      : "r"(addr));
}
__device__ __forceinline__ void ldsm2(uint32_t* r, uint32_t addr) {
  asm volatile("ldmatrix.sync.aligned.m8n8.x2.shared.b16 {%0,%1}, [%2];"
               : "=r"(r[0]), "=r"(r[1])
               : "r"(addr));
}
__device__ __forceinline__ void ldsm4t(uint32_t* r, uint32_t addr) {
  asm volatile(
      "ldmatrix.sync.aligned.m8n8.x4.trans.shared.b16 {%0,%1,%2,%3}, [%4];"
      : "=r"(r[0]), "=r"(r[1]), "=r"(r[2]), "=r"(r[3])
      : "r"(addr));
}

// D += A @ B (m16n8k16, fp16 in, fp32 acc)
__device__ __forceinline__ void mma16816h(float* c, const uint32_t* a,
                                          const uint32_t* b) {
  asm volatile(
      "mma.sync.aligned.m16n8k16.row.col.f32.f16.f16.f32 "
      "{%0,%1,%2,%3}, {%4,%5,%6,%7}, {%8,%9}, {%0,%1,%2,%3};"
      : "+f"(c[0]), "+f"(c[1]), "+f"(c[2]), "+f"(c[3])
      : "r"(a[0]), "r"(a[1]), "r"(a[2]), "r"(a[3]), "r"(b[0]), "r"(b[1]));
}

// pack two fp16
__device__ __forceinline__ uint32_t pack2h(float a, float b) {
  return (uint32_t)__half_as_ushort(__float2half_rn(a)) |
         ((uint32_t)__half_as_ushort(__float2half_rn(b)) << 16);
}
// hi/lo split of two floats, packed fp16x2
__device__ __forceinline__ void split2h(float a, float b, uint32_t& hi,
                                        uint32_t& lo) {
  __half h0 = __float2half_rn(a);
  __half h1 = __float2half_rn(b);
  __half l0 = __float2half_rn(a - __half2float(h0));
  __half l1 = __float2half_rn(b - __half2float(h1));
  hi = (uint32_t)__half_as_ushort(h0) | ((uint32_t)__half_as_ushort(h1) << 16);
  lo = (uint32_t)__half_as_ushort(l0) | ((uint32_t)__half_as_ushort(l1) << 16);
}

// ---------------------------------------------------------------------------
// Fused conversion kernel: z=0 -> x fp16 hi/lo split (vectorized);
// z=1..4 -> W transpose to fp16 [N,K] for Wq,Wk,Wv,Wp (single term).
// ---------------------------------------------------------------------------
__global__ void conv_all(const float* __restrict__ x,
                         const float* __restrict__ Wq,
                         const float* __restrict__ Wk,
                         const float* __restrict__ Wv,
                         const float* __restrict__ Wp,
                         __half* __restrict__ xh, __half* __restrict__ xl,
                         __half* __restrict__ wt) {
  __shared__ float tile[32][33];
  const int z = blockIdx.z;
  const int tx = threadIdx.x, ty = threadIdx.y;
  if (z == 0) {
    const int bid = blockIdx.y * 32 + blockIdx.x;
    const int t = ty * 32 + tx;
    const float4* src = (const float4*)x + (size_t)bid * 2048;
    uint2* dh = (uint2*)xh + (size_t)bid * 2048;
    uint2* dl = (uint2*)xl + (size_t)bid * 2048;
#pragma unroll
    for (int it = 0; it < 8; it++) {
      const int i4 = it * 256 + t;
      float4 v = src[i4];
      uint32_t h0, l0, h1, l1;
      split2h(v.x, v.y, h0, l0);
      split2h(v.z, v.w, h1, l1);
      dh[i4] = make_uint2(h0, h1);
      dl[i4] = make_uint2(l0, l1);
    }
  } else {
    const float* W = (z == 1) ? Wq : (z == 2) ? Wk : (z == 3) ? Wv : Wp;
    const size_t WSZ = (size_t)KK * NN;
    __half* th = wt + (size_t)(z - 1) * WSZ;
    const int x0 = blockIdx.x * 32;  // n
    const int y0 = blockIdx.y * 32;  // k
#pragma unroll
    for (int r = 0; r < 32; r += 8)
      tile[ty + r][tx] = W[(size_t)(y0 + ty + r) * NN + x0 + tx];
    __syncthreads();
#pragma unroll
    for (int r = 0; r < 32; r += 8) {
      float v = tile[tx][ty + r];
      th[(size_t)(x0 + ty + r) * KK + y0 + tx] = __float2half_rn(v);
    }
  }
}

// ---------------------------------------------------------------------------
// mma.sync 2-term fp16 GEMM: out = (Ah+Al)[M,K] @ W[N,K]^T + bias.
// 128x128 block tile, BKC=32, NST=2 double-buffered, 3 tiles/stage -> 60KB.
// FUSED=1: QKV fused; FUSED=0: proj (fp32 row-major out).
// ---------------------------------------------------------------------------
#define BKC 32
#define ROWB 80
#define TILEB (128 * ROWB)           // 10240
#define STAGEB (3 * TILEB)           // 30720 (Ah, Al, W)
#define NST 2
#define NCH (KK / BKC)               // 32
#define GEMM_SMEM (NST * STAGEB)     // 61440

__device__ __forceinline__ void load_tile32(uint32_t sbase, const __half* g,
                                            int tid) {
#pragma unroll
  for (int it = 0; it < 2; it++) {
    const int lin = it * 256 + tid;
    const int row = lin >> 2, cc = lin & 3;
    cpasync16(sbase + row * ROWB + cc * 16, g + (size_t)row * KK + cc * 8);
  }
}

__device__ __forceinline__ void load_chunk(uint32_t st, const __half* Ahb,
                                           const __half* Alb,
                                           const __half* Wb, int k0, int tid) {
  load_tile32(st + 0 * TILEB, Ahb + k0, tid);
  load_tile32(st + 1 * TILEB, Alb + k0, tid);
  load_tile32(st + 2 * TILEB, Wb + k0, tid);
  CP_COMMIT();
}

template <int FUSED>
__global__ __launch_bounds__(256, 2) void gemm_tc(
    const __half* __restrict__ Ah, const __half* __restrict__ Al,
    const __half* __restrict__ Bw, const float* __restrict__ b0p,
    const float* __restrict__ b1p, const float* __restrict__ b2p,
    float* __restrict__ out, float* __restrict__ kout,
    float* __restrict__ vout, __half* __restrict__ qh,
    __half* __restrict__ ql, __half* __restrict__ kf,
    __half* __restrict__ vf) {
  extern __shared__ __align__(128) uint8_t smem_raw[];
  const uint32_t sb = smem_u32(smem_raw);
  const int tid = threadIdx.x;
  const int wid = tid >> 5, lane = tid & 31;
  const int gid = lane >> 2, tig = lane & 3;
  const int n0 = blockIdx.x * 128;
  const int m0 = blockIdx.y * 128;
  const int wm0 = (wid & 1) * 64;
  const int wn0 = (wid >> 1) * 32;

  const __half* Ahb = Ah + (size_t)m0 * KK;
  const __half* Alb = Al + (size_t)m0 * KK;
  const __half* Wb = Bw + (size_t)n0 * KK;

  float acc[4][4][4];
#pragma unroll
  for (int i = 0; i < 4; i++)
#pragma unroll
    for (int j = 0; j < 4; j++)
#pragma unroll
      for (int r = 0; r < 4; r++) acc[i][j][r] = 0.f;

  const int amat = lane >> 3;
  const int arow_in = ((amat & 1) << 3) + (lane & 7);
  const int acol = (amat >> 1) << 4;
  const int brow_in = lane & 7;
  const int bcol = ((lane >> 3) & 1) << 4;

#pragma unroll
  for (int c = 0; c < 2; c++)
    load_chunk(sb + c * STAGEB, Ahb, Alb, Wb, c * BKC, tid);

  for (int c = 0; c < NCH; c++) {
    if (c + 1 < NCH)
      asm volatile("cp.async.wait_group 1;" ::: "memory");
    else
      asm volatile("cp.async.wait_group 0;" ::: "memory");
    __syncthreads();

    const uint32_t st = sb + (c & 1) * STAGEB;
    const uint32_t tAh = st + 0 * TILEB;
    const uint32_t tAl = st + 1 * TILEB;
    const uint32_t tBw = st + 2 * TILEB;

#pragma unroll
    for (int ks = 0; ks < 2; ks++) {
      const int kb = ks * 32;
      uint32_t ah[4][4], al[4][4], bw[4][2];
#pragma unroll
      for (int i = 0; i < 4; i++) {
        const uint32_t ao = (wm0 + i * 16 + arow_in) * ROWB + kb + acol;
        ldsm4(ah[i], tAh + ao);
        ldsm4(al[i], tAl + ao);
      }
#pragma unroll
      for (int j = 0; j < 4; j++) {
        const uint32_t bo = (wn0 + j * 8 + brow_in) * ROWB + kb + bcol;
        ldsm2(bw[j], tBw + bo);
      }
#pragma unroll
      for (int i = 0; i < 4; i++)
#pragma unroll
        for (int j = 0; j < 4; j++) mma16816h(acc[i][j], ah[i], bw[j]);
#pragma unroll
      for (int i = 0; i < 4; i++)
#pragma unroll
        for (int j = 0; j < 4; j++) mma16816h(acc[i][j], al[i], bw[j]);
    }
    __syncthreads();

    if (c + 2 < NCH)
      load_chunk(sb + (c & 1) * STAGEB, Ahb, Alb, Wb, (c + 2) * BKC, tid);
  }

  // Epilogue
  int mat = 0;
  const float* bias = b0p;
  if (FUSED) {
    mat = n0 >> 10;  // uniform per block
    bias = (mat == 0) ? b0p : (mat == 1) ? b1p : b2p;
  }
#pragma unroll
  for (int i = 0; i < 4; i++) {
#pragma unroll
    for (int j = 0; j < 4; j++) {
      const int col = n0 + wn0 + j * 8 + tig * 2;
      const int cloc = col & (NN - 1);
      const float bb0 = __ldg(bias + cloc);
      const float bb1 = __ldg(bias + cloc + 1);
#pragma unroll
      for (int hh = 0; hh < 2; hh++) {
        const int m = m0 + wm0 + i * 16 + gid + hh * 8;
        float v0 = acc[i][j][hh * 2 + 0] + bb0;
        float v1 = acc[i][j][hh * 2 + 1] + bb1;
        if (!FUSED) {
          *(float2*)(out + (size_t)m * NN + col) = make_float2(v0, v1);
        } else {
          const int b = m >> 11, t = m & (TT - 1);
          const int h = cloc >> 6, hd = cloc & (HD - 1);
          const size_t ho = (((size_t)b * HH + h) * TT + t) * HD + hd;
          if (mat == 0) {  // Q: pre-scale by 1/8 (exact), fp16 split
            uint32_t hw, lw;
            split2h(v0 * 0.125f, v1 * 0.125f, hw, lw);
            *(uint32_t*)(qh + ho) = hw;
            *(uint32_t*)(ql + ho) = lw;
          } else if (mat == 1) {  // K: fp32 out + single fp16 for attn
            *(float2*)(kout + ho) = make_float2(v0, v1);
            *(uint32_t*)(kf + ho) = pack2h(v0, v1);
          } else {  // V
            *(float2*)(vout + ho) = make_float2(v0, v1);
            *(uint32_t*)(vf + ho) = pack2h(v0, v1);
          }
        }
      }
    }
  }
}

// ---------------------------------------------------------------------------
// Tensor-core causal flash attention, 2-term fp16:
// S = (qh+ql)·k  (q split exact; k single fp16)
// O += (ph+pl)·v (p split exact; v single fp16)
// KV smem: 2 arrays/stage (halved vs bf16 3-term); MMAs/tile 192 -> 128.
// ---------------------------------------------------------------------------
#define AROW 144
#define QSZ (128 * AROW)              // 18432
#define KSZ (64 * AROW)               // 9216
#define STG2 (2 * KSZ)                // 18432 (k, v)
#define ATT_SMEM (2 * QSZ + 2 * STG2) // 73728

__device__ __forceinline__ void loadkv(uint32_t st, const __half* kfp,
                                       const __half* vfp, int kv0, int tid) {
#pragma unroll
  for (int it = 0; it < 4; it++) {
    const int arr = it >> 1;                 // 0: k, 1: v
    const int rem = ((it & 1) << 8) + tid;   // 0..511
    const int row = rem >> 3, c = rem & 7;
    const __half* base = arr ? vfp : kfp;
    cpasync16(st + arr * KSZ + row * AROW + c * 16,
              base + (size_t)(kv0 + row) * HD + c * 8);
  }
}

__global__ __launch_bounds__(256, 2) void attn_mma(
    const __half* __restrict__ qh, const __half* __restrict__ ql,
    const __half* __restrict__ kf, const __half* __restrict__ vf,
    __half* __restrict__ yh, __half* __restrict__ yl) {
  extern __shared__ __align__(128) uint8_t smem_raw[];
  const uint32_t sb = smem_u32(smem_raw);
  const int tid = threadIdx.x;
  const int w = tid >> 5, lane = tid & 31;
  const int gid = lane >> 2, tig = lane & 3;
  const int qblk = blockIdx.x, h = blockIdx.y, b = blockIdx.z;
  const int q0 = qblk * 128;
  const size_t hoff = (((size_t)b * HH + h) * TT) * HD;
  const __half* qhp = qh + hoff;
  const __half* qlp = ql + hoff;
  const __half* kfp = kf + hoff;
  const __half* vfp = vf + hoff;

#pragma unroll
  for (int it = 0; it < 8; it++) {
    const int arr = it >> 2;
    const int rem = ((it & 3) << 8) + tid;
    const int row = rem >> 3, c = rem & 7;
    cpasync16(sb + arr * QSZ + row * AROW + c * 16,
              (arr ? qlp : qhp) + (size_t)(q0 + row) * HD + c * 8);
  }
  loadkv(sb + 2 * QSZ, kfp, vfp, 0, tid);
  CP_COMMIT();
  loadkv(sb + 2 * QSZ + STG2, kfp, vfp, 64, tid);
  CP_COMMIT();

  float s[8][4], o[8][4];
  float mrow[2] = {-INFINITY, -INFINITY};
  float lrow[2] = {0.f, 0.f};
#pragma unroll
  for (int j = 0; j < 8; j++)
#pragma unroll
    for (int r = 0; r < 4; r++) o[j][r] = 0.f;

  const int amat = lane >> 3;
  const int arow_in = ((amat & 1) << 3) + (lane & 7);
  const int acol = (amat >> 1) << 4;
  const int brow_in = lane & 7;
  const int bcol = ((lane >> 3) & 1) << 4;
  const int ntiles = 2 * qblk + 2;

  for (int t = 0; t < ntiles; t++) {
    if (t + 1 < ntiles)
      asm volatile("cp.async.wait_group 1;" ::: "memory");
    else
      asm volatile("cp.async.wait_group 0;" ::: "memory");
    __syncthreads();

    const uint32_t st = sb + 2 * QSZ + (t & 1) * STG2;
    const uint32_t tK = st, tV = st + KSZ;

#pragma unroll
    for (int j = 0; j < 8; j++)
#pragma unroll
      for (int r = 0; r < 4; r++) s[j][r] = 0.f;

    // ---- S = (qh+ql) K^T: j-groups of 4, term-major ----
#pragma unroll
    for (int kk = 0; kk < 4; kk++) {
      uint32_t aq[4], aql[4];
      const uint32_t qo = (w * 16 + arow_in) * AROW + kk * 32 + acol;
      ldsm4(aq, sb + qo);
      ldsm4(aql, sb + QSZ + qo);
#pragma unroll
      for (int g = 0; g < 2; g++) {
        uint32_t kbf[4][2];
#pragma unroll
        for (int jj = 0; jj < 4; jj++) {
          const uint32_t ko =
              ((g * 4 + jj) * 8 + brow_in) * AROW + kk * 32 + bcol;
          ldsm2(kbf[jj], tK + ko);
        }
#pragma unroll
        for (int jj = 0; jj < 4; jj++) mma16816h(s[g * 4 + jj], aq, kbf[jj]);
#pragma unroll
        for (int jj = 0; jj < 4; jj++) mma16816h(s[g * 4 + jj], aql, kbf[jj]);
      }
    }

    const int kv0 = t * 64;
    if (kv0 + 63 > q0) {
#pragma unroll
      for (int j = 0; j < 8; j++) {
        const int jg = kv0 + j * 8 + tig * 2;
#pragma unroll
        for (int r = 0; r < 2; r++) {
          const int rg = q0 + w * 16 + gid + r * 8;
          if (jg > rg) s[j][r * 2] = -INFINITY;
          if (jg + 1 > rg) s[j][r * 2 + 1] = -INFINITY;
        }
      }
    }

#pragma unroll
    for (int r = 0; r < 2; r++) {
      float mx = mrow[r];
#pragma unroll
      for (int j = 0; j < 8; j++)
        mx = fmaxf(mx, fmaxf(s[j][r * 2], s[j][r * 2 + 1]));
      mx = fmaxf(mx, __shfl_xor_sync(0xffffffffu, mx, 1));
      mx = fmaxf(mx, __shfl_xor_sync(0xffffffffu, mx, 2));
      const float alpha = __expf(mrow[r] - mx);
      mrow[r] = mx;
      float ls = 0.f;
#pragma unroll
      for (int j = 0; j < 8; j++) {
        const float p0 = __expf(s[j][r * 2] - mx);
        const float p1 = __expf(s[j][r * 2 + 1] - mx);
        s[j][r * 2] = p0;
        s[j][r * 2 + 1] = p1;
        ls += p0 + p1;
      }
      ls += __shfl_xor_sync(0xffffffffu, ls, 1);
      ls += __shfl_xor_sync(0xffffffffu, ls, 2);
      lrow[r] = lrow[r] * alpha + ls;
#pragma unroll
      for (int j = 0; j < 8; j++) {
        o[j][r * 2] *= alpha;
        o[j][r * 2 + 1] *= alpha;
      }
    }

    // ---- O += (ph+pl) V: term-major across np-pairs ----
#pragma unroll
    for (int kk = 0; kk < 4; kk++) {
      uint32_t ph4[4], pl4[4];
#pragma unroll
      for (int half = 0; half < 2; half++) {
        const int j = 2 * kk + half;
        split2h(s[j][0], s[j][1], ph4[half * 2 + 0], pl4[half * 2 + 0]);
        split2h(s[j][2], s[j][3], ph4[half * 2 + 1], pl4[half * 2 + 1]);
      }
      const uint32_t vrow = kk * 16 + (lane & 15);
      const uint32_t vco = (lane >> 4) << 4;
#pragma unroll
      for (int npg = 0; npg < 2; npg++) {
        uint32_t vfr[2][4];
#pragma unroll
        for (int p = 0; p < 2; p++) {
          const uint32_t vo = vrow * AROW + (npg * 2 + p) * 32 + vco;
          ldsm4t(vfr[p], tV + vo);
        }
#pragma unroll
        for (int p = 0; p < 2; p++) {
          const int np = npg * 2 + p;
          mma16816h(o[2 * np], ph4, vfr[p]);
          mma16816h(o[2 * np + 1], ph4, vfr[p] + 2);
        }
#pragma unroll
        for (int p = 0; p < 2; p++) {
          const int np = npg * 2 + p;
          mma16816h(o[2 * np], pl4, vfr[p]);
          mma16816h(o[2 * np + 1], pl4, vfr[p] + 2);
        }
      }
    }
    __syncthreads();

    if (t + 2 < ntiles) {
      loadkv(st, kfp, vfp, (t + 2) * 64, tid);
      CP_COMMIT();
    }
  }

  // Epilogue: normalize, emit fp16 hi/lo y for the proj GEMM.
  const float i0 = 1.f / lrow[0];
  const float i1 = 1.f / lrow[1];
  const int r0 = q0 + w * 16 + gid;
  const size_t base0 = ((size_t)b * TT + r0) * CC + h * HD;
  const size_t base1 = base0 + (size_t)8 * CC;
#pragma unroll
  for (int n = 0; n < 8; n++) {
    const int col = n * 8 + tig * 2;
    uint32_t hw, lw;
    split2h(o[n][0] * i0, o[n][1] * i0, hw, lw);
    *(uint32_t*)(yh + base0 + col) = hw;
    *(uint32_t*)(yl + base0 + col) = lw;
    split2h(o[n][2] * i1, o[n][3] * i1, hw, lw);
    *(uint32_t*)(yh + base1 + col) = hw;
    *(uint32_t*)(yl + base1 + col) = lw;
  }
}

// ---------------------------------------------------------------------------
// kernel_launch
// ---------------------------------------------------------------------------
extern "C" void kernel_launch(void* const* d_in, const int* in_sizes, int n_in,
                              void* d_out, int out_size) {
  const float* x = (const float*)d_in[0];
  const float* Wq = (const float*)d_in[2];
  const float* bq = (const float*)d_in[3];
  const float* Wk = (const float*)d_in[4];
  const float* bk = (const float*)d_in[5];
  const float* Wv = (const float*)d_in[6];
  const float* bv = (const float*)d_in[7];
  const float* Wp = (const float*)d_in[8];
  const float* bp = (const float*)d_in[9];

  float* out = (float*)d_out;
  float* kout = out + (size_t)BB * TT * CC;        // present[0] = k
  float* vout = kout + (size_t)BB * HH * TT * HD;  // present[1] = v

  __half *xh, *xl, *wt, *yh, *yl, *qhb, *qlb, *kfb, *vfb;
  cudaGetSymbolAddress((void**)&xh, g_xh);
  cudaGetSymbolAddress((void**)&xl, g_xl);
  cudaGetSymbolAddress((void**)&wt, g_wt);
  cudaGetSymbolAddress((void**)&yh, g_yh);
  cudaGetSymbolAddress((void**)&yl, g_yl);
  cudaGetSymbolAddress((void**)&qhb, g_qh);
  cudaGetSymbolAddress((void**)&qlb, g_ql);
  cudaGetSymbolAddress((void**)&kfb, g_kf);
  cudaGetSymbolAddress((void**)&vfb, g_vf);

  // #1: fused conversions (x fp16 split + 4 W transposes to fp16)
  conv_all<<<dim3(32, 32, 5), dim3(32, 8)>>>(x, Wq, Wk, Wv, Wp, xh, xl, wt);

  // #2: fused QKV projection (2-term fp16, tensor core, 2 CTAs/SM)
  cudaFuncSetAttribute(gemm_tc<1>, cudaFuncAttributeMaxDynamicSharedMemorySize,
                       GEMM_SMEM);
  cudaFuncSetAttribute(gemm_tc<0>, cudaFuncAttributeMaxDynamicSharedMemorySize,
                       GEMM_SMEM);
  dim3 qkvgrid(3 * NN / 128, MM / 128);  // (24, 64)
  gemm_tc<1><<<qkvgrid, 256, GEMM_SMEM>>>(xh, xl, wt, bq, bk, bv, nullptr,
                                          kout, vout, qhb, qlb, kfb, vfb);

  // #3: tensor-core attention (2-term fp16)
  cudaFuncSetAttribute(attn_mma, cudaFuncAttributeMaxDynamicSharedMemorySize,
                       ATT_SMEM);
  dim3 agrid(TT / 128, HH, BB);
  attn_mma<<<agrid, 256, ATT_SMEM>>>(qhb, qlb, kfb, vfb, yh, yl);

  // #4: output projection (lands under ncu -s 5) — 13 args, matches signature
  const size_t WSZ = (size_t)KK * NN;
  dim3 pgrid(NN / 128, MM / 128);
  gemm_tc<0><<<pgrid, 256, GEMM_SMEM>>>(yh, yl, wt + 3 * WSZ, bp, nullptr,
                                        nullptr, out, nullptr, nullptr,
                                        nullptr, nullptr, nullptr, nullptr);
}

// round 15
// speedup vs baseline: 1.7259x; 1.1749x over previous
#include <cuda_runtime.h>
#include <cuda_bf16.h>
#include <cuda_fp16.h>
#include <cstdint>
#include <math.h>

// Problem constants
#define BB 4
#define TT 2048
#define CC 1024
#define HH 16
#define HD 64
#define MM (BB * TT)   // 8192
#define KK CC          // 1024
#define NN CC          // 1024

// ---------------------------------------------------------------------------
// Scratch (__device__ globals; no allocation allowed)
// ---------------------------------------------------------------------------
__device__ __half g_xf[(size_t)MM * KK];          // x fp16 (single term)
__device__ __half g_wt[(size_t)4 * KK * NN];      // W^T fp16 [N,K]; Q,K,V,P
__device__ __half g_yh[(size_t)MM * NN];          // y hi (fp16)
__device__ __half g_yl[(size_t)MM * NN];          // y lo (fp16 residual)
// head-layout fp16 attention operands (q pre-scaled by 1/8, split; k/v single)
__device__ __half g_qh[(size_t)BB * HH * TT * HD];
__device__ __half g_ql[(size_t)BB * HH * TT * HD];
__device__ __half g_kf[(size_t)BB * HH * TT * HD];
__device__ __half g_vf[(size_t)BB * HH * TT * HD];

// ---------------------------------------------------------------------------
// PTX helpers (base compute_100-safe: cp.async / ldmatrix / mma.sync only)
// ---------------------------------------------------------------------------
__device__ __forceinline__ uint32_t smem_u32(const void* p) {
  uint32_t a;
  asm("{ .reg .u64 t; cvta.to.shared.u64 t, %1; cvt.u32.u64 %0, t; }"
      : "=r"(a) : "l"(p));
  return a;
}
__device__ __forceinline__ void cpasync16(uint32_t dst, const void* src) {
  asm volatile("cp.async.cg.shared.global [%0], [%1], 16;" ::"r"(dst),
               "l"(src));
}
#define CP_COMMIT() asm volatile("cp.async.commit_group;" ::: "memory")

__device__ __forceinline__ void ldsm4(uint32_t* r, uint32_t addr) {
  asm volatile(
      "ldmatrix.sync.aligned.m8n8.x4.shared.b16 {%0,%1,%2,%3}, [%4];"
      : "=r"(r[0]), "=r"(r[1]), "=r"(r[2]), "=r"(r[3])
      : "r"(addr));
}
__device__ __forceinline__ void ldsm2(uint32_t* r, uint32_t addr) {
  asm volatile("ldmatrix.sync.aligned.m8n8.x2.shared.b16 {%0,%1}, [%2];"
               : "=r"(r[0]), "=r"(r[1])
               : "r"(addr));
}
__device__ __forceinline__ void ldsm4t(uint32_t* r, uint32_t addr) {
  asm volatile(
      "ldmatrix.sync.aligned.m8n8.x4.trans.shared.b16 {%0,%1,%2,%3}, [%4];"
      : "=r"(r[0]), "=r"(r[1]), "=r"(r[2]), "=r"(r[3])
      : "r"(addr));
}

// D += A @ B (m16n8k16, fp16 in, fp32 acc)
__device__ __forceinline__ void mma16816h(float* c, const uint32_t* a,
                                          const uint32_t* b) {
  asm volatile(
      "mma.sync.aligned.m16n8k16.row.col.f32.f16.f16.f32 "
      "{%0,%1,%2,%3}, {%4,%5,%6,%7}, {%8,%9}, {%0,%1,%2,%3};"
      : "+f"(c[0]), "+f"(c[1]), "+f"(c[2]), "+f"(c[3])
      : "r"(a[0]), "r"(a[1]), "r"(a[2]), "r"(a[3]), "r"(b[0]), "r"(b[1]));
}

// pack two fp16
__device__ __forceinline__ uint32_t pack2h(float a, float b) {
  return (uint32_t)__half_as_ushort(__float2half_rn(a)) |
         ((uint32_t)__half_as_ushort(__float2half_rn(b)) << 16);
}
// hi/lo split of two floats, packed fp16x2
__device__ __forceinline__ void split2h(float a, float b, uint32_t& hi,
                                        uint32_t& lo) {
  __half h0 = __float2half_rn(a);
  __half h1 = __float2half_rn(b);
  __half l0 = __float2half_rn(a - __half2float(h0));
  __half l1 = __float2half_rn(b - __half2float(h1));
  hi = (uint32_t)__half_as_ushort(h0) | ((uint32_t)__half_as_ushort(h1) << 16);
  lo = (uint32_t)__half_as_ushort(l0) | ((uint32_t)__half_as_ushort(l1) << 16);
}

// ---------------------------------------------------------------------------
// Fused conversion kernel: z=0 -> x fp16 (single term, vectorized);
// z=1..4 -> W transpose to fp16 [N,K] for Wq,Wk,Wv,Wp.
// ---------------------------------------------------------------------------
__global__ void conv_all(const float* __restrict__ x,
                         const float* __restrict__ Wq,
                         const float* __restrict__ Wk,
                         const float* __restrict__ Wv,
                         const float* __restrict__ Wp,
                         __half* __restrict__ xf, __half* __restrict__ wt) {
  __shared__ float tile[32][33];
  const int z = blockIdx.z;
  const int tx = threadIdx.x, ty = threadIdx.y;
  if (z == 0) {
    const int bid = blockIdx.y * 32 + blockIdx.x;
    const int t = ty * 32 + tx;
    const float4* src = (const float4*)x + (size_t)bid * 2048;
    uint2* df = (uint2*)xf + (size_t)bid * 2048;
#pragma unroll
    for (int it = 0; it < 8; it++) {
      const int i4 = it * 256 + t;
      float4 v = src[i4];
      df[i4] = make_uint2(pack2h(v.x, v.y), pack2h(v.z, v.w));
    }
  } else {
    const float* W = (z == 1) ? Wq : (z == 2) ? Wk : (z == 3) ? Wv : Wp;
    const size_t WSZ = (size_t)KK * NN;
    __half* th = wt + (size_t)(z - 1) * WSZ;
    const int x0 = blockIdx.x * 32;  // n
    const int y0 = blockIdx.y * 32;  // k
#pragma unroll
    for (int r = 0; r < 32; r += 8)
      tile[ty + r][tx] = W[(size_t)(y0 + ty + r) * NN + x0 + tx];
    __syncthreads();
#pragma unroll
    for (int r = 0; r < 32; r += 8) {
      float v = tile[tx][ty + r];
      th[(size_t)(x0 + ty + r) * KK + y0 + tx] = __float2half_rn(v);
    }
  }
}

// ---------------------------------------------------------------------------
// mma.sync fp16 GEMM, TERMS = number of A terms (1: single-fp16 A;
// 2: hi/lo-split A, exact to O(u^2)). 128x128 tile, BKC=32, NST=2.
// FUSED=1: QKV fused (TERMS=1); FUSED=0: proj (TERMS=2, fp32 out + bias).
// ---------------------------------------------------------------------------
#define BKC 32
#define ROWB 80
#define TILEB (128 * ROWB)           // 10240
#define NST 2
#define NCH (KK / BKC)               // 32
// per-TERMS stage bytes: (TERMS+1) tiles
#define STAGEB_T(T) ((T + 1) * TILEB)
#define GEMM_SMEM_T(T) (NST * STAGEB_T(T))

__device__ __forceinline__ void load_tile32(uint32_t sbase, const __half* g,
                                            int tid) {
#pragma unroll
  for (int it = 0; it < 2; it++) {
    const int lin = it * 256 + tid;
    const int row = lin >> 2, cc = lin & 3;
    cpasync16(sbase + row * ROWB + cc * 16, g + (size_t)row * KK + cc * 8);
  }
}

template <int FUSED, int TERMS>
__global__ __launch_bounds__(256, 2) void gemm_tc(
    const __half* __restrict__ Ah, const __half* __restrict__ Al,
    const __half* __restrict__ Bw, const float* __restrict__ b0p,
    const float* __restrict__ b1p, const float* __restrict__ b2p,
    float* __restrict__ out, float* __restrict__ kout,
    float* __restrict__ vout, __half* __restrict__ qh,
    __half* __restrict__ ql, __half* __restrict__ kf,
    __half* __restrict__ vf) {
  constexpr int STAGEB = STAGEB_T(TERMS);
  extern __shared__ __align__(128) uint8_t smem_raw[];
  const uint32_t sb = smem_u32(smem_raw);
  const int tid = threadIdx.x;
  const int wid = tid >> 5, lane = tid & 31;
  const int gid = lane >> 2, tig = lane & 3;
  const int n0 = blockIdx.x * 128;
  const int m0 = blockIdx.y * 128;
  const int wm0 = (wid & 1) * 64;
  const int wn0 = (wid >> 1) * 32;

  const __half* Ahb = Ah + (size_t)m0 * KK;
  const __half* Alb = (TERMS == 2) ? Al + (size_t)m0 * KK : nullptr;
  const __half* Wb = Bw + (size_t)n0 * KK;

  float acc[4][4][4];
#pragma unroll
  for (int i = 0; i < 4; i++)
#pragma unroll
    for (int j = 0; j < 4; j++)
#pragma unroll
      for (int r = 0; r < 4; r++) acc[i][j][r] = 0.f;

  const int amat = lane >> 3;
  const int arow_in = ((amat & 1) << 3) + (lane & 7);
  const int acol = (amat >> 1) << 4;
  const int brow_in = lane & 7;
  const int bcol = ((lane >> 3) & 1) << 4;

#pragma unroll
  for (int c = 0; c < 2; c++) {
    const uint32_t st = sb + c * STAGEB;
    load_tile32(st + 0 * TILEB, Ahb + c * BKC, tid);
    if (TERMS == 2) load_tile32(st + 1 * TILEB, Alb + c * BKC, tid);
    load_tile32(st + (TERMS)*TILEB, Wb + c * BKC, tid);
    CP_COMMIT();
  }

  for (int c = 0; c < NCH; c++) {
    if (c + 1 < NCH)
      asm volatile("cp.async.wait_group 1;" ::: "memory");
    else
      asm volatile("cp.async.wait_group 0;" ::: "memory");
    __syncthreads();

    const uint32_t st = sb + (c & 1) * STAGEB;
    const uint32_t tAh = st + 0 * TILEB;
    const uint32_t tAl = st + 1 * TILEB;
    const uint32_t tBw = st + (TERMS)*TILEB;

#pragma unroll
    for (int ks = 0; ks < 2; ks++) {
      const int kb = ks * 32;
      uint32_t ah[4][4], al[4][4], bw[4][2];
#pragma unroll
      for (int i = 0; i < 4; i++) {
        const uint32_t ao = (wm0 + i * 16 + arow_in) * ROWB + kb + acol;
        ldsm4(ah[i], tAh + ao);
        if (TERMS == 2) ldsm4(al[i], tAl + ao);
      }
#pragma unroll
      for (int j = 0; j < 4; j++) {
        const uint32_t bo = (wn0 + j * 8 + brow_in) * ROWB + kb + bcol;
        ldsm2(bw[j], tBw + bo);
      }
#pragma unroll
      for (int i = 0; i < 4; i++)
#pragma unroll
        for (int j = 0; j < 4; j++) mma16816h(acc[i][j], ah[i], bw[j]);
      if (TERMS == 2) {
#pragma unroll
        for (int i = 0; i < 4; i++)
#pragma unroll
          for (int j = 0; j < 4; j++) mma16816h(acc[i][j], al[i], bw[j]);
      }
    }
    __syncthreads();

    if (c + 2 < NCH) {
      const uint32_t stl = sb + (c & 1) * STAGEB;
      const int k0 = (c + 2) * BKC;
      load_tile32(stl + 0 * TILEB, Ahb + k0, tid);
      if (TERMS == 2) load_tile32(stl + 1 * TILEB, Alb + k0, tid);
      load_tile32(stl + (TERMS)*TILEB, Wb + k0, tid);
      CP_COMMIT();
    }
  }

  // Epilogue
  int mat = 0;
  const float* bias = b0p;
  if (FUSED) {
    mat = n0 >> 10;  // uniform per block
    bias = (mat == 0) ? b0p : (mat == 1) ? b1p : b2p;
  }
#pragma unroll
  for (int i = 0; i < 4; i++) {
#pragma unroll
    for (int j = 0; j < 4; j++) {
      const int col = n0 + wn0 + j * 8 + tig * 2;
      const int cloc = col & (NN - 1);
      const float bb0 = __ldg(bias + cloc);
      const float bb1 = __ldg(bias + cloc + 1);
#pragma unroll
      for (int hh = 0; hh < 2; hh++) {
        const int m = m0 + wm0 + i * 16 + gid + hh * 8;
        float v0 = acc[i][j][hh * 2 + 0] + bb0;
        float v1 = acc[i][j][hh * 2 + 1] + bb1;
        if (!FUSED) {
          *(float2*)(out + (size_t)m * NN + col) = make_float2(v0, v1);
        } else {
          const int b = m >> 11, t = m & (TT - 1);
          const int h = cloc >> 6, hd = cloc & (HD - 1);
          const size_t ho = (((size_t)b * HH + h) * TT + t) * HD + hd;
          if (mat == 0) {  // Q: pre-scale by 1/8 (exact), fp16 split
            uint32_t hw, lw;
            split2h(v0 * 0.125f, v1 * 0.125f, hw, lw);
            *(uint32_t*)(qh + ho) = hw;
            *(uint32_t*)(ql + ho) = lw;
          } else if (mat == 1) {  // K: fp32 out + single fp16 for attn
            *(float2*)(kout + ho) = make_float2(v0, v1);
            *(uint32_t*)(kf + ho) = pack2h(v0, v1);
          } else {  // V
            *(float2*)(vout + ho) = make_float2(v0, v1);
            *(uint32_t*)(vf + ho) = pack2h(v0, v1);
          }
        }
      }
    }
  }
}

// ---------------------------------------------------------------------------
// Tensor-core causal flash attention, 2-term fp16 (unchanged from R13 pass):
// S = (qh+ql)·k ; O += (ph+pl)·v
// ---------------------------------------------------------------------------
#define AROW 144
#define QSZ (128 * AROW)              // 18432
#define KSZ (64 * AROW)               // 9216
#define STG2 (2 * KSZ)                // 18432 (k, v)
#define ATT_SMEM (2 * QSZ + 2 * STG2) // 73728

__device__ __forceinline__ void loadkv(uint32_t st, const __half* kfp,
                                       const __half* vfp, int kv0, int tid) {
#pragma unroll
  for (int it = 0; it < 4; it++) {
    const int arr = it >> 1;                 // 0: k, 1: v
    const int rem = ((it & 1) << 8) + tid;   // 0..511
    const int row = rem >> 3, c = rem & 7;
    const __half* base = arr ? vfp : kfp;
    cpasync16(st + arr * KSZ + row * AROW + c * 16,
              base + (size_t)(kv0 + row) * HD + c * 8);
  }
}

__global__ __launch_bounds__(256, 2) void attn_mma(
    const __half* __restrict__ qh, const __half* __restrict__ ql,
    const __half* __restrict__ kf, const __half* __restrict__ vf,
    __half* __restrict__ yh, __half* __restrict__ yl) {
  extern __shared__ __align__(128) uint8_t smem_raw[];
  const uint32_t sb = smem_u32(smem_raw);
  const int tid = threadIdx.x;
  const int w = tid >> 5, lane = tid & 31;
  const int gid = lane >> 2, tig = lane & 3;
  const int qblk = blockIdx.x, h = blockIdx.y, b = blockIdx.z;
  const int q0 = qblk * 128;
  const size_t hoff = (((size_t)b * HH + h) * TT) * HD;
  const __half* qhp = qh + hoff;
  const __half* qlp = ql + hoff;
  const __half* kfp = kf + hoff;
  const __half* vfp = vf + hoff;

#pragma unroll
  for (int it = 0; it < 8; it++) {
    const int arr = it >> 2;
    const int rem = ((it & 3) << 8) + tid;
    const int row = rem >> 3, c = rem & 7;
    cpasync16(sb + arr * QSZ + row * AROW + c * 16,
              (arr ? qlp : qhp) + (size_t)(q0 + row) * HD + c * 8);
  }
  loadkv(sb + 2 * QSZ, kfp, vfp, 0, tid);
  CP_COMMIT();
  loadkv(sb + 2 * QSZ + STG2, kfp, vfp, 64, tid);
  CP_COMMIT();

  float s[8][4], o[8][4];
  float mrow[2] = {-INFINITY, -INFINITY};
  float lrow[2] = {0.f, 0.f};
#pragma unroll
  for (int j = 0; j < 8; j++)
#pragma unroll
    for (int r = 0; r < 4; r++) o[j][r] = 0.f;

  const int amat = lane >> 3;
  const int arow_in = ((amat & 1) << 3) + (lane & 7);
  const int acol = (amat >> 1) << 4;
  const int brow_in = lane & 7;
  const int bcol = ((lane >> 3) & 1) << 4;
  const int ntiles = 2 * qblk + 2;

  for (int t = 0; t < ntiles; t++) {
    if (t + 1 < ntiles)
      asm volatile("cp.async.wait_group 1;" ::: "memory");
    else
      asm volatile("cp.async.wait_group 0;" ::: "memory");
    __syncthreads();

    const uint32_t st = sb + 2 * QSZ + (t & 1) * STG2;
    const uint32_t tK = st, tV = st + KSZ;

#pragma unroll
    for (int j = 0; j < 8; j++)
#pragma unroll
      for (int r = 0; r < 4; r++) s[j][r] = 0.f;

#pragma unroll
    for (int kk = 0; kk < 4; kk++) {
      uint32_t aq[4], aql[4];
      const uint32_t qo = (w * 16 + arow_in) * AROW + kk * 32 + acol;
      ldsm4(aq, sb + qo);
      ldsm4(aql, sb + QSZ + qo);
#pragma unroll
      for (int g = 0; g < 2; g++) {
        uint32_t kbf[4][2];
#pragma unroll
        for (int jj = 0; jj < 4; jj++) {
          const uint32_t ko =
              ((g * 4 + jj) * 8 + brow_in) * AROW + kk * 32 + bcol;
          ldsm2(kbf[jj], tK + ko);
        }
#pragma unroll
        for (int jj = 0; jj < 4; jj++) mma16816h(s[g * 4 + jj], aq, kbf[jj]);
#pragma unroll
        for (int jj = 0; jj < 4; jj++) mma16816h(s[g * 4 + jj], aql, kbf[jj]);
      }
    }

    const int kv0 = t * 64;
    if (kv0 + 63 > q0) {
#pragma unroll
      for (int j = 0; j < 8; j++) {
        const int jg = kv0 + j * 8 + tig * 2;
#pragma unroll
        for (int r = 0; r < 2; r++) {
          const int rg = q0 + w * 16 + gid + r * 8;
          if (jg > rg) s[j][r * 2] = -INFINITY;
          if (jg + 1 > rg) s[j][r * 2 + 1] = -INFINITY;
        }
      }
    }

#pragma unroll
    for (int r = 0; r < 2; r++) {
      float mx = mrow[r];
#pragma unroll
      for (int j = 0; j < 8; j++)
        mx = fmaxf(mx, fmaxf(s[j][r * 2], s[j][r * 2 + 1]));
      mx = fmaxf(mx, __shfl_xor_sync(0xffffffffu, mx, 1));
      mx = fmaxf(mx, __shfl_xor_sync(0xffffffffu, mx, 2));
      const float alpha = __expf(mrow[r] - mx);
      mrow[r] = mx;
      float ls = 0.f;
#pragma unroll
      for (int j = 0; j < 8; j++) {
        const float p0 = __expf(s[j][r * 2] - mx);
        const float p1 = __expf(s[j][r * 2 + 1] - mx);
        s[j][r * 2] = p0;
        s[j][r * 2 + 1] = p1;
        ls += p0 + p1;
      }
      ls += __shfl_xor_sync(0xffffffffu, ls, 1);
      ls += __shfl_xor_sync(0xffffffffu, ls, 2);
      lrow[r] = lrow[r] * alpha + ls;
#pragma unroll
      for (int j = 0; j < 8; j++) {
        o[j][r * 2] *= alpha;
        o[j][r * 2 + 1] *= alpha;
      }
    }

#pragma unroll
    for (int kk = 0; kk < 4; kk++) {
      uint32_t ph4[4], pl4[4];
#pragma unroll
      for (int half = 0; half < 2; half++) {
        const int j = 2 * kk + half;
        split2h(s[j][0], s[j][1], ph4[half * 2 + 0], pl4[half * 2 + 0]);
        split2h(s[j][2], s[j][3], ph4[half * 2 + 1], pl4[half * 2 + 1]);
      }
      const uint32_t vrow = kk * 16 + (lane & 15);
      const uint32_t vco = (lane >> 4) << 4;
#pragma unroll
      for (int npg = 0; npg < 2; npg++) {
        uint32_t vfr[2][4];
#pragma unroll
        for (int p = 0; p < 2; p++) {
          const uint32_t vo = vrow * AROW + (npg * 2 + p) * 32 + vco;
          ldsm4t(vfr[p], tV + vo);
        }
#pragma unroll
        for (int p = 0; p < 2; p++) {
          const int np = npg * 2 + p;
          mma16816h(o[2 * np], ph4, vfr[p]);
          mma16816h(o[2 * np + 1], ph4, vfr[p] + 2);
        }
#pragma unroll
        for (int p = 0; p < 2; p++) {
          const int np = npg * 2 + p;
          mma16816h(o[2 * np], pl4, vfr[p]);
          mma16816h(o[2 * np + 1], pl4, vfr[p] + 2);
        }
      }
    }
    __syncthreads();

    if (t + 2 < ntiles) {
      loadkv(st, kfp, vfp, (t + 2) * 64, tid);
      CP_COMMIT();
    }
  }

  // Epilogue: normalize, emit fp16 hi/lo y for the proj GEMM.
  const float i0 = 1.f / lrow[0];
  const float i1 = 1.f / lrow[1];
  const int r0 = q0 + w * 16 + gid;
  const size_t base0 = ((size_t)b * TT + r0) * CC + h * HD;
  const size_t base1 = base0 + (size_t)8 * CC;
#pragma unroll
  for (int n = 0; n < 8; n++) {
    const int col = n * 8 + tig * 2;
    uint32_t hw, lw;
    split2h(o[n][0] * i0, o[n][1] * i0, hw, lw);
    *(uint32_t*)(yh + base0 + col) = hw;
    *(uint32_t*)(yl + base0 + col) = lw;
    split2h(o[n][2] * i1, o[n][3] * i1, hw, lw);
    *(uint32_t*)(yh + base1 + col) = hw;
    *(uint32_t*)(yl + base1 + col) = lw;
  }
}

// ---------------------------------------------------------------------------
// kernel_launch
// ---------------------------------------------------------------------------
extern "C" void kernel_launch(void* const* d_in, const int* in_sizes, int n_in,
                              void* d_out, int out_size) {
  const float* x = (const float*)d_in[0];
  const float* Wq = (const float*)d_in[2];
  const float* bq = (const float*)d_in[3];
  const float* Wk = (const float*)d_in[4];
  const float* bk = (const float*)d_in[5];
  const float* Wv = (const float*)d_in[6];
  const float* bv = (const float*)d_in[7];
  const float* Wp = (const float*)d_in[8];
  const float* bp = (const float*)d_in[9];

  float* out = (float*)d_out;
  float* kout = out + (size_t)BB * TT * CC;        // present[0] = k
  float* vout = kout + (size_t)BB * HH * TT * HD;  // present[1] = v

  __half *xf, *wt, *yh, *yl, *qhb, *qlb, *kfb, *vfb;
  cudaGetSymbolAddress((void**)&xf, g_xf);
  cudaGetSymbolAddress((void**)&wt, g_wt);
  cudaGetSymbolAddress((void**)&yh, g_yh);
  cudaGetSymbolAddress((void**)&yl, g_yl);
  cudaGetSymbolAddress((void**)&qhb, g_qh);
  cudaGetSymbolAddress((void**)&qlb, g_ql);
  cudaGetSymbolAddress((void**)&kfb, g_kf);
  cudaGetSymbolAddress((void**)&vfb, g_vf);

  // #1: fused conversions (x fp16 + 4 W transposes to fp16)
  conv_all<<<dim3(32, 32, 5), dim3(32, 8)>>>(x, Wq, Wk, Wv, Wp, xf, wt);

  // #2: fused QKV projection (1-term fp16 A, tensor core, 2 CTAs/SM)
  cudaFuncSetAttribute(gemm_tc<1, 1>,
                       cudaFuncAttributeMaxDynamicSharedMemorySize,
                       GEMM_SMEM_T(1));
  cudaFuncSetAttribute(gemm_tc<0, 2>,
                       cudaFuncAttributeMaxDynamicSharedMemorySize,
                       GEMM_SMEM_T(2));
  dim3 qkvgrid(3 * NN / 128, MM / 128);  // (24, 64)
  gemm_tc<1, 1><<<qkvgrid, 256, GEMM_SMEM_T(1)>>>(
      xf, nullptr, wt, bq, bk, bv, nullptr, kout, vout, qhb, qlb, kfb, vfb);

  // #3: tensor-core attention (2-term fp16)
  cudaFuncSetAttribute(attn_mma, cudaFuncAttributeMaxDynamicSharedMemorySize,
                       ATT_SMEM);
  dim3 agrid(TT / 128, HH, BB);
  attn_mma<<<agrid, 256, ATT_SMEM>>>(qhb, qlb, kfb, vfb, yh, yl);

  // #4: output projection (2-term y; lands under ncu -s 5)
  const size_t WSZ = (size_t)KK * NN;
  dim3 pgrid(NN / 128, MM / 128);
  gemm_tc<0, 2><<<pgrid, 256, GEMM_SMEM_T(2)>>>(
      yh, yl, wt + 3 * WSZ, bp, nullptr, nullptr, out, nullptr, nullptr,
      nullptr, nullptr, nullptr, nullptr);
}

// round 16
// speedup vs baseline: 2.2039x; 1.2769x over previous
#include <cuda_runtime.h>
#include <cuda_bf16.h>
#include <cuda_fp16.h>
#include <cstdint>
#include <math.h>

// Problem constants
#define BB 4
#define TT 2048
#define CC 1024
#define HH 16
#define HD 64
#define MM (BB * TT)   // 8192
#define KK CC          // 1024
#define NN CC          // 1024

// ---------------------------------------------------------------------------
// Scratch (__device__ globals; no allocation allowed)
// ---------------------------------------------------------------------------
__device__ __half g_xf[(size_t)MM * KK];          // x fp16
__device__ __half g_wt[(size_t)4 * KK * NN];      // W^T fp16 [N,K]; Q,K,V,P
__device__ __half g_yf[(size_t)MM * NN];          // y fp16
// head-layout fp16 attention operands (q pre-scaled by 1/8)
__device__ __half g_qf[(size_t)BB * HH * TT * HD];
__device__ __half g_kf[(size_t)BB * HH * TT * HD];
__device__ __half g_vf[(size_t)BB * HH * TT * HD];

// ---------------------------------------------------------------------------
// PTX helpers (base compute_100-safe: cp.async / ldmatrix / mma.sync only)
// ---------------------------------------------------------------------------
__device__ __forceinline__ uint32_t smem_u32(const void* p) {
  uint32_t a;
  asm("{ .reg .u64 t; cvta.to.shared.u64 t, %1; cvt.u32.u64 %0, t; }"
      : "=r"(a) : "l"(p));
  return a;
}
__device__ __forceinline__ void cpasync16(uint32_t dst, const void* src) {
  asm volatile("cp.async.cg.shared.global [%0], [%1], 16;" ::"r"(dst),
               "l"(src));
}
#define CP_COMMIT() asm volatile("cp.async.commit_group;" ::: "memory")

__device__ __forceinline__ void ldsm4(uint32_t* r, uint32_t addr) {
  asm volatile(
      "ldmatrix.sync.aligned.m8n8.x4.shared.b16 {%0,%1,%2,%3}, [%4];"
      : "=r"(r[0]), "=r"(r[1]), "=r"(r[2]), "=r"(r[3])
      : "r"(addr));
}
__device__ __forceinline__ void ldsm2(uint32_t* r, uint32_t addr) {
  asm volatile("ldmatrix.sync.aligned.m8n8.x2.shared.b16 {%0,%1}, [%2];"
               : "=r"(r[0]), "=r"(r[1])
               : "r"(addr));
}
__device__ __forceinline__ void ldsm4t(uint32_t* r, uint32_t addr) {
  asm volatile(
      "ldmatrix.sync.aligned.m8n8.x4.trans.shared.b16 {%0,%1,%2,%3}, [%4];"
      : "=r"(r[0]), "=r"(r[1]), "=r"(r[2]), "=r"(r[3])
      : "r"(addr));
}

// D += A @ B (m16n8k16, fp16 in, fp32 acc)
__device__ __forceinline__ void mma16816h(float* c, const uint32_t* a,
                                          const uint32_t* b) {
  asm volatile(
      "mma.sync.aligned.m16n8k16.row.col.f32.f16.f16.f32 "
      "{%0,%1,%2,%3}, {%4,%5,%6,%7}, {%8,%9}, {%0,%1,%2,%3};"
      : "+f"(c[0]), "+f"(c[1]), "+f"(c[2]), "+f"(c[3])
      : "r"(a[0]), "r"(a[1]), "r"(a[2]), "r"(a[3]), "r"(b[0]), "r"(b[1]));
}

// pack two fp16
__device__ __forceinline__ uint32_t pack2h(float a, float b) {
  return (uint32_t)__half_as_ushort(__float2half_rn(a)) |
         ((uint32_t)__half_as_ushort(__float2half_rn(b)) << 16);
}

// ---------------------------------------------------------------------------
// Fused conversion kernel: z=0 -> x fp16 (vectorized);
// z=1..4 -> W transpose to fp16 [N,K] for Wq,Wk,Wv,Wp.
// ---------------------------------------------------------------------------
__global__ void conv_all(const float* __restrict__ x,
                         const float* __restrict__ Wq,
                         const float* __restrict__ Wk,
                         const float* __restrict__ Wv,
                         const float* __restrict__ Wp,
                         __half* __restrict__ xf, __half* __restrict__ wt) {
  __shared__ float tile[32][33];
  const int z = blockIdx.z;
  const int tx = threadIdx.x, ty = threadIdx.y;
  if (z == 0) {
    const int bid = blockIdx.y * 32 + blockIdx.x;
    const int t = ty * 32 + tx;
    const float4* src = (const float4*)x + (size_t)bid * 2048;
    uint2* df = (uint2*)xf + (size_t)bid * 2048;
#pragma unroll
    for (int it = 0; it < 8; it++) {
      const int i4 = it * 256 + t;
      float4 v = src[i4];
      df[i4] = make_uint2(pack2h(v.x, v.y), pack2h(v.z, v.w));
    }
  } else {
    const float* W = (z == 1) ? Wq : (z == 2) ? Wk : (z == 3) ? Wv : Wp;
    const size_t WSZ = (size_t)KK * NN;
    __half* th = wt + (size_t)(z - 1) * WSZ;
    const int x0 = blockIdx.x * 32;  // n
    const int y0 = blockIdx.y * 32;  // k
#pragma unroll
    for (int r = 0; r < 32; r += 8)
      tile[ty + r][tx] = W[(size_t)(y0 + ty + r) * NN + x0 + tx];
    __syncthreads();
#pragma unroll
    for (int r = 0; r < 32; r += 8) {
      float v = tile[tx][ty + r];
      th[(size_t)(x0 + ty + r) * KK + y0 + tx] = __float2half_rn(v);
    }
  }
}

// ---------------------------------------------------------------------------
// mma.sync single-term fp16 GEMM: out = A[M,K] @ W[N,K]^T + bias.
// 128x128 tile, BKC=32, NST=2 double-buffered, 2 tiles/stage -> 40KB.
// FUSED=1: QKV fused (epilogue routes by n0>>10); FUSED=0: proj (fp32 out).
// ---------------------------------------------------------------------------
#define BKC 32
#define ROWB 80
#define TILEB (128 * ROWB)           // 10240
#define STAGEB (2 * TILEB)           // 20480 (A, W)
#define NST 2
#define NCH (KK / BKC)               // 32
#define GEMM_SMEM (NST * STAGEB)     // 40960

__device__ __forceinline__ void load_tile32(uint32_t sbase, const __half* g,
                                            int tid) {
#pragma unroll
  for (int it = 0; it < 2; it++) {
    const int lin = it * 256 + tid;
    const int row = lin >> 2, cc = lin & 3;
    cpasync16(sbase + row * ROWB + cc * 16, g + (size_t)row * KK + cc * 8);
  }
}

template <int FUSED>
__global__ __launch_bounds__(256, 2) void gemm_tc(
    const __half* __restrict__ Af, const __half* __restrict__ Bw,
    const float* __restrict__ b0p, const float* __restrict__ b1p,
    const float* __restrict__ b2p, float* __restrict__ out,
    float* __restrict__ kout, float* __restrict__ vout,
    __half* __restrict__ qf, __half* __restrict__ kf,
    __half* __restrict__ vf) {
  extern __shared__ __align__(128) uint8_t smem_raw[];
  const uint32_t sb = smem_u32(smem_raw);
  const int tid = threadIdx.x;
  const int wid = tid >> 5, lane = tid & 31;
  const int gid = lane >> 2, tig = lane & 3;
  const int n0 = blockIdx.x * 128;
  const int m0 = blockIdx.y * 128;
  const int wm0 = (wid & 1) * 64;
  const int wn0 = (wid >> 1) * 32;

  const __half* Afb = Af + (size_t)m0 * KK;
  const __half* Wb = Bw + (size_t)n0 * KK;

  float acc[4][4][4];
#pragma unroll
  for (int i = 0; i < 4; i++)
#pragma unroll
    for (int j = 0; j < 4; j++)
#pragma unroll
      for (int r = 0; r < 4; r++) acc[i][j][r] = 0.f;

  const int amat = lane >> 3;
  const int arow_in = ((amat & 1) << 3) + (lane & 7);
  const int acol = (amat >> 1) << 4;
  const int brow_in = lane & 7;
  const int bcol = ((lane >> 3) & 1) << 4;

#pragma unroll
  for (int c = 0; c < 2; c++) {
    const uint32_t st = sb + c * STAGEB;
    load_tile32(st + 0 * TILEB, Afb + c * BKC, tid);
    load_tile32(st + 1 * TILEB, Wb + c * BKC, tid);
    CP_COMMIT();
  }

  for (int c = 0; c < NCH; c++) {
    if (c + 1 < NCH)
      asm volatile("cp.async.wait_group 1;" ::: "memory");
    else
      asm volatile("cp.async.wait_group 0;" ::: "memory");
    __syncthreads();

    const uint32_t st = sb + (c & 1) * STAGEB;
    const uint32_t tAf = st + 0 * TILEB;
    const uint32_t tBw = st + 1 * TILEB;

#pragma unroll
    for (int ks = 0; ks < 2; ks++) {
      const int kb = ks * 32;
      uint32_t af[4][4], bw[4][2];
#pragma unroll
      for (int i = 0; i < 4; i++) {
        const uint32_t ao = (wm0 + i * 16 + arow_in) * ROWB + kb + acol;
        ldsm4(af[i], tAf + ao);
      }
#pragma unroll
      for (int j = 0; j < 4; j++) {
        const uint32_t bo = (wn0 + j * 8 + brow_in) * ROWB + kb + bcol;
        ldsm2(bw[j], tBw + bo);
      }
#pragma unroll
      for (int i = 0; i < 4; i++)
#pragma unroll
        for (int j = 0; j < 4; j++) mma16816h(acc[i][j], af[i], bw[j]);
    }
    __syncthreads();

    if (c + 2 < NCH) {
      const uint32_t stl = sb + (c & 1) * STAGEB;
      const int k0 = (c + 2) * BKC;
      load_tile32(stl + 0 * TILEB, Afb + k0, tid);
      load_tile32(stl + 1 * TILEB, Wb + k0, tid);
      CP_COMMIT();
    }
  }

  // Epilogue
  int mat = 0;
  const float* bias = b0p;
  if (FUSED) {
    mat = n0 >> 10;  // uniform per block
    bias = (mat == 0) ? b0p : (mat == 1) ? b1p : b2p;
  }
#pragma unroll
  for (int i = 0; i < 4; i++) {
#pragma unroll
    for (int j = 0; j < 4; j++) {
      const int col = n0 + wn0 + j * 8 + tig * 2;
      const int cloc = col & (NN - 1);
      const float bb0 = __ldg(bias + cloc);
      const float bb1 = __ldg(bias + cloc + 1);
#pragma unroll
      for (int hh = 0; hh < 2; hh++) {
        const int m = m0 + wm0 + i * 16 + gid + hh * 8;
        float v0 = acc[i][j][hh * 2 + 0] + bb0;
        float v1 = acc[i][j][hh * 2 + 1] + bb1;
        if (!FUSED) {
          *(float2*)(out + (size_t)m * NN + col) = make_float2(v0, v1);
        } else {
          const int b = m >> 11, t = m & (TT - 1);
          const int h = cloc >> 6, hd = cloc & (HD - 1);
          const size_t ho = (((size_t)b * HH + h) * TT + t) * HD + hd;
          if (mat == 0) {  // Q: pre-scale by 1/8 (exact), single fp16
            *(uint32_t*)(qf + ho) = pack2h(v0 * 0.125f, v1 * 0.125f);
          } else if (mat == 1) {  // K: fp32 out + single fp16 for attn
            *(float2*)(kout + ho) = make_float2(v0, v1);
            *(uint32_t*)(kf + ho) = pack2h(v0, v1);
          } else {  // V
            *(float2*)(vout + ho) = make_float2(v0, v1);
            *(uint32_t*)(vf + ho) = pack2h(v0, v1);
          }
        }
      }
    }
  }
}

// ---------------------------------------------------------------------------
// Tensor-core causal flash attention, single-term fp16:
// S = q·k ; O += p·v   (all fp16 operands, fp32 accumulation)
// 32 S-MMAs + 32 PV-MMAs per 64-wide KV tile.
// ---------------------------------------------------------------------------
#define AROW 144
#define QSZ (128 * AROW)              // 18432
#define KSZ (64 * AROW)               // 9216
#define STG2 (2 * KSZ)                // 18432 (k, v)
#define ATT_SMEM (QSZ + 2 * STG2)     // 55296

__device__ __forceinline__ void loadkv(uint32_t st, const __half* kfp,
                                       const __half* vfp, int kv0, int tid) {
#pragma unroll
  for (int it = 0; it < 4; it++) {
    const int arr = it >> 1;                 // 0: k, 1: v
    const int rem = ((it & 1) << 8) + tid;   // 0..511
    const int row = rem >> 3, c = rem & 7;
    const __half* base = arr ? vfp : kfp;
    cpasync16(st + arr * KSZ + row * AROW + c * 16,
              base + (size_t)(kv0 + row) * HD + c * 8);
  }
}

__global__ __launch_bounds__(256, 2) void attn_mma(
    const __half* __restrict__ qf, const __half* __restrict__ kf,
    const __half* __restrict__ vf, __half* __restrict__ yf) {
  extern __shared__ __align__(128) uint8_t smem_raw[];
  const uint32_t sb = smem_u32(smem_raw);
  const int tid = threadIdx.x;
  const int w = tid >> 5, lane = tid & 31;
  const int gid = lane >> 2, tig = lane & 3;
  const int qblk = blockIdx.x, h = blockIdx.y, b = blockIdx.z;
  const int q0 = qblk * 128;
  const size_t hoff = (((size_t)b * HH + h) * TT) * HD;
  const __half* qfp = qf + hoff;
  const __half* kfp = kf + hoff;
  const __half* vfp = vf + hoff;

  // Q load: 128 rows x 128B = 1024 x 16B chunks
#pragma unroll
  for (int it = 0; it < 4; it++) {
    const int rem = it * 256 + tid;
    const int row = rem >> 3, c = rem & 7;
    cpasync16(sb + row * AROW + c * 16,
              qfp + (size_t)(q0 + row) * HD + c * 8);
  }
  loadkv(sb + QSZ, kfp, vfp, 0, tid);
  CP_COMMIT();
  loadkv(sb + QSZ + STG2, kfp, vfp, 64, tid);
  CP_COMMIT();

  float s[8][4], o[8][4];
  float mrow[2] = {-INFINITY, -INFINITY};
  float lrow[2] = {0.f, 0.f};
#pragma unroll
  for (int j = 0; j < 8; j++)
#pragma unroll
    for (int r = 0; r < 4; r++) o[j][r] = 0.f;

  const int amat = lane >> 3;
  const int arow_in = ((amat & 1) << 3) + (lane & 7);
  const int acol = (amat >> 1) << 4;
  const int brow_in = lane & 7;
  const int bcol = ((lane >> 3) & 1) << 4;
  const int ntiles = 2 * qblk + 2;

  for (int t = 0; t < ntiles; t++) {
    if (t + 1 < ntiles)
      asm volatile("cp.async.wait_group 1;" ::: "memory");
    else
      asm volatile("cp.async.wait_group 0;" ::: "memory");
    __syncthreads();

    const uint32_t st = sb + QSZ + (t & 1) * STG2;
    const uint32_t tK = st, tV = st + KSZ;

#pragma unroll
    for (int j = 0; j < 8; j++)
#pragma unroll
      for (int r = 0; r < 4; r++) s[j][r] = 0.f;

    // ---- S = q K^T ----
#pragma unroll
    for (int kk = 0; kk < 4; kk++) {
      uint32_t aq[4];
      const uint32_t qo = (w * 16 + arow_in) * AROW + kk * 32 + acol;
      ldsm4(aq, sb + qo);
#pragma unroll
      for (int g = 0; g < 2; g++) {
        uint32_t kbf[4][2];
#pragma unroll
        for (int jj = 0; jj < 4; jj++) {
          const uint32_t ko =
              ((g * 4 + jj) * 8 + brow_in) * AROW + kk * 32 + bcol;
          ldsm2(kbf[jj], tK + ko);
        }
#pragma unroll
        for (int jj = 0; jj < 4; jj++) mma16816h(s[g * 4 + jj], aq, kbf[jj]);
      }
    }

    const int kv0 = t * 64;
    if (kv0 + 63 > q0) {
#pragma unroll
      for (int j = 0; j < 8; j++) {
        const int jg = kv0 + j * 8 + tig * 2;
#pragma unroll
        for (int r = 0; r < 2; r++) {
          const int rg = q0 + w * 16 + gid + r * 8;
          if (jg > rg) s[j][r * 2] = -INFINITY;
          if (jg + 1 > rg) s[j][r * 2 + 1] = -INFINITY;
        }
      }
    }

#pragma unroll
    for (int r = 0; r < 2; r++) {
      float mx = mrow[r];
#pragma unroll
      for (int j = 0; j < 8; j++)
        mx = fmaxf(mx, fmaxf(s[j][r * 2], s[j][r * 2 + 1]));
      mx = fmaxf(mx, __shfl_xor_sync(0xffffffffu, mx, 1));
      mx = fmaxf(mx, __shfl_xor_sync(0xffffffffu, mx, 2));
      const float alpha = __expf(mrow[r] - mx);
      mrow[r] = mx;
      float ls = 0.f;
#pragma unroll
      for (int j = 0; j < 8; j++) {
        const float p0 = __expf(s[j][r * 2] - mx);
        const float p1 = __expf(s[j][r * 2 + 1] - mx);
        s[j][r * 2] = p0;
        s[j][r * 2 + 1] = p1;
        ls += p0 + p1;
      }
      ls += __shfl_xor_sync(0xffffffffu, ls, 1);
      ls += __shfl_xor_sync(0xffffffffu, ls, 2);
      lrow[r] = lrow[r] * alpha + ls;
#pragma unroll
      for (int j = 0; j < 8; j++) {
        o[j][r * 2] *= alpha;
        o[j][r * 2 + 1] *= alpha;
      }
    }

    // ---- O += p V (single-term p) ----
#pragma unroll
    for (int kk = 0; kk < 4; kk++) {
      uint32_t ph4[4];
#pragma unroll
      for (int half = 0; half < 2; half++) {
        const int j = 2 * kk + half;
        ph4[half * 2 + 0] = pack2h(s[j][0], s[j][1]);
        ph4[half * 2 + 1] = pack2h(s[j][2], s[j][3]);
      }
      const uint32_t vrow = kk * 16 + (lane & 15);
      const uint32_t vco = (lane >> 4) << 4;
#pragma unroll
      for (int npg = 0; npg < 2; npg++) {
        uint32_t vfr[2][4];
#pragma unroll
        for (int p = 0; p < 2; p++) {
          const uint32_t vo = vrow * AROW + (npg * 2 + p) * 32 + vco;
          ldsm4t(vfr[p], tV + vo);
        }
#pragma unroll
        for (int p = 0; p < 2; p++) {
          const int np = npg * 2 + p;
          mma16816h(o[2 * np], ph4, vfr[p]);
          mma16816h(o[2 * np + 1], ph4, vfr[p] + 2);
        }
      }
    }
    __syncthreads();

    if (t + 2 < ntiles) {
      loadkv(st, kfp, vfp, (t + 2) * 64, tid);
      CP_COMMIT();
    }
  }

  // Epilogue: normalize, emit single fp16 y for the proj GEMM.
  const float i0 = 1.f / lrow[0];
  const float i1 = 1.f / lrow[1];
  const int r0 = q0 + w * 16 + gid;
  const size_t base0 = ((size_t)b * TT + r0) * CC + h * HD;
  const size_t base1 = base0 + (size_t)8 * CC;
#pragma unroll
  for (int n = 0; n < 8; n++) {
    const int col = n * 8 + tig * 2;
    *(uint32_t*)(yf + base0 + col) = pack2h(o[n][0] * i0, o[n][1] * i0);
    *(uint32_t*)(yf + base1 + col) = pack2h(o[n][2] * i1, o[n][3] * i1);
  }
}

// ---------------------------------------------------------------------------
// kernel_launch
// ---------------------------------------------------------------------------
extern "C" void kernel_launch(void* const* d_in, const int* in_sizes, int n_in,
                              void* d_out, int out_size) {
  const float* x = (const float*)d_in[0];
  const float* Wq = (const float*)d_in[2];
  const float* bq = (const float*)d_in[3];
  const float* Wk = (const float*)d_in[4];
  const float* bk = (const float*)d_in[5];
  const float* Wv = (const float*)d_in[6];
  const float* bv = (const float*)d_in[7];
  const float* Wp = (const float*)d_in[8];
  const float* bp = (const float*)d_in[9];

  float* out = (float*)d_out;
  float* kout = out + (size_t)BB * TT * CC;        // present[0] = k
  float* vout = kout + (size_t)BB * HH * TT * HD;  // present[1] = v

  __half *xf, *wt, *yf, *qfb, *kfb, *vfb;
  cudaGetSymbolAddress((void**)&xf, g_xf);
  cudaGetSymbolAddress((void**)&wt, g_wt);
  cudaGetSymbolAddress((void**)&yf, g_yf);
  cudaGetSymbolAddress((void**)&qfb, g_qf);
  cudaGetSymbolAddress((void**)&kfb, g_kf);
  cudaGetSymbolAddress((void**)&vfb, g_vf);

  // #1: fused conversions (x fp16 + 4 W transposes to fp16)
  conv_all<<<dim3(32, 32, 5), dim3(32, 8)>>>(x, Wq, Wk, Wv, Wp, xf, wt);

  // #2: fused QKV projection (single-term fp16, tensor core, 2 CTAs/SM)
  cudaFuncSetAttribute(gemm_tc<1>, cudaFuncAttributeMaxDynamicSharedMemorySize,
                       GEMM_SMEM);
  cudaFuncSetAttribute(gemm_tc<0>, cudaFuncAttributeMaxDynamicSharedMemorySize,
                       GEMM_SMEM);
  dim3 qkvgrid(3 * NN / 128, MM / 128);  // (24, 64)
  gemm_tc<1><<<qkvgrid, 256, GEMM_SMEM>>>(xf, wt, bq, bk, bv, nullptr, kout,
                                          vout, qfb, kfb, vfb);

  // #3: tensor-core attention (single-term fp16)
  cudaFuncSetAttribute(attn_mma, cudaFuncAttributeMaxDynamicSharedMemorySize,
                       ATT_SMEM);
  dim3 agrid(TT / 128, HH, BB);
  attn_mma<<<agrid, 256, ATT_SMEM>>>(qfb, kfb, vfb, yf);

  // #4: output projection (single-term y; lands under ncu -s 5)
  const size_t WSZ = (size_t)KK * NN;
  dim3 pgrid(NN / 128, MM / 128);
  gemm_tc<0><<<pgrid, 256, GEMM_SMEM>>>(yf, wt + 3 * WSZ, bp, nullptr, nullptr,
                                        out, nullptr, nullptr, nullptr,
                                        nullptr, nullptr);
}

// round 17
// speedup vs baseline: 2.4683x; 1.1200x over previous
#include <cuda_runtime.h>
#include <cuda_bf16.h>
#include <cuda_fp16.h>
#include <cstdint>
#include <math.h>

// Problem constants
#define BB 4
#define TT 2048
#define CC 1024
#define HH 16
#define HD 64
#define MM (BB * TT)   // 8192
#define KK CC          // 1024
#define NN CC          // 1024

// ---------------------------------------------------------------------------
// Scratch (__device__ globals; no allocation allowed)
// ---------------------------------------------------------------------------
__device__ __half g_xf[(size_t)MM * KK];          // x fp16
__device__ __half g_wt[(size_t)4 * KK * NN];      // W^T fp16 [N,K]; Q,K,V,P
__device__ __half g_yf[(size_t)MM * NN];          // y fp16
// head-layout fp16 attention operands (q pre-scaled by 1/8)
__device__ __half g_qf[(size_t)BB * HH * TT * HD];
__device__ __half g_kf[(size_t)BB * HH * TT * HD];
__device__ __half g_vf[(size_t)BB * HH * TT * HD];

// ---------------------------------------------------------------------------
// PTX helpers (base compute_100-safe: cp.async / ldmatrix / mma.sync only)
// ---------------------------------------------------------------------------
__device__ __forceinline__ uint32_t smem_u32(const void* p) {
  uint32_t a;
  asm("{ .reg .u64 t; cvta.to.shared.u64 t, %1; cvt.u32.u64 %0, t; }"
      : "=r"(a) : "l"(p));
  return a;
}
__device__ __forceinline__ void cpasync16(uint32_t dst, const void* src) {
  asm volatile("cp.async.cg.shared.global [%0], [%1], 16;" ::"r"(dst),
               "l"(src));
}
#define CP_COMMIT() asm volatile("cp.async.commit_group;" ::: "memory")

__device__ __forceinline__ void ldsm4(uint32_t* r, uint32_t addr) {
  asm volatile(
      "ldmatrix.sync.aligned.m8n8.x4.shared.b16 {%0,%1,%2,%3}, [%4];"
      : "=r"(r[0]), "=r"(r[1]), "=r"(r[2]), "=r"(r[3])
      : "r"(addr));
}
__device__ __forceinline__ void ldsm2(uint32_t* r, uint32_t addr) {
  asm volatile("ldmatrix.sync.aligned.m8n8.x2.shared.b16 {%0,%1}, [%2];"
               : "=r"(r[0]), "=r"(r[1])
               : "r"(addr));
}
__device__ __forceinline__ void ldsm4t(uint32_t* r, uint32_t addr) {
  asm volatile(
      "ldmatrix.sync.aligned.m8n8.x4.trans.shared.b16 {%0,%1,%2,%3}, [%4];"
      : "=r"(r[0]), "=r"(r[1]), "=r"(r[2]), "=r"(r[3])
      : "r"(addr));
}

// D += A @ B (m16n8k16, fp16 in, fp32 acc)
__device__ __forceinline__ void mma16816h(float* c, const uint32_t* a,
                                          const uint32_t* b) {
  asm volatile(
      "mma.sync.aligned.m16n8k16.row.col.f32.f16.f16.f32 "
      "{%0,%1,%2,%3}, {%4,%5,%6,%7}, {%8,%9}, {%0,%1,%2,%3};"
      : "+f"(c[0]), "+f"(c[1]), "+f"(c[2]), "+f"(c[3])
      : "r"(a[0]), "r"(a[1]), "r"(a[2]), "r"(a[3]), "r"(b[0]), "r"(b[1]));
}

// pack two fp16
__device__ __forceinline__ uint32_t pack2h(float a, float b) {
  return (uint32_t)__half_as_ushort(__float2half_rn(a)) |
         ((uint32_t)__half_as_ushort(__float2half_rn(b)) << 16);
}

// ---------------------------------------------------------------------------
// Fused conversion kernel: z=0 -> x fp16 (vectorized);
// z=1..4 -> W transpose to fp16 [N,K] for Wq,Wk,Wv,Wp.
// ---------------------------------------------------------------------------
__global__ void conv_all(const float* __restrict__ x,
                         const float* __restrict__ Wq,
                         const float* __restrict__ Wk,
                         const float* __restrict__ Wv,
                         const float* __restrict__ Wp,
                         __half* __restrict__ xf, __half* __restrict__ wt) {
  __shared__ float tile[32][33];
  const int z = blockIdx.z;
  const int tx = threadIdx.x, ty = threadIdx.y;
  if (z == 0) {
    const int bid = blockIdx.y * 32 + blockIdx.x;
    const int t = ty * 32 + tx;
    const float4* src = (const float4*)x + (size_t)bid * 2048;
    uint2* df = (uint2*)xf + (size_t)bid * 2048;
#pragma unroll
    for (int it = 0; it < 8; it++) {
      const int i4 = it * 256 + t;
      float4 v = src[i4];
      df[i4] = make_uint2(pack2h(v.x, v.y), pack2h(v.z, v.w));
    }
  } else {
    const float* W = (z == 1) ? Wq : (z == 2) ? Wk : (z == 3) ? Wv : Wp;
    const size_t WSZ = (size_t)KK * NN;
    __half* th = wt + (size_t)(z - 1) * WSZ;
    const int x0 = blockIdx.x * 32;  // n
    const int y0 = blockIdx.y * 32;  // k
#pragma unroll
    for (int r = 0; r < 32; r += 8)
      tile[ty + r][tx] = W[(size_t)(y0 + ty + r) * NN + x0 + tx];
    __syncthreads();
#pragma unroll
    for (int r = 0; r < 32; r += 8) {
      float v = tile[tx][ty + r];
      th[(size_t)(x0 + ty + r) * KK + y0 + tx] = __float2half_rn(v);
    }
  }
}

// ---------------------------------------------------------------------------
// mma.sync single-term fp16 GEMM: out = A[M,K] @ W[N,K]^T + bias.
// 128x128 tile, BKC=64 (halved chunk count -> halved sync/wait overhead),
// NST=2 double-buffered, 2 tiles/stage (A, W) -> 72KB -> 2 CTAs/SM.
// ROWB=144: row start bank = 4r mod 32, distinct for r=0..7 -> ldsm clean.
// FUSED=1: QKV fused (epilogue routes by n0>>10); FUSED=0: proj (fp32 out).
// ---------------------------------------------------------------------------
#define BKC 64
#define ROWB 144
#define TILEB (128 * ROWB)           // 18432
#define STAGEB (2 * TILEB)           // 36864 (A, W)
#define NST 2
#define NCH (KK / BKC)               // 16
#define GEMM_SMEM (NST * STAGEB)     // 73728

__device__ __forceinline__ void load_tile64(uint32_t sbase, const __half* g,
                                            int tid) {
  // 128 rows x 128B data (8 x 16B); 256 threads -> 4 cps each
#pragma unroll
  for (int it = 0; it < 4; it++) {
    const int lin = it * 256 + tid;
    const int row = lin >> 3, cc = lin & 7;
    cpasync16(sbase + row * ROWB + cc * 16, g + (size_t)row * KK + cc * 8);
  }
}

template <int FUSED>
__global__ __launch_bounds__(256, 2) void gemm_tc(
    const __half* __restrict__ Af, const __half* __restrict__ Bw,
    const float* __restrict__ b0p, const float* __restrict__ b1p,
    const float* __restrict__ b2p, float* __restrict__ out,
    float* __restrict__ kout, float* __restrict__ vout,
    __half* __restrict__ qf, __half* __restrict__ kf,
    __half* __restrict__ vf) {
  extern __shared__ __align__(128) uint8_t smem_raw[];
  const uint32_t sb = smem_u32(smem_raw);
  const int tid = threadIdx.x;
  const int wid = tid >> 5, lane = tid & 31;
  const int gid = lane >> 2, tig = lane & 3;
  const int n0 = blockIdx.x * 128;
  const int m0 = blockIdx.y * 128;
  const int wm0 = (wid & 1) * 64;
  const int wn0 = (wid >> 1) * 32;

  const __half* Afb = Af + (size_t)m0 * KK;
  const __half* Wb = Bw + (size_t)n0 * KK;

  float acc[4][4][4];
#pragma unroll
  for (int i = 0; i < 4; i++)
#pragma unroll
    for (int j = 0; j < 4; j++)
#pragma unroll
      for (int r = 0; r < 4; r++) acc[i][j][r] = 0.f;

  const int amat = lane >> 3;
  const int arow_in = ((amat & 1) << 3) + (lane & 7);
  const int acol = (amat >> 1) << 4;
  const int brow_in = lane & 7;
  const int bcol = ((lane >> 3) & 1) << 4;

#pragma unroll
  for (int c = 0; c < 2; c++) {
    const uint32_t st = sb + c * STAGEB;
    load_tile64(st + 0 * TILEB, Afb + c * BKC, tid);
    load_tile64(st + 1 * TILEB, Wb + c * BKC, tid);
    CP_COMMIT();
  }

  for (int c = 0; c < NCH; c++) {
    if (c + 1 < NCH)
      asm volatile("cp.async.wait_group 1;" ::: "memory");
    else
      asm volatile("cp.async.wait_group 0;" ::: "memory");
    __syncthreads();

    const uint32_t st = sb + (c & 1) * STAGEB;
    const uint32_t tAf = st + 0 * TILEB;
    const uint32_t tBw = st + 1 * TILEB;

#pragma unroll
    for (int ks = 0; ks < 4; ks++) {
      const int kb = ks * 32;
      uint32_t af[4][4], bw[4][2];
#pragma unroll
      for (int i = 0; i < 4; i++) {
        const uint32_t ao = (wm0 + i * 16 + arow_in) * ROWB + kb + acol;
        ldsm4(af[i], tAf + ao);
      }
#pragma unroll
      for (int j = 0; j < 4; j++) {
        const uint32_t bo = (wn0 + j * 8 + brow_in) * ROWB + kb + bcol;
        ldsm2(bw[j], tBw + bo);
      }
#pragma unroll
      for (int i = 0; i < 4; i++)
#pragma unroll
        for (int j = 0; j < 4; j++) mma16816h(acc[i][j], af[i], bw[j]);
    }
    __syncthreads();

    if (c + 2 < NCH) {
      const uint32_t stl = sb + (c & 1) * STAGEB;
      const int k0 = (c + 2) * BKC;
      load_tile64(stl + 0 * TILEB, Afb + k0, tid);
      load_tile64(stl + 1 * TILEB, Wb + k0, tid);
      CP_COMMIT();
    }
  }

  // Epilogue
  int mat = 0;
  const float* bias = b0p;
  if (FUSED) {
    mat = n0 >> 10;  // uniform per block
    bias = (mat == 0) ? b0p : (mat == 1) ? b1p : b2p;
  }
#pragma unroll
  for (int i = 0; i < 4; i++) {
#pragma unroll
    for (int j = 0; j < 4; j++) {
      const int col = n0 + wn0 + j * 8 + tig * 2;
      const int cloc = col & (NN - 1);
      const float bb0 = __ldg(bias + cloc);
      const float bb1 = __ldg(bias + cloc + 1);
#pragma unroll
      for (int hh = 0; hh < 2; hh++) {
        const int m = m0 + wm0 + i * 16 + gid + hh * 8;
        float v0 = acc[i][j][hh * 2 + 0] + bb0;
        float v1 = acc[i][j][hh * 2 + 1] + bb1;
        if (!FUSED) {
          *(float2*)(out + (size_t)m * NN + col) = make_float2(v0, v1);
        } else {
          const int b = m >> 11, t = m & (TT - 1);
          const int h = cloc >> 6, hd = cloc & (HD - 1);
          const size_t ho = (((size_t)b * HH + h) * TT + t) * HD + hd;
          if (mat == 0) {  // Q: pre-scale by 1/8 (exact), single fp16
            *(uint32_t*)(qf + ho) = pack2h(v0 * 0.125f, v1 * 0.125f);
          } else if (mat == 1) {  // K: fp32 out + single fp16 for attn
            *(float2*)(kout + ho) = make_float2(v0, v1);
            *(uint32_t*)(kf + ho) = pack2h(v0, v1);
          } else {  // V
            *(float2*)(vout + ho) = make_float2(v0, v1);
            *(uint32_t*)(vf + ho) = pack2h(v0, v1);
          }
        }
      }
    }
  }
}

// ---------------------------------------------------------------------------
// Tensor-core causal flash attention, single-term fp16 (unchanged from R15):
// S = q·k ; O += p·v
// ---------------------------------------------------------------------------
#define AROW 144
#define QSZ (128 * AROW)              // 18432
#define KSZ (64 * AROW)               // 9216
#define STG2 (2 * KSZ)                // 18432 (k, v)
#define ATT_SMEM (QSZ + 2 * STG2)     // 55296

__device__ __forceinline__ void loadkv(uint32_t st, const __half* kfp,
                                       const __half* vfp, int kv0, int tid) {
#pragma unroll
  for (int it = 0; it < 4; it++) {
    const int arr = it >> 1;                 // 0: k, 1: v
    const int rem = ((it & 1) << 8) + tid;   // 0..511
    const int row = rem >> 3, c = rem & 7;
    const __half* base = arr ? vfp : kfp;
    cpasync16(st + arr * KSZ + row * AROW + c * 16,
              base + (size_t)(kv0 + row) * HD + c * 8);
  }
}

__global__ __launch_bounds__(256, 2) void attn_mma(
    const __half* __restrict__ qf, const __half* __restrict__ kf,
    const __half* __restrict__ vf, __half* __restrict__ yf) {
  extern __shared__ __align__(128) uint8_t smem_raw[];
  const uint32_t sb = smem_u32(smem_raw);
  const int tid = threadIdx.x;
  const int w = tid >> 5, lane = tid & 31;
  const int gid = lane >> 2, tig = lane & 3;
  const int qblk = blockIdx.x, h = blockIdx.y, b = blockIdx.z;
  const int q0 = qblk * 128;
  const size_t hoff = (((size_t)b * HH + h) * TT) * HD;
  const __half* qfp = qf + hoff;
  const __half* kfp = kf + hoff;
  const __half* vfp = vf + hoff;

#pragma unroll
  for (int it = 0; it < 4; it++) {
    const int rem = it * 256 + tid;
    const int row = rem >> 3, c = rem & 7;
    cpasync16(sb + row * AROW + c * 16,
              qfp + (size_t)(q0 + row) * HD + c * 8);
  }
  loadkv(sb + QSZ, kfp, vfp, 0, tid);
  CP_COMMIT();
  loadkv(sb + QSZ + STG2, kfp, vfp, 64, tid);
  CP_COMMIT();

  float s[8][4], o[8][4];
  float mrow[2] = {-INFINITY, -INFINITY};
  float lrow[2] = {0.f, 0.f};
#pragma unroll
  for (int j = 0; j < 8; j++)
#pragma unroll
    for (int r = 0; r < 4; r++) o[j][r] = 0.f;

  const int amat = lane >> 3;
  const int arow_in = ((amat & 1) << 3) + (lane & 7);
  const int acol = (amat >> 1) << 4;
  const int brow_in = lane & 7;
  const int bcol = ((lane >> 3) & 1) << 4;
  const int ntiles = 2 * qblk + 2;

  for (int t = 0; t < ntiles; t++) {
    if (t + 1 < ntiles)
      asm volatile("cp.async.wait_group 1;" ::: "memory");
    else
      asm volatile("cp.async.wait_group 0;" ::: "memory");
    __syncthreads();

    const uint32_t st = sb + QSZ + (t & 1) * STG2;
    const uint32_t tK = st, tV = st + KSZ;

#pragma unroll
    for (int j = 0; j < 8; j++)
#pragma unroll
      for (int r = 0; r < 4; r++) s[j][r] = 0.f;

    // ---- S = q K^T ----
#pragma unroll
    for (int kk = 0; kk < 4; kk++) {
      uint32_t aq[4];
      const uint32_t qo = (w * 16 + arow_in) * AROW + kk * 32 + acol;
      ldsm4(aq, sb + qo);
#pragma unroll
      for (int g = 0; g < 2; g++) {
        uint32_t kbf[4][2];
#pragma unroll
        for (int jj = 0; jj < 4; jj++) {
          const uint32_t ko =
              ((g * 4 + jj) * 8 + brow_in) * AROW + kk * 32 + bcol;
          ldsm2(kbf[jj], tK + ko);
        }
#pragma unroll
        for (int jj = 0; jj < 4; jj++) mma16816h(s[g * 4 + jj], aq, kbf[jj]);
      }
    }

    const int kv0 = t * 64;
    if (kv0 + 63 > q0) {
#pragma unroll
      for (int j = 0; j < 8; j++) {
        const int jg = kv0 + j * 8 + tig * 2;
#pragma unroll
        for (int r = 0; r < 2; r++) {
          const int rg = q0 + w * 16 + gid + r * 8;
          if (jg > rg) s[j][r * 2] = -INFINITY;
          if (jg + 1 > rg) s[j][r * 2 + 1] = -INFINITY;
        }
      }
    }

#pragma unroll
    for (int r = 0; r < 2; r++) {
      float mx = mrow[r];
#pragma unroll
      for (int j = 0; j < 8; j++)
        mx = fmaxf(mx, fmaxf(s[j][r * 2], s[j][r * 2 + 1]));
      mx = fmaxf(mx, __shfl_xor_sync(0xffffffffu, mx, 1));
      mx = fmaxf(mx, __shfl_xor_sync(0xffffffffu, mx, 2));
      const float alpha = __expf(mrow[r] - mx);
      mrow[r] = mx;
      float ls = 0.f;
#pragma unroll
      for (int j = 0; j < 8; j++) {
        const float p0 = __expf(s[j][r * 2] - mx);
        const float p1 = __expf(s[j][r * 2 + 1] - mx);
        s[j][r * 2] = p0;
        s[j][r * 2 + 1] = p1;
        ls += p0 + p1;
      }
      ls += __shfl_xor_sync(0xffffffffu, ls, 1);
      ls += __shfl_xor_sync(0xffffffffu, ls, 2);
      lrow[r] = lrow[r] * alpha + ls;
#pragma unroll
      for (int j = 0; j < 8; j++) {
        o[j][r * 2] *= alpha;
        o[j][r * 2 + 1] *= alpha;
      }
    }

    // ---- O += p V (single-term p) ----
#pragma unroll
    for (int kk = 0; kk < 4; kk++) {
      uint32_t ph4[4];
#pragma unroll
      for (int half = 0; half < 2; half++) {
        const int j = 2 * kk + half;
        ph4[half * 2 + 0] = pack2h(s[j][0], s[j][1]);
        ph4[half * 2 + 1] = pack2h(s[j][2], s[j][3]);
      }
      const uint32_t vrow = kk * 16 + (lane & 15);
      const uint32_t vco = (lane >> 4) << 4;
#pragma unroll
      for (int npg = 0; npg < 2; npg++) {
        uint32_t vfr[2][4];
#pragma unroll
        for (int p = 0; p < 2; p++) {
          const uint32_t vo = vrow * AROW + (npg * 2 + p) * 32 + vco;
          ldsm4t(vfr[p], tV + vo);
        }
#pragma unroll
        for (int p = 0; p < 2; p++) {
          const int np = npg * 2 + p;
          mma16816h(o[2 * np], ph4, vfr[p]);
          mma16816h(o[2 * np + 1], ph4, vfr[p] + 2);
        }
      }
    }
    __syncthreads();

    if (t + 2 < ntiles) {
      loadkv(st, kfp, vfp, (t + 2) * 64, tid);
      CP_COMMIT();
    }
  }

  // Epilogue: normalize, emit single fp16 y for the proj GEMM.
  const float i0 = 1.f / lrow[0];
  const float i1 = 1.f / lrow[1];
  const int r0 = q0 + w * 16 + gid;
  const size_t base0 = ((size_t)b * TT + r0) * CC + h * HD;
  const size_t base1 = base0 + (size_t)8 * CC;
#pragma unroll
  for (int n = 0; n < 8; n++) {
    const int col = n * 8 + tig * 2;
    *(uint32_t*)(yf + base0 + col) = pack2h(o[n][0] * i0, o[n][1] * i0);
    *(uint32_t*)(yf + base1 + col) = pack2h(o[n][2] * i1, o[n][3] * i1);
  }
}

// ---------------------------------------------------------------------------
// kernel_launch
// ---------------------------------------------------------------------------
extern "C" void kernel_launch(void* const* d_in, const int* in_sizes, int n_in,
                              void* d_out, int out_size) {
  const float* x = (const float*)d_in[0];
  const float* Wq = (const float*)d_in[2];
  const float* bq = (const float*)d_in[3];
  const float* Wk = (const float*)d_in[4];
  const float* bk = (const float*)d_in[5];
  const float* Wv = (const float*)d_in[6];
  const float* bv = (const float*)d_in[7];
  const float* Wp = (const float*)d_in[8];
  const float* bp = (const float*)d_in[9];

  float* out = (float*)d_out;
  float* kout = out + (size_t)BB * TT * CC;        // present[0] = k
  float* vout = kout + (size_t)BB * HH * TT * HD;  // present[1] = v

  __half *xf, *wt, *yf, *qfb, *kfb, *vfb;
  cudaGetSymbolAddress((void**)&xf, g_xf);
  cudaGetSymbolAddress((void**)&wt, g_wt);
  cudaGetSymbolAddress((void**)&yf, g_yf);
  cudaGetSymbolAddress((void**)&qfb, g_qf);
  cudaGetSymbolAddress((void**)&kfb, g_kf);
  cudaGetSymbolAddress((void**)&vfb, g_vf);

  // #1: fused conversions (x fp16 + 4 W transposes to fp16)
  conv_all<<<dim3(32, 32, 5), dim3(32, 8)>>>(x, Wq, Wk, Wv, Wp, xf, wt);

  // #2: fused QKV projection (single-term fp16, BKC=64, 2 CTAs/SM)
  cudaFuncSetAttribute(gemm_tc<1>, cudaFuncAttributeMaxDynamicSharedMemorySize,
                       GEMM_SMEM);
  cudaFuncSetAttribute(gemm_tc<0>, cudaFuncAttributeMaxDynamicSharedMemorySize,
                       GEMM_SMEM);
  dim3 qkvgrid(3 * NN / 128, MM / 128);  // (24, 64)
  gemm_tc<1><<<qkvgrid, 256, GEMM_SMEM>>>(xf, wt, bq, bk, bv, nullptr, kout,
                                          vout, qfb, kfb, vfb);

  // #3: tensor-core attention (single-term fp16)
  cudaFuncSetAttribute(attn_mma, cudaFuncAttributeMaxDynamicSharedMemorySize,
                       ATT_SMEM);
  dim3 agrid(TT / 128, HH, BB);
  attn_mma<<<agrid, 256, ATT_SMEM>>>(qfb, kfb, vfb, yf);

  // #4: output projection (lands under ncu -s 5)
  const size_t WSZ = (size_t)KK * NN;
  dim3 pgrid(NN / 128, MM / 128);
  gemm_tc<0><<<pgrid, 256, GEMM_SMEM>>>(yf, wt + 3 * WSZ, bp, nullptr, nullptr,
                                        out, nullptr, nullptr, nullptr,
                                        nullptr, nullptr);
}